// round 7
// baseline (speedup 1.0000x reference)
#include <cuda_runtime.h>
#include <cuda_bf16.h>
#include <cstdint>

#define D_DIM 1792
#define B_DIM 8192
#define NB 128
#define NBLK (D_DIM / NB)     // 14
#define NB2 256
#define NBLK2 (D_DIM / NB2)   // 7
#define MREM0 1536            // largest trailing M in the chain

// ---------------- fp32 scratch ----------------
__device__ __align__(16) float g_Vn   [ (size_t)D_DIM * D_DIM ];
__device__ __align__(16) float g_G    [ (size_t)D_DIM * D_DIM ];
__device__ __align__(16) float g_RHS  [ (size_t)D_DIM * D_DIM ];
__device__ __align__(16) float g_Wt   [ (size_t)D_DIM * D_DIM ];
__device__ __align__(16) float g_Tinv [ (size_t)NBLK * NB * NB ];

// ---------------- bf16 hi|lo scratch ----------------
__device__ __align__(16) __nv_bfloat16 g_Vn_hl    [ (size_t)D_DIM * 2 * D_DIM ];
__device__ __align__(16) __nv_bfloat16 g_VnT_hl   [ (size_t)D_DIM * 2 * D_DIM ];
__device__ __align__(16) __nv_bfloat16 g_G_hl     [ (size_t)D_DIM * 2 * D_DIM ];
__device__ __align__(16) __nv_bfloat16 g_WtT_hl   [ (size_t)D_DIM * 2 * D_DIM ];
__device__ __align__(16) __nv_bfloat16 g_RHST_hl  [ (size_t)D_DIM * 2 * D_DIM ];
__device__ __align__(16) __nv_bfloat16 g_P_hl     [ (size_t)D_DIM * 2 * D_DIM ];
__device__ __align__(16) __nv_bfloat16 g_XT_hl    [ (size_t)B_DIM * 2 * D_DIM ];
__device__ __align__(16) __nv_bfloat16 g_Tinv2_hl [ (size_t)NBLK2 * NB2 * 2 * NB2 ];
__device__ __align__(16) __nv_bfloat16 g_Tinv2T_hl[ (size_t)NBLK2 * NB2 * 2 * NB2 ];
__device__ __align__(16) __nv_bfloat16 g_S_hl     [ (size_t)(NBLK2 - 1) * MREM0 * 2 * NB2 ];

// ============================================================================
// helpers
// ============================================================================
__device__ __forceinline__ uint32_t smem_u32(const void* p) {
    uint32_t a;
    asm("{ .reg .u64 t; cvta.to.shared.u64 t, %1; cvt.u32.u64 %0, t; }"
        : "=r"(a) : "l"(p));
    return a;
}
__device__ __forceinline__ void cpa16(uint32_t s, const void* g) {
    asm volatile("cp.async.cg.shared.global [%0], [%1], 16;" :: "r"(s), "l"(g));
}
#define CPA_COMMIT() asm volatile("cp.async.commit_group;" ::: "memory")
#define CPA_WAIT(n)  asm volatile("cp.async.wait_group %0;" :: "n"(n) : "memory")

#define LDSM4(r0, r1, r2, r3, addr) \
    asm volatile("ldmatrix.sync.aligned.m8n8.x4.shared.b16 {%0,%1,%2,%3}, [%4];" \
        : "=r"(r0), "=r"(r1), "=r"(r2), "=r"(r3) : "r"(addr))

#define MMA16816(d, a, b0, b1) \
    asm volatile("mma.sync.aligned.m16n8k16.row.col.f32.bf16.bf16.f32 " \
        "{%0,%1,%2,%3}, {%4,%5,%6,%7}, {%8,%9}, {%0,%1,%2,%3};" \
        : "+f"((d)[0]), "+f"((d)[1]), "+f"((d)[2]), "+f"((d)[3]) \
        : "r"((a)[0]), "r"((a)[1]), "r"((a)[2]), "r"((a)[3]), "r"(b0), "r"(b1))

// ============================================================================
// Generalized bf16-split tensor GEMM:
//   R = alpha * A @ B^T (+ C if BETA) (+ I if ADDI)
//   FPOUT: write R (fp32) to C.   HLOUT: write hi/lo split of R to Chl
//          (hi at Chl[r*ldchl + c], lo at Chl[r*ldchl + ldchl/2 + c]).
//   A hi at A[m*lda2 + k], lo at +loA.   B hi at B[n*ldb2 + k], lo at +loB.
//   TRI: lower-triangular tile set.  BDIAG: A block-diagonal 256-blocks.
//   ZB: z-batched.  CTA 128x128, 4 warps of 64x64, k=32/stage, 3 stages.
// ============================================================================
#define TILE_B   8192
#define STAGE_B  (4 * TILE_B)
#define GEMM_SMEM (3 * STAGE_B)
#define GEMM_THR 128

template <int ADDI, int TRI, int BETA, int BDIAG, int ZB, int FPOUT, int HLOUT>
__global__ void __launch_bounds__(GEMM_THR, 2)
mma_gemm(const __nv_bfloat16* __restrict__ A, const __nv_bfloat16* __restrict__ B,
         float* __restrict__ C, __nv_bfloat16* __restrict__ Chl,
         int K, int lda2, int loA, int ldb2, int loB,
         int ldc, int ldchl, float alpha,
         long long zAs, long long zBs, long long zCHs, int M0, int dM)
{
    extern __shared__ __align__(128) char smem[];
    const uint32_t s0 = smem_u32(smem);
    const int tid  = threadIdx.x;
    const int lane = tid & 31;
    const int wid  = tid >> 5;
    const int wm   = wid >> 1;
    const int wn   = wid & 1;

    if (ZB) {
        const int z = blockIdx.z;
        A += zAs * z; B += zBs * z;
        if (HLOUT) Chl += zCHs * z;
        if ((int)(blockIdx.y * 128) >= M0 - dM * z) return;
    }

    int row0, col0;
    if (TRI) {
        int bid = blockIdx.x;
        int r = 0;
        while ((r + 1) * (r + 2) / 2 <= bid) ++r;
        row0 = r * 128;
        col0 = (bid - r * (r + 1) / 2) * 128;
    } else {
        row0 = blockIdx.y * 128;
        col0 = blockIdx.x * 128;
    }

    const __nv_bfloat16* Ap = A;
    const __nv_bfloat16* Bp = B;
    int rowA0 = row0;
    if (BDIAG) {
        const int bi = row0 >> 8;
        Ap += (size_t)bi * 256 * lda2;
        Bp += bi * 256;
        rowA0 = row0 & 255;
    }
    const int T = K / 32;

    float acc[4][8][4];
#pragma unroll
    for (int i = 0; i < 4; i++)
#pragma unroll
        for (int j = 0; j < 8; j++)
#pragma unroll
            for (int q = 0; q < 4; q++) acc[i][j][q] = 0.f;

    auto load_stage = [&](int s) {
        const int k0 = s * 32;
        const uint32_t base = s0 + (s % 3) * STAGE_B;
#pragma unroll
        for (int qq = 0; qq < 4; ++qq) {
            const int jj = tid + qq * GEMM_THR;
            const int r  = jj >> 2;
            const int cc = jj & 3;
            const uint32_t soff = r * 64 + ((cc ^ ((r >> 1) & 3)) << 4);
            const __nv_bfloat16* ag = Ap + (size_t)(rowA0 + r) * lda2 + k0 + cc * 8;
            const __nv_bfloat16* bg = Bp + (size_t)(col0 + r) * ldb2 + k0 + cc * 8;
            cpa16(base + 0 * TILE_B + soff, ag);
            cpa16(base + 1 * TILE_B + soff, ag + loA);
            cpa16(base + 2 * TILE_B + soff, bg);
            cpa16(base + 3 * TILE_B + soff, bg + loB);
        }
        CPA_COMMIT();
    };

    load_stage(0); load_stage(1);

    for (int s = 0; s < T; ++s) {
        CPA_WAIT(1);
        __syncthreads();
        if (s + 2 < T) load_stage(s + 2);

        const uint32_t buf = s0 + (s % 3) * STAGE_B;
#pragma unroll
        for (int kk = 0; kk < 2; ++kk) {
            uint32_t ah[4][4], al[4][4], bb[8][2];
#pragma unroll
            for (int mi = 0; mi < 4; ++mi) {
                const int row = wm * 64 + mi * 16 + ((lane >> 3) & 1) * 8 + (lane & 7);
                const int cc  = kk * 2 + (lane >> 4);
                const uint32_t off = row * 64 + ((cc ^ ((row >> 1) & 3)) << 4);
                LDSM4(ah[mi][0], ah[mi][1], ah[mi][2], ah[mi][3], buf + 0 * TILE_B + off);
                LDSM4(al[mi][0], al[mi][1], al[mi][2], al[mi][3], buf + 1 * TILE_B + off);
            }
#pragma unroll
            for (int p = 0; p < 4; ++p) {
                const int row = wn * 64 + p * 16 + (lane >> 4) * 8 + (lane & 7);
                const int cc  = kk * 2 + ((lane >> 3) & 1);
                const uint32_t off = row * 64 + ((cc ^ ((row >> 1) & 3)) << 4);
                LDSM4(bb[p * 2][0], bb[p * 2][1], bb[p * 2 + 1][0], bb[p * 2 + 1][1],
                      buf + 2 * TILE_B + off);
            }
#pragma unroll
            for (int mi = 0; mi < 4; ++mi)
#pragma unroll
                for (int nj = 0; nj < 8; ++nj) {
                    MMA16816(acc[mi][nj], ah[mi], bb[nj][0], bb[nj][1]);  // hh
                    MMA16816(acc[mi][nj], al[mi], bb[nj][0], bb[nj][1]);  // lh
                }
#pragma unroll
            for (int p = 0; p < 4; ++p) {
                const int row = wn * 64 + p * 16 + (lane >> 4) * 8 + (lane & 7);
                const int cc  = kk * 2 + ((lane >> 3) & 1);
                const uint32_t off = row * 64 + ((cc ^ ((row >> 1) & 3)) << 4);
                LDSM4(bb[p * 2][0], bb[p * 2][1], bb[p * 2 + 1][0], bb[p * 2 + 1][1],
                      buf + 3 * TILE_B + off);
            }
#pragma unroll
            for (int mi = 0; mi < 4; ++mi)
#pragma unroll
                for (int nj = 0; nj < 8; ++nj)
                    MMA16816(acc[mi][nj], ah[mi], bb[nj][0], bb[nj][1]);  // hl
        }
    }

    const int g = lane >> 2, t = lane & 3;
    const int half = ldchl >> 1;
#pragma unroll
    for (int mi = 0; mi < 4; ++mi) {
#pragma unroll
        for (int nj = 0; nj < 8; ++nj) {
            const int r_ = row0 + wm * 64 + mi * 16 + g;
            const int c_ = col0 + wn * 64 + nj * 8 + 2 * t;
            float2 v, v2;
            v.x  = alpha * acc[mi][nj][0];
            v.y  = alpha * acc[mi][nj][1];
            v2.x = alpha * acc[mi][nj][2];
            v2.y = alpha * acc[mi][nj][3];
            if (BETA) {
                float2 o  = *reinterpret_cast<const float2*>(&C[(size_t)r_ * ldc + c_]);
                float2 o2 = *reinterpret_cast<const float2*>(&C[(size_t)(r_ + 8) * ldc + c_]);
                v.x += o.x;  v.y += o.y;
                v2.x += o2.x; v2.y += o2.y;
            }
            if (ADDI) {
                if (r_ == c_)     v.x  += 1.f;
                if (r_ == c_ + 1) v.y  += 1.f;
                if (r_ + 8 == c_)     v2.x += 1.f;
                if (r_ + 8 == c_ + 1) v2.y += 1.f;
            }
            if (FPOUT) {
                *reinterpret_cast<float2*>(&C[(size_t)r_ * ldc + c_])       = v;
                *reinterpret_cast<float2*>(&C[(size_t)(r_ + 8) * ldc + c_]) = v2;
            }
            if (HLOUT) {
                __nv_bfloat162 h, h2, l, l2;
                h.x  = __float2bfloat16(v.x);   h.y  = __float2bfloat16(v.y);
                h2.x = __float2bfloat16(v2.x);  h2.y = __float2bfloat16(v2.y);
                l.x  = __float2bfloat16(v.x  - __bfloat162float(h.x));
                l.y  = __float2bfloat16(v.y  - __bfloat162float(h.y));
                l2.x = __float2bfloat16(v2.x - __bfloat162float(h2.x));
                l2.y = __float2bfloat16(v2.y - __bfloat162float(h2.y));
                *reinterpret_cast<__nv_bfloat162*>(&Chl[(size_t)r_ * ldchl + c_])              = h;
                *reinterpret_cast<__nv_bfloat162*>(&Chl[(size_t)r_ * ldchl + half + c_])       = l;
                *reinterpret_cast<__nv_bfloat162*>(&Chl[(size_t)(r_ + 8) * ldchl + c_])        = h2;
                *reinterpret_cast<__nv_bfloat162*>(&Chl[(size_t)(r_ + 8) * ldchl + half + c_]) = l2;
            }
        }
    }
}

// ============================================================================
// Row-normalize U -> Vn (fp32), Vn_hl (hi|lo), RHS = 2*Vn
// ============================================================================
__global__ void normalize_kernel(const float* __restrict__ U) {
    int row = blockIdx.x;
    const float* u = U + (size_t)row * D_DIM;
    __shared__ float red[256];
    float s = 0.f;
    for (int c = threadIdx.x; c < D_DIM; c += 256) { float v = u[c]; s += v * v; }
    red[threadIdx.x] = s;
    __syncthreads();
    for (int off = 128; off > 0; off >>= 1) {
        if (threadIdx.x < off) red[threadIdx.x] += red[threadIdx.x + off];
        __syncthreads();
    }
    float inv = rsqrtf(red[0]);
    for (int c = threadIdx.x; c < D_DIM; c += 256) {
        float v = u[c] * inv;
        g_Vn [(size_t)row * D_DIM + c] = v;
        g_RHS[(size_t)row * D_DIM + c] = 2.f * v;
        __nv_bfloat16 h = __float2bfloat16(v);
        g_Vn_hl[(size_t)row * 2 * D_DIM + c]         = h;
        g_Vn_hl[(size_t)row * 2 * D_DIM + D_DIM + c] =
            __float2bfloat16(v - __bfloat162float(h));
    }
}

// ============================================================================
// Transposed + split conversion (fp32 [R,C] -> hi/lo rows of out)
// ============================================================================
__global__ void conv_hl_T_gen(const float* __restrict__ in, int R, int C,
                              __nv_bfloat16* __restrict__ out, int outld,
                              int outcol0, int looff,
                              long long zIn, long long zOut) {
    in  += zIn  * blockIdx.z;
    out += zOut * blockIdx.z;
    __shared__ float t[32][33];
    int r0 = blockIdx.y * 32, c0 = blockIdx.x * 32;
    int tx = threadIdx.x, ty = threadIdx.y;
    for (int i = 0; i < 32; i += 8)
        t[ty + i][tx] = in[(size_t)(r0 + ty + i) * C + c0 + tx];
    __syncthreads();
    for (int i = 0; i < 32; i += 8) {
        float x = t[tx][ty + i];
        __nv_bfloat16 h = __float2bfloat16(x);
        out[(size_t)(c0 + ty + i) * outld + outcol0 + r0 + tx] = h;
        out[(size_t)(c0 + ty + i) * outld + looff + outcol0 + r0 + tx] =
            __float2bfloat16(x - __bfloat162float(h));
    }
}

// ============================================================================
// Diag-block inversion (unit lower tri, 128x128, one CTA each)
// ============================================================================
#define INV_SMEM (2 * NB * (NB + 1) * (int)sizeof(float))
__global__ void invert_diag_kernel() {
    extern __shared__ float sm[];
    float (*Gs)[NB + 1] = (float (*)[NB + 1])sm;
    float (*Zs)[NB + 1] = (float (*)[NB + 1])(sm + NB * (NB + 1));
    const int b0 = blockIdx.x * NB;
    const int tid = threadIdx.x;
    for (int idx = tid; idx < NB * NB; idx += 256) {
        int r = idx >> 7, c = idx & 127;
        Gs[r][c] = g_G[(size_t)(b0 + r) * D_DIM + b0 + c];
        Zs[r][c] = (r == c) ? 1.f : 0.f;
    }
    __syncthreads();
    for (int j = 0; j < NB - 1; ++j) {
        int rows = NB - 1 - j;
        for (int idx = tid; idx < rows * NB; idx += 256) {
            int r = j + 1 + (idx >> 7);
            int c = idx & 127;
            Zs[r][c] -= 2.f * Gs[r][j] * Zs[j][c];
        }
        __syncthreads();
    }
    float* out = g_Tinv + (size_t)blockIdx.x * NB * NB;
    for (int idx = tid; idx < NB * NB; idx += 256) {
        int r = idx >> 7, c = idx & 127;
        out[(size_t)r * NB + c] = Zs[r][c];
    }
}

// ============================================================================
// Pair-combine: 7 Tinv2 blocks (256x256) from 14 inverted 128 blocks.
// Emits Tinv2_hl (row-major hi/lo) and Tinv2T_hl (transposed hi/lo) directly.
// ============================================================================
#define CMB_SMEM (3 * 128 * 129 * (int)sizeof(float))
__device__ __forceinline__ void cmb_wr(__nv_bfloat16* Thl, __nv_bfloat16* TThl,
                                       int r, int c, float x) {
    __nv_bfloat16 h = __float2bfloat16(x);
    __nv_bfloat16 l = __float2bfloat16(x - __bfloat162float(h));
    Thl [(size_t)r * 512 + c]        = h;
    Thl [(size_t)r * 512 + 256 + c]  = l;
    TThl[(size_t)c * 512 + r]        = h;
    TThl[(size_t)c * 512 + 256 + r]  = l;
}
__global__ void __launch_bounds__(256, 1) combine_tinv() {
    extern __shared__ float sm[];
    float (*Abuf)[129] = (float (*)[129])sm;
    float (*Bbuf)[129] = (float (*)[129])(sm + 128 * 129);
    float (*Tm)[129]   = (float (*)[129])(sm + 2 * 128 * 129);
    const int p = blockIdx.x;
    const int tid = threadIdx.x;
    const int trow = (tid / 16) * 8;
    const int tcol = (tid % 16) * 8;
    const float* InvA = g_Tinv + (size_t)(2 * p)     * NB * NB;
    const float* InvB = g_Tinv + (size_t)(2 * p + 1) * NB * NB;
    const size_t g21 = (size_t)(p * 256 + 128) * D_DIM + p * 256;
    __nv_bfloat16* Thl  = g_Tinv2_hl  + (size_t)p * NB2 * 2 * NB2;
    __nv_bfloat16* TThl = g_Tinv2T_hl + (size_t)p * NB2 * 2 * NB2;

    for (int idx = tid; idx < 128 * 128; idx += 256) {
        int r = idx >> 7, c = idx & 127;
        Abuf[r][c] = 2.f * g_G[g21 + (size_t)r * D_DIM + c];
        Bbuf[r][c] = InvA[idx];
    }
    __syncthreads();
    {
        float acc[8][8];
#pragma unroll
        for (int i = 0; i < 8; i++)
#pragma unroll
            for (int j = 0; j < 8; j++) acc[i][j] = 0.f;
        for (int k = 0; k < 128; ++k) {
            float a[8], b[8];
#pragma unroll
            for (int i = 0; i < 8; i++) a[i] = Abuf[trow + i][k];
#pragma unroll
            for (int j = 0; j < 8; j++) b[j] = Bbuf[k][tcol + j];
#pragma unroll
            for (int i = 0; i < 8; i++)
#pragma unroll
                for (int j = 0; j < 8; j++) acc[i][j] += a[i] * b[j];
        }
        __syncthreads();
#pragma unroll
        for (int i = 0; i < 8; i++)
#pragma unroll
            for (int j = 0; j < 8; j++) Tm[trow + i][tcol + j] = acc[i][j];
    }
    __syncthreads();
    for (int idx = tid; idx < 128 * 128; idx += 256) {
        int r = idx >> 7, c = idx & 127;
        Abuf[r][c] = InvB[idx];
    }
    __syncthreads();
    {
        float acc[8][8];
#pragma unroll
        for (int i = 0; i < 8; i++)
#pragma unroll
            for (int j = 0; j < 8; j++) acc[i][j] = 0.f;
        for (int k = 0; k < 128; ++k) {
            float a[8], b[8];
#pragma unroll
            for (int i = 0; i < 8; i++) a[i] = Abuf[trow + i][k];
#pragma unroll
            for (int j = 0; j < 8; j++) b[j] = Tm[k][tcol + j];
#pragma unroll
            for (int i = 0; i < 8; i++)
#pragma unroll
                for (int j = 0; j < 8; j++) acc[i][j] += a[i] * b[j];
        }
        // Q21 = -acc (register-resident)
#pragma unroll
        for (int i = 0; i < 8; i++)
#pragma unroll
            for (int j = 0; j < 8; j++)
                cmb_wr(Thl, TThl, 128 + trow + i, tcol + j, -acc[i][j]);
    }
    // Q11 = InvA (Bbuf), Q22 = InvB (Abuf), Q12 = 0
    for (int idx = tid; idx < 128 * 128; idx += 256) {
        int r = idx >> 7, c = idx & 127;
        cmb_wr(Thl, TThl, r, c, Bbuf[r][c]);
        cmb_wr(Thl, TThl, 128 + r, 128 + c, Abuf[r][c]);
        cmb_wr(Thl, TThl, r, 128 + c, 0.f);
    }
}

// ============================================================================
extern "C" void kernel_launch(void* const* d_in, const int* in_sizes, int n_in,
                              void* d_out, int out_size)
{
    const float* X;
    const float* U;
    if (in_sizes[0] == D_DIM * D_DIM && in_sizes[1] != D_DIM * D_DIM) {
        U = (const float*)d_in[0]; X = (const float*)d_in[1];
    } else {
        X = (const float*)d_in[0]; U = (const float*)d_in[1];
    }
    float* out = (float*)d_out;

    float *Vn, *G, *RHS, *Wt;
    cudaGetSymbolAddress((void**)&Vn,  g_Vn);
    cudaGetSymbolAddress((void**)&G,   g_G);
    cudaGetSymbolAddress((void**)&RHS, g_RHS);
    cudaGetSymbolAddress((void**)&Wt,  g_Wt);
    __nv_bfloat16 *Vn_hl, *VnT_hl, *G_hl, *WtT_hl, *RHST_hl, *P_hl, *XT_hl;
    __nv_bfloat16 *Tinv2_hl, *Tinv2T_hl, *S_hl;
    cudaGetSymbolAddress((void**)&Vn_hl,     g_Vn_hl);
    cudaGetSymbolAddress((void**)&VnT_hl,    g_VnT_hl);
    cudaGetSymbolAddress((void**)&G_hl,      g_G_hl);
    cudaGetSymbolAddress((void**)&WtT_hl,    g_WtT_hl);
    cudaGetSymbolAddress((void**)&RHST_hl,   g_RHST_hl);
    cudaGetSymbolAddress((void**)&P_hl,      g_P_hl);
    cudaGetSymbolAddress((void**)&XT_hl,     g_XT_hl);
    cudaGetSymbolAddress((void**)&Tinv2_hl,  g_Tinv2_hl);
    cudaGetSymbolAddress((void**)&Tinv2T_hl, g_Tinv2T_hl);
    cudaGetSymbolAddress((void**)&S_hl,      g_S_hl);

    cudaFuncSetAttribute(invert_diag_kernel,
                         cudaFuncAttributeMaxDynamicSharedMemorySize, INV_SMEM);
    cudaFuncSetAttribute(combine_tinv,
                         cudaFuncAttributeMaxDynamicSharedMemorySize, CMB_SMEM);
    cudaFuncSetAttribute(mma_gemm<0,1,0,0,0,1,1>,
                         cudaFuncAttributeMaxDynamicSharedMemorySize, GEMM_SMEM);
    cudaFuncSetAttribute(mma_gemm<0,0,0,0,1,0,1>,
                         cudaFuncAttributeMaxDynamicSharedMemorySize, GEMM_SMEM);
    cudaFuncSetAttribute(mma_gemm<0,0,1,0,0,1,0>,
                         cudaFuncAttributeMaxDynamicSharedMemorySize, GEMM_SMEM);
    cudaFuncSetAttribute(mma_gemm<0,0,0,1,0,1,0>,
                         cudaFuncAttributeMaxDynamicSharedMemorySize, GEMM_SMEM);
    cudaFuncSetAttribute(mma_gemm<1,0,0,0,0,0,1>,
                         cudaFuncAttributeMaxDynamicSharedMemorySize, GEMM_SMEM);
    cudaFuncSetAttribute(mma_gemm<0,0,0,0,0,1,0>,
                         cudaFuncAttributeMaxDynamicSharedMemorySize, GEMM_SMEM);

    const dim3 t32x8(32, 8);
    const int D2 = 2 * D_DIM;   // 3584

    // 0) Vn (+hl), RHS = 2*Vn
    normalize_kernel<<<D_DIM, 256>>>(U);
    // 1) VnT_hl
    conv_hl_T_gen<<<dim3(D_DIM / 32, D_DIM / 32), t32x8>>>(
        Vn, D_DIM, D_DIM, VnT_hl, D2, 0, D_DIM, 0, 0);
    // 2) G = Vn @ Vn^T (lower tiles; fp32 + hl fused)
    mma_gemm<0,1,0,0,0,1,1><<<NBLK * (NBLK + 1) / 2, GEMM_THR, GEMM_SMEM>>>(
        Vn_hl, Vn_hl, G, G_hl, D_DIM, D2, D_DIM, D2, D_DIM, D_DIM, D2, 1.f,
        0, 0, 0, D_DIM, 0);
    // 3) invert 14 diag blocks
    invert_diag_kernel<<<NBLK, 256, INV_SMEM>>>();
    // 4) combine into 7 Tinv2 blocks (emits Tinv2_hl + Tinv2T_hl)
    combine_tinv<<<NBLK2, 256, CMB_SMEM>>>();
    // 5) S_i = 2 * G[(i+1)*256:, blk i] @ Tinv2_i^T  (z-batched, hl-only out)
    mma_gemm<0,0,0,0,1,0,1><<<dim3(NB2 / 128, MREM0 / 128, NBLK2 - 1), GEMM_THR, GEMM_SMEM>>>(
        G_hl + (size_t)NB2 * D2, Tinv2T_hl, nullptr, S_hl,
        NB2, D2, D_DIM, 2 * NB2, NB2, 0, 2 * NB2, 2.f,
        (long long)NB2 * D2 + NB2,
        (long long)NB2 * 2 * NB2,
        (long long)MREM0 * 2 * NB2,
        MREM0, NB2);

    // 6..) chain: finalize RHS^T slice, then trailing update via S_i
    for (int i = 0; i < NBLK2; ++i) {
        conv_hl_T_gen<<<dim3(D_DIM / 32, NB2 / 32), t32x8>>>(
            RHS + (size_t)i * NB2 * D_DIM, NB2, D_DIM,
            RHST_hl, D2, i * NB2, D_DIM, 0, 0);
        int mrem = D_DIM - (i + 1) * NB2;
        if (mrem > 0) {
            mma_gemm<0,0,1,0,0,1,0><<<dim3(D_DIM / 128, mrem / 128), GEMM_THR, GEMM_SMEM>>>(
                S_hl + (size_t)i * MREM0 * 2 * NB2,
                RHST_hl + (size_t)i * NB2,
                RHS + (size_t)(i + 1) * NB2 * D_DIM, nullptr,
                NB2, 2 * NB2, NB2, D2, D_DIM, D_DIM, 0, -1.f,
                0, 0, 0, mrem, 0);
        }
    }

    // Wt = blockdiag(Tinv2) @ RHS
    mma_gemm<0,0,0,1,0,1,0><<<dim3(D_DIM / 128, D_DIM / 128), GEMM_THR, GEMM_SMEM>>>(
        Tinv2_hl, RHST_hl, Wt, nullptr,
        NB2, 2 * NB2, NB2, D2, D_DIM, D_DIM, 0, 1.f, 0, 0, 0, D_DIM, 0);
    conv_hl_T_gen<<<dim3(D_DIM / 32, D_DIM / 32), t32x8>>>(
        Wt, D_DIM, D_DIM, WtT_hl, D2, 0, D_DIM, 0, 0);

    // P = I - Wt^T @ Vn  (hl-only out)
    mma_gemm<1,0,0,0,0,0,1><<<dim3(D_DIM / 128, D_DIM / 128), GEMM_THR, GEMM_SMEM>>>(
        WtT_hl, VnT_hl, nullptr, P_hl,
        D_DIM, D2, D_DIM, D2, D_DIM, 0, D2, -1.f, 0, 0, 0, D_DIM, 0);

    // X^T split (independent; placed just before use)
    conv_hl_T_gen<<<dim3(B_DIM / 32, D_DIM / 32), t32x8>>>(
        X, D_DIM, B_DIM, XT_hl, D2, 0, D_DIM, 0, 0);

    // out = P @ X
    mma_gemm<0,0,0,0,0,1,0><<<dim3(B_DIM / 128, D_DIM / 128), GEMM_THR, GEMM_SMEM>>>(
        P_hl, XT_hl, out, nullptr,
        D_DIM, D2, D_DIM, D2, D_DIM, B_DIM, 0, 1.f, 0, 0, 0, D_DIM, 0);

    (void)n_in; (void)out_size;
}

// round 8
// speedup vs baseline: 1.2242x; 1.2242x over previous
#include <cuda_runtime.h>
#include <cuda_bf16.h>
#include <cstdint>

#define D_DIM 1792
#define B_DIM 8192
#define NB 128
#define NBLK (D_DIM / NB)     // 14
#define NB2 256
#define NBLK2 (D_DIM / NB2)   // 7
#define MREM0 1536            // largest trailing M in the chain

// ---------------- fp32 scratch ----------------
__device__ __align__(16) float g_Vn   [ (size_t)D_DIM * D_DIM ];
__device__ __align__(16) float g_G    [ (size_t)D_DIM * D_DIM ];
__device__ __align__(16) float g_RHS  [ (size_t)D_DIM * D_DIM ];
__device__ __align__(16) float g_Wt   [ (size_t)D_DIM * D_DIM ];
__device__ __align__(16) float g_Tinv [ (size_t)NBLK * NB * NB ];
__device__ __align__(16) float g_Tinv2[ (size_t)NBLK2 * NB2 * NB2 ];

// ---------------- bf16 hi|lo scratch ----------------
__device__ __align__(16) __nv_bfloat16 g_Vn_hl    [ (size_t)D_DIM * 2 * D_DIM ];
__device__ __align__(16) __nv_bfloat16 g_VnT_hl   [ (size_t)D_DIM * 2 * D_DIM ];
__device__ __align__(16) __nv_bfloat16 g_G_hl     [ (size_t)D_DIM * 2 * D_DIM ];
__device__ __align__(16) __nv_bfloat16 g_WtT_hl   [ (size_t)D_DIM * 2 * D_DIM ];
__device__ __align__(16) __nv_bfloat16 g_RHST_hl  [ (size_t)D_DIM * 2 * D_DIM ];
__device__ __align__(16) __nv_bfloat16 g_P_hl     [ (size_t)D_DIM * 2 * D_DIM ];
__device__ __align__(16) __nv_bfloat16 g_XT_hl    [ (size_t)B_DIM * 2 * D_DIM ];
__device__ __align__(16) __nv_bfloat16 g_Tinv2_hl [ (size_t)NBLK2 * NB2 * 2 * NB2 ];
__device__ __align__(16) __nv_bfloat16 g_Tinv2T_hl[ (size_t)NBLK2 * NB2 * 2 * NB2 ];
__device__ __align__(16) __nv_bfloat16 g_S_hl     [ (size_t)(NBLK2 - 1) * MREM0 * 2 * NB2 ];

// ============================================================================
// helpers
// ============================================================================
__device__ __forceinline__ uint32_t smem_u32(const void* p) {
    uint32_t a;
    asm("{ .reg .u64 t; cvta.to.shared.u64 t, %1; cvt.u32.u64 %0, t; }"
        : "=r"(a) : "l"(p));
    return a;
}
__device__ __forceinline__ void cpa16(uint32_t s, const void* g) {
    asm volatile("cp.async.cg.shared.global [%0], [%1], 16;" :: "r"(s), "l"(g));
}
#define CPA_COMMIT() asm volatile("cp.async.commit_group;" ::: "memory")
#define CPA_WAIT(n)  asm volatile("cp.async.wait_group %0;" :: "n"(n) : "memory")

#define LDSM4(r0, r1, r2, r3, addr) \
    asm volatile("ldmatrix.sync.aligned.m8n8.x4.shared.b16 {%0,%1,%2,%3}, [%4];" \
        : "=r"(r0), "=r"(r1), "=r"(r2), "=r"(r3) : "r"(addr))

#define MMA16816(d, a, b0, b1) \
    asm volatile("mma.sync.aligned.m16n8k16.row.col.f32.bf16.bf16.f32 " \
        "{%0,%1,%2,%3}, {%4,%5,%6,%7}, {%8,%9}, {%0,%1,%2,%3};" \
        : "+f"((d)[0]), "+f"((d)[1]), "+f"((d)[2]), "+f"((d)[3]) \
        : "r"((a)[0]), "r"((a)[1]), "r"((a)[2]), "r"((a)[3]), "r"(b0), "r"(b1))

// ============================================================================
// Generalized bf16-split tensor GEMM:
//   R = alpha * A @ B^T (+ C if BETA) (+ I if ADDI)
//   FPOUT: write R (fp32) to C.   HLOUT: write hi/lo split of R to Chl.
// ============================================================================
#define TILE_B   8192
#define STAGE_B  (4 * TILE_B)
#define GEMM_SMEM (3 * STAGE_B)
#define GEMM_THR 128

template <int ADDI, int TRI, int BETA, int BDIAG, int ZB, int FPOUT, int HLOUT>
__global__ void __launch_bounds__(GEMM_THR, 2)
mma_gemm(const __nv_bfloat16* __restrict__ A, const __nv_bfloat16* __restrict__ B,
         float* __restrict__ C, __nv_bfloat16* __restrict__ Chl,
         int K, int lda2, int loA, int ldb2, int loB,
         int ldc, int ldchl, float alpha,
         long long zAs, long long zBs, long long zCHs, int M0, int dM)
{
    extern __shared__ __align__(128) char smem[];
    const uint32_t s0 = smem_u32(smem);
    const int tid  = threadIdx.x;
    const int lane = tid & 31;
    const int wid  = tid >> 5;
    const int wm   = wid >> 1;
    const int wn   = wid & 1;

    if (ZB) {
        const int z = blockIdx.z;
        A += zAs * z; B += zBs * z;
        if (HLOUT) Chl += zCHs * z;
        if ((int)(blockIdx.y * 128) >= M0 - dM * z) return;
    }

    int row0, col0;
    if (TRI) {
        int bid = blockIdx.x;
        int r = 0;
        while ((r + 1) * (r + 2) / 2 <= bid) ++r;
        row0 = r * 128;
        col0 = (bid - r * (r + 1) / 2) * 128;
    } else {
        row0 = blockIdx.y * 128;
        col0 = blockIdx.x * 128;
    }

    const __nv_bfloat16* Ap = A;
    const __nv_bfloat16* Bp = B;
    int rowA0 = row0;
    if (BDIAG) {
        const int bi = row0 >> 8;
        Ap += (size_t)bi * 256 * lda2;
        Bp += bi * 256;
        rowA0 = row0 & 255;
    }
    const int T = K / 32;

    float acc[4][8][4];
#pragma unroll
    for (int i = 0; i < 4; i++)
#pragma unroll
        for (int j = 0; j < 8; j++)
#pragma unroll
            for (int q = 0; q < 4; q++) acc[i][j][q] = 0.f;

    auto load_stage = [&](int s) {
        const int k0 = s * 32;
        const uint32_t base = s0 + (s % 3) * STAGE_B;
#pragma unroll
        for (int qq = 0; qq < 4; ++qq) {
            const int jj = tid + qq * GEMM_THR;
            const int r  = jj >> 2;
            const int cc = jj & 3;
            const uint32_t soff = r * 64 + ((cc ^ ((r >> 1) & 3)) << 4);
            const __nv_bfloat16* ag = Ap + (size_t)(rowA0 + r) * lda2 + k0 + cc * 8;
            const __nv_bfloat16* bg = Bp + (size_t)(col0 + r) * ldb2 + k0 + cc * 8;
            cpa16(base + 0 * TILE_B + soff, ag);
            cpa16(base + 1 * TILE_B + soff, ag + loA);
            cpa16(base + 2 * TILE_B + soff, bg);
            cpa16(base + 3 * TILE_B + soff, bg + loB);
        }
        CPA_COMMIT();
    };

    load_stage(0); load_stage(1);

    for (int s = 0; s < T; ++s) {
        CPA_WAIT(1);
        __syncthreads();
        if (s + 2 < T) load_stage(s + 2);

        const uint32_t buf = s0 + (s % 3) * STAGE_B;
#pragma unroll
        for (int kk = 0; kk < 2; ++kk) {
            uint32_t ah[4][4], al[4][4], bb[8][2];
#pragma unroll
            for (int mi = 0; mi < 4; ++mi) {
                const int row = wm * 64 + mi * 16 + ((lane >> 3) & 1) * 8 + (lane & 7);
                const int cc  = kk * 2 + (lane >> 4);
                const uint32_t off = row * 64 + ((cc ^ ((row >> 1) & 3)) << 4);
                LDSM4(ah[mi][0], ah[mi][1], ah[mi][2], ah[mi][3], buf + 0 * TILE_B + off);
                LDSM4(al[mi][0], al[mi][1], al[mi][2], al[mi][3], buf + 1 * TILE_B + off);
            }
#pragma unroll
            for (int p = 0; p < 4; ++p) {
                const int row = wn * 64 + p * 16 + (lane >> 4) * 8 + (lane & 7);
                const int cc  = kk * 2 + ((lane >> 3) & 1);
                const uint32_t off = row * 64 + ((cc ^ ((row >> 1) & 3)) << 4);
                LDSM4(bb[p * 2][0], bb[p * 2][1], bb[p * 2 + 1][0], bb[p * 2 + 1][1],
                      buf + 2 * TILE_B + off);
            }
#pragma unroll
            for (int mi = 0; mi < 4; ++mi)
#pragma unroll
                for (int nj = 0; nj < 8; ++nj) {
                    MMA16816(acc[mi][nj], ah[mi], bb[nj][0], bb[nj][1]);  // hh
                    MMA16816(acc[mi][nj], al[mi], bb[nj][0], bb[nj][1]);  // lh
                }
#pragma unroll
            for (int p = 0; p < 4; ++p) {
                const int row = wn * 64 + p * 16 + (lane >> 4) * 8 + (lane & 7);
                const int cc  = kk * 2 + ((lane >> 3) & 1);
                const uint32_t off = row * 64 + ((cc ^ ((row >> 1) & 3)) << 4);
                LDSM4(bb[p * 2][0], bb[p * 2][1], bb[p * 2 + 1][0], bb[p * 2 + 1][1],
                      buf + 3 * TILE_B + off);
            }
#pragma unroll
            for (int mi = 0; mi < 4; ++mi)
#pragma unroll
                for (int nj = 0; nj < 8; ++nj)
                    MMA16816(acc[mi][nj], ah[mi], bb[nj][0], bb[nj][1]);  // hl
        }
    }

    const int g = lane >> 2, t = lane & 3;
    const int half = ldchl >> 1;
#pragma unroll
    for (int mi = 0; mi < 4; ++mi) {
#pragma unroll
        for (int nj = 0; nj < 8; ++nj) {
            const int r_ = row0 + wm * 64 + mi * 16 + g;
            const int c_ = col0 + wn * 64 + nj * 8 + 2 * t;
            float2 v, v2;
            v.x  = alpha * acc[mi][nj][0];
            v.y  = alpha * acc[mi][nj][1];
            v2.x = alpha * acc[mi][nj][2];
            v2.y = alpha * acc[mi][nj][3];
            if (BETA) {
                float2 o  = *reinterpret_cast<const float2*>(&C[(size_t)r_ * ldc + c_]);
                float2 o2 = *reinterpret_cast<const float2*>(&C[(size_t)(r_ + 8) * ldc + c_]);
                v.x += o.x;  v.y += o.y;
                v2.x += o2.x; v2.y += o2.y;
            }
            if (ADDI) {
                if (r_ == c_)     v.x  += 1.f;
                if (r_ == c_ + 1) v.y  += 1.f;
                if (r_ + 8 == c_)     v2.x += 1.f;
                if (r_ + 8 == c_ + 1) v2.y += 1.f;
            }
            if (FPOUT) {
                *reinterpret_cast<float2*>(&C[(size_t)r_ * ldc + c_])       = v;
                *reinterpret_cast<float2*>(&C[(size_t)(r_ + 8) * ldc + c_]) = v2;
            }
            if (HLOUT) {
                __nv_bfloat162 h, h2, l, l2;
                h.x  = __float2bfloat16(v.x);   h.y  = __float2bfloat16(v.y);
                h2.x = __float2bfloat16(v2.x);  h2.y = __float2bfloat16(v2.y);
                l.x  = __float2bfloat16(v.x  - __bfloat162float(h.x));
                l.y  = __float2bfloat16(v.y  - __bfloat162float(h.y));
                l2.x = __float2bfloat16(v2.x - __bfloat162float(h2.x));
                l2.y = __float2bfloat16(v2.y - __bfloat162float(h2.y));
                *reinterpret_cast<__nv_bfloat162*>(&Chl[(size_t)r_ * ldchl + c_])              = h;
                *reinterpret_cast<__nv_bfloat162*>(&Chl[(size_t)r_ * ldchl + half + c_])       = l;
                *reinterpret_cast<__nv_bfloat162*>(&Chl[(size_t)(r_ + 8) * ldchl + c_])        = h2;
                *reinterpret_cast<__nv_bfloat162*>(&Chl[(size_t)(r_ + 8) * ldchl + half + c_]) = l2;
            }
        }
    }
}

// ============================================================================
// Row-normalize U -> Vn (fp32), Vn_hl (hi|lo), RHS = 2*Vn
// ============================================================================
__global__ void normalize_kernel(const float* __restrict__ U) {
    int row = blockIdx.x;
    const float* u = U + (size_t)row * D_DIM;
    __shared__ float red[256];
    float s = 0.f;
    for (int c = threadIdx.x; c < D_DIM; c += 256) { float v = u[c]; s += v * v; }
    red[threadIdx.x] = s;
    __syncthreads();
    for (int off = 128; off > 0; off >>= 1) {
        if (threadIdx.x < off) red[threadIdx.x] += red[threadIdx.x + off];
        __syncthreads();
    }
    float inv = rsqrtf(red[0]);
    for (int c = threadIdx.x; c < D_DIM; c += 256) {
        float v = u[c] * inv;
        g_Vn [(size_t)row * D_DIM + c] = v;
        g_RHS[(size_t)row * D_DIM + c] = 2.f * v;
        __nv_bfloat16 h = __float2bfloat16(v);
        g_Vn_hl[(size_t)row * 2 * D_DIM + c]         = h;
        g_Vn_hl[(size_t)row * 2 * D_DIM + D_DIM + c] =
            __float2bfloat16(v - __bfloat162float(h));
    }
}

// ============================================================================
// conversions
// ============================================================================
__global__ void conv_hl(const float* __restrict__ in, __nv_bfloat16* __restrict__ out, int C) {
    int r = blockIdx.y;
    int c = blockIdx.x * 256 + threadIdx.x;
    float x = in[(size_t)r * C + c];
    __nv_bfloat16 h = __float2bfloat16(x);
    out[(size_t)r * 2 * C + c]     = h;
    out[(size_t)r * 2 * C + C + c] = __float2bfloat16(x - __bfloat162float(h));
}
__global__ void conv_hl_T_gen(const float* __restrict__ in, int R, int C,
                              __nv_bfloat16* __restrict__ out, int outld,
                              int outcol0, int looff,
                              long long zIn, long long zOut) {
    in  += zIn  * blockIdx.z;
    out += zOut * blockIdx.z;
    __shared__ float t[32][33];
    int r0 = blockIdx.y * 32, c0 = blockIdx.x * 32;
    int tx = threadIdx.x, ty = threadIdx.y;
    for (int i = 0; i < 32; i += 8)
        t[ty + i][tx] = in[(size_t)(r0 + ty + i) * C + c0 + tx];
    __syncthreads();
    for (int i = 0; i < 32; i += 8) {
        float x = t[tx][ty + i];
        __nv_bfloat16 h = __float2bfloat16(x);
        out[(size_t)(c0 + ty + i) * outld + outcol0 + r0 + tx] = h;
        out[(size_t)(c0 + ty + i) * outld + looff + outcol0 + r0 + tx] =
            __float2bfloat16(x - __bfloat162float(h));
    }
}

// ============================================================================
// Diag-block inversion, COLUMN-SLICED: grid (NBLK, 8); each CTA computes a
// 16-column slice of one 128-block inverse. 112 CTAs instead of 14.
// ============================================================================
#define INV_SMEM ((128 * 129 + 128 * 17) * (int)sizeof(float))
__global__ void invert_diag_kernel() {
    extern __shared__ float sm[];
    float (*Gs)[129] = (float (*)[129])sm;
    float (*Zs)[17]  = (float (*)[17])(sm + 128 * 129);
    const int b0 = blockIdx.x * NB;
    const int c0 = blockIdx.y * 16;
    const int tid = threadIdx.x;

    for (int idx = tid; idx < 128 * 128; idx += 256) {
        int r = idx >> 7, c = idx & 127;
        Gs[r][c] = g_G[(size_t)(b0 + r) * D_DIM + b0 + c];
    }
    for (int idx = tid; idx < 128 * 16; idx += 256) {
        int r = idx >> 4, c = idx & 15;
        Zs[r][c] = (r == c0 + c) ? 1.f : 0.f;
    }
    __syncthreads();
    for (int j = 0; j < NB - 1; ++j) {
        const int rows = NB - 1 - j;
        for (int idx = tid; idx < rows * 16; idx += 256) {
            int r = j + 1 + (idx >> 4);
            int c = idx & 15;
            Zs[r][c] -= 2.f * Gs[r][j] * Zs[j][c];
        }
        __syncthreads();
    }
    float* outp = g_Tinv + (size_t)blockIdx.x * NB * NB;
    for (int idx = tid; idx < 128 * 16; idx += 256) {
        int r = idx >> 4, c = idx & 15;
        outp[(size_t)r * NB + c0 + c] = Zs[r][c];
    }
}

// ============================================================================
// Pair-combine (round-6 form): 7 Tinv2 blocks (256x256) fp32, coalesced.
// ============================================================================
#define CMB_SMEM (3 * 128 * 129 * (int)sizeof(float))
__global__ void __launch_bounds__(256, 1) combine_tinv() {
    extern __shared__ float sm[];
    float (*Abuf)[129] = (float (*)[129])sm;
    float (*Bbuf)[129] = (float (*)[129])(sm + 128 * 129);
    float (*Tm)[129]   = (float (*)[129])(sm + 2 * 128 * 129);
    const int p = blockIdx.x;
    const int tid = threadIdx.x;
    const int trow = (tid / 16) * 8;
    const int tcol = (tid % 16) * 8;
    const float* InvA = g_Tinv + (size_t)(2 * p)     * NB * NB;
    const float* InvB = g_Tinv + (size_t)(2 * p + 1) * NB * NB;
    const size_t g21 = (size_t)(p * 256 + 128) * D_DIM + p * 256;

    for (int idx = tid; idx < 128 * 128; idx += 256) {
        int r = idx >> 7, c = idx & 127;
        Abuf[r][c] = 2.f * g_G[g21 + (size_t)r * D_DIM + c];
        Bbuf[r][c] = InvA[idx];
    }
    __syncthreads();
    {
        float acc[8][8];
#pragma unroll
        for (int i = 0; i < 8; i++)
#pragma unroll
            for (int j = 0; j < 8; j++) acc[i][j] = 0.f;
        for (int k = 0; k < 128; ++k) {
            float a[8], b[8];
#pragma unroll
            for (int i = 0; i < 8; i++) a[i] = Abuf[trow + i][k];
#pragma unroll
            for (int j = 0; j < 8; j++) b[j] = Bbuf[k][tcol + j];
#pragma unroll
            for (int i = 0; i < 8; i++)
#pragma unroll
                for (int j = 0; j < 8; j++) acc[i][j] += a[i] * b[j];
        }
        __syncthreads();
#pragma unroll
        for (int i = 0; i < 8; i++)
#pragma unroll
            for (int j = 0; j < 8; j++) Tm[trow + i][tcol + j] = acc[i][j];
    }
    __syncthreads();
    for (int idx = tid; idx < 128 * 128; idx += 256) {
        int r = idx >> 7, c = idx & 127;
        Abuf[r][c] = InvB[idx];
    }
    __syncthreads();
    float* outp = g_Tinv2 + (size_t)p * NB2 * NB2;
    {
        float acc[8][8];
#pragma unroll
        for (int i = 0; i < 8; i++)
#pragma unroll
            for (int j = 0; j < 8; j++) acc[i][j] = 0.f;
        for (int k = 0; k < 128; ++k) {
            float a[8], b[8];
#pragma unroll
            for (int i = 0; i < 8; i++) a[i] = Abuf[trow + i][k];
#pragma unroll
            for (int j = 0; j < 8; j++) b[j] = Tm[k][tcol + j];
#pragma unroll
            for (int i = 0; i < 8; i++)
#pragma unroll
                for (int j = 0; j < 8; j++) acc[i][j] += a[i] * b[j];
        }
#pragma unroll
        for (int i = 0; i < 8; i++) {
#pragma unroll
            for (int j = 0; j < 8; j++) {
                int r = trow + i, c = tcol + j;
                outp[(size_t)r * NB2 + c]               = Bbuf[r][c];
                outp[(size_t)r * NB2 + 128 + c]         = 0.f;
                outp[(size_t)(128 + r) * NB2 + c]       = -acc[i][j];
                outp[(size_t)(128 + r) * NB2 + 128 + c] = Abuf[r][c];
            }
        }
    }
}

// ============================================================================
extern "C" void kernel_launch(void* const* d_in, const int* in_sizes, int n_in,
                              void* d_out, int out_size)
{
    const float* X;
    const float* U;
    if (in_sizes[0] == D_DIM * D_DIM && in_sizes[1] != D_DIM * D_DIM) {
        U = (const float*)d_in[0]; X = (const float*)d_in[1];
    } else {
        X = (const float*)d_in[0]; U = (const float*)d_in[1];
    }
    float* out = (float*)d_out;

    float *Vn, *G, *RHS, *Wt, *Tinv2;
    cudaGetSymbolAddress((void**)&Vn,    g_Vn);
    cudaGetSymbolAddress((void**)&G,     g_G);
    cudaGetSymbolAddress((void**)&RHS,   g_RHS);
    cudaGetSymbolAddress((void**)&Wt,    g_Wt);
    cudaGetSymbolAddress((void**)&Tinv2, g_Tinv2);
    __nv_bfloat16 *Vn_hl, *VnT_hl, *G_hl, *WtT_hl, *RHST_hl, *P_hl, *XT_hl;
    __nv_bfloat16 *Tinv2_hl, *Tinv2T_hl, *S_hl;
    cudaGetSymbolAddress((void**)&Vn_hl,     g_Vn_hl);
    cudaGetSymbolAddress((void**)&VnT_hl,    g_VnT_hl);
    cudaGetSymbolAddress((void**)&G_hl,      g_G_hl);
    cudaGetSymbolAddress((void**)&WtT_hl,    g_WtT_hl);
    cudaGetSymbolAddress((void**)&RHST_hl,   g_RHST_hl);
    cudaGetSymbolAddress((void**)&P_hl,      g_P_hl);
    cudaGetSymbolAddress((void**)&XT_hl,     g_XT_hl);
    cudaGetSymbolAddress((void**)&Tinv2_hl,  g_Tinv2_hl);
    cudaGetSymbolAddress((void**)&Tinv2T_hl, g_Tinv2T_hl);
    cudaGetSymbolAddress((void**)&S_hl,      g_S_hl);

    cudaFuncSetAttribute(invert_diag_kernel,
                         cudaFuncAttributeMaxDynamicSharedMemorySize, INV_SMEM);
    cudaFuncSetAttribute(combine_tinv,
                         cudaFuncAttributeMaxDynamicSharedMemorySize, CMB_SMEM);
    cudaFuncSetAttribute(mma_gemm<0,1,0,0,0,1,1>,
                         cudaFuncAttributeMaxDynamicSharedMemorySize, GEMM_SMEM);
    cudaFuncSetAttribute(mma_gemm<0,0,0,0,1,0,1>,
                         cudaFuncAttributeMaxDynamicSharedMemorySize, GEMM_SMEM);
    cudaFuncSetAttribute(mma_gemm<0,0,1,0,0,1,0>,
                         cudaFuncAttributeMaxDynamicSharedMemorySize, GEMM_SMEM);
    cudaFuncSetAttribute(mma_gemm<0,0,0,1,0,1,0>,
                         cudaFuncAttributeMaxDynamicSharedMemorySize, GEMM_SMEM);
    cudaFuncSetAttribute(mma_gemm<1,0,0,0,0,0,1>,
                         cudaFuncAttributeMaxDynamicSharedMemorySize, GEMM_SMEM);
    cudaFuncSetAttribute(mma_gemm<0,0,0,0,0,1,0>,
                         cudaFuncAttributeMaxDynamicSharedMemorySize, GEMM_SMEM);

    const dim3 t32x8(32, 8);
    const int D2 = 2 * D_DIM;   // 3584

    // 0) Vn (+hl fused), RHS = 2*Vn
    normalize_kernel<<<D_DIM, 256>>>(U);
    // 1) VnT_hl
    conv_hl_T_gen<<<dim3(D_DIM / 32, D_DIM / 32), t32x8>>>(
        Vn, D_DIM, D_DIM, VnT_hl, D2, 0, D_DIM, 0, 0);
    // 2) G = Vn @ Vn^T (lower tiles; fp32 + hl fused)
    mma_gemm<0,1,0,0,0,1,1><<<NBLK * (NBLK + 1) / 2, GEMM_THR, GEMM_SMEM>>>(
        Vn_hl, Vn_hl, G, G_hl, D_DIM, D2, D_DIM, D2, D_DIM, D_DIM, D2, 1.f,
        0, 0, 0, D_DIM, 0);
    // 3) invert 14 diag blocks — column-sliced, 112 CTAs
    invert_diag_kernel<<<dim3(NBLK, 8), 256, INV_SMEM>>>();
    // 4) combine into 7 Tinv2 blocks (fp32, coalesced)
    combine_tinv<<<NBLK2, 256, CMB_SMEM>>>();
    // 4b) Tinv2 hi/lo splits (row-major and transposed)
    conv_hl<<<dim3(1, NBLK2 * NB2), 256>>>(Tinv2, Tinv2_hl, NB2);
    conv_hl_T_gen<<<dim3(NB2 / 32, NB2 / 32, NBLK2), t32x8>>>(
        Tinv2, NB2, NB2, Tinv2T_hl, 2 * NB2, 0, NB2,
        (long long)NB2 * NB2, (long long)NB2 * 2 * NB2);
    // 5) S_i = 2 * G[(i+1)*256:, blk i] @ Tinv2_i^T  (z-batched, hl-only out)
    mma_gemm<0,0,0,0,1,0,1><<<dim3(NB2 / 128, MREM0 / 128, NBLK2 - 1), GEMM_THR, GEMM_SMEM>>>(
        G_hl + (size_t)NB2 * D2, Tinv2T_hl, nullptr, S_hl,
        NB2, D2, D_DIM, 2 * NB2, NB2, 0, 2 * NB2, 2.f,
        (long long)NB2 * D2 + NB2,
        (long long)NB2 * 2 * NB2,
        (long long)MREM0 * 2 * NB2,
        MREM0, NB2);

    // 6..) chain: finalize RHS^T slice, then trailing update via S_i
    for (int i = 0; i < NBLK2; ++i) {
        conv_hl_T_gen<<<dim3(D_DIM / 32, NB2 / 32), t32x8>>>(
            RHS + (size_t)i * NB2 * D_DIM, NB2, D_DIM,
            RHST_hl, D2, i * NB2, D_DIM, 0, 0);
        int mrem = D_DIM - (i + 1) * NB2;
        if (mrem > 0) {
            mma_gemm<0,0,1,0,0,1,0><<<dim3(D_DIM / 128, mrem / 128), GEMM_THR, GEMM_SMEM>>>(
                S_hl + (size_t)i * MREM0 * 2 * NB2,
                RHST_hl + (size_t)i * NB2,
                RHS + (size_t)(i + 1) * NB2 * D_DIM, nullptr,
                NB2, 2 * NB2, NB2, D2, D_DIM, D_DIM, 0, -1.f,
                0, 0, 0, mrem, 0);
        }
    }

    // Wt = blockdiag(Tinv2) @ RHS
    mma_gemm<0,0,0,1,0,1,0><<<dim3(D_DIM / 128, D_DIM / 128), GEMM_THR, GEMM_SMEM>>>(
        Tinv2_hl, RHST_hl, Wt, nullptr,
        NB2, 2 * NB2, NB2, D2, D_DIM, D_DIM, 0, 1.f, 0, 0, 0, D_DIM, 0);
    conv_hl_T_gen<<<dim3(D_DIM / 32, D_DIM / 32), t32x8>>>(
        Wt, D_DIM, D_DIM, WtT_hl, D2, 0, D_DIM, 0, 0);

    // P = I - Wt^T @ Vn  (hl-only out)
    mma_gemm<1,0,0,0,0,0,1><<<dim3(D_DIM / 128, D_DIM / 128), GEMM_THR, GEMM_SMEM>>>(
        WtT_hl, VnT_hl, nullptr, P_hl,
        D_DIM, D2, D_DIM, D2, D_DIM, 0, D2, -1.f, 0, 0, 0, D_DIM, 0);

    // X^T split
    conv_hl_T_gen<<<dim3(B_DIM / 32, D_DIM / 32), t32x8>>>(
        X, D_DIM, B_DIM, XT_hl, D2, 0, D_DIM, 0, 0);

    // out = P @ X
    mma_gemm<0,0,0,0,0,1,0><<<dim3(B_DIM / 128, D_DIM / 128), GEMM_THR, GEMM_SMEM>>>(
        P_hl, XT_hl, out, nullptr,
        D_DIM, D2, D_DIM, D2, D_DIM, B_DIM, 0, 1.f, 0, 0, 0, D_DIM, 0);

    (void)n_in; (void)out_size;
}

// round 9
// speedup vs baseline: 1.6433x; 1.3423x over previous
#include <cuda_runtime.h>
#include <cuda_bf16.h>
#include <cuda_fp16.h>
#include <cstdint>

#define D_DIM 1792
#define B_DIM 8192
#define NB 128
#define NBLK (D_DIM / NB)     // 14
#define NB2 256
#define NBLK2 (D_DIM / NB2)   // 7
#define MREM0 1536

// ---------------- fp32 scratch ----------------
__device__ __align__(16) float g_Vn   [ (size_t)D_DIM * D_DIM ];
__device__ __align__(16) float g_G    [ (size_t)D_DIM * D_DIM ];
__device__ __align__(16) float g_RHS  [ (size_t)D_DIM * D_DIM ];
__device__ __align__(16) float g_Wt   [ (size_t)D_DIM * D_DIM ];
__device__ __align__(16) float g_Tinv [ (size_t)NBLK * NB * NB ];
__device__ __align__(16) float g_Tinv2[ (size_t)NBLK2 * NB2 * NB2 ];

// ---------------- bf16 hi|lo scratch ----------------
__device__ __align__(16) __nv_bfloat16 g_Vn_hl    [ (size_t)D_DIM * 2 * D_DIM ];
__device__ __align__(16) __nv_bfloat16 g_VnT_hl   [ (size_t)D_DIM * 2 * D_DIM ];
__device__ __align__(16) __nv_bfloat16 g_G_hl     [ (size_t)D_DIM * 2 * D_DIM ];
__device__ __align__(16) __nv_bfloat16 g_WtT_hl   [ (size_t)D_DIM * 2 * D_DIM ];
__device__ __align__(16) __nv_bfloat16 g_RHST_hl  [ (size_t)D_DIM * 2 * D_DIM ];
__device__ __align__(16) __nv_bfloat16 g_Tinv2_hl [ (size_t)NBLK2 * NB2 * 2 * NB2 ];
__device__ __align__(16) __nv_bfloat16 g_Tinv2T_hl[ (size_t)NBLK2 * NB2 * 2 * NB2 ];
__device__ __align__(16) __nv_bfloat16 g_S_hl     [ (size_t)(NBLK2 - 1) * MREM0 * 2 * NB2 ];

// ---------------- fp16 single-precision operands for PX ----------------
__device__ __align__(16) __half g_P_h [ (size_t)D_DIM * D_DIM ];
__device__ __align__(16) __half g_XT_h[ (size_t)B_DIM * D_DIM ];

// ============================================================================
// helpers
// ============================================================================
__device__ __forceinline__ uint32_t smem_u32(const void* p) {
    uint32_t a;
    asm("{ .reg .u64 t; cvta.to.shared.u64 t, %1; cvt.u32.u64 %0, t; }"
        : "=r"(a) : "l"(p));
    return a;
}
__device__ __forceinline__ void cpa16(uint32_t s, const void* g) {
    asm volatile("cp.async.cg.shared.global [%0], [%1], 16;" :: "r"(s), "l"(g));
}
#define CPA_COMMIT() asm volatile("cp.async.commit_group;" ::: "memory")
#define CPA_WAIT(n)  asm volatile("cp.async.wait_group %0;" :: "n"(n) : "memory")

#define LDSM4(r0, r1, r2, r3, addr) \
    asm volatile("ldmatrix.sync.aligned.m8n8.x4.shared.b16 {%0,%1,%2,%3}, [%4];" \
        : "=r"(r0), "=r"(r1), "=r"(r2), "=r"(r3) : "r"(addr))

#define MMA16816(d, a, b0, b1) \
    asm volatile("mma.sync.aligned.m16n8k16.row.col.f32.bf16.bf16.f32 " \
        "{%0,%1,%2,%3}, {%4,%5,%6,%7}, {%8,%9}, {%0,%1,%2,%3};" \
        : "+f"((d)[0]), "+f"((d)[1]), "+f"((d)[2]), "+f"((d)[3]) \
        : "r"((a)[0]), "r"((a)[1]), "r"((a)[2]), "r"((a)[3]), "r"(b0), "r"(b1))

#define MMA16816H(d, a, b0, b1) \
    asm volatile("mma.sync.aligned.m16n8k16.row.col.f32.f16.f16.f32 " \
        "{%0,%1,%2,%3}, {%4,%5,%6,%7}, {%8,%9}, {%0,%1,%2,%3};" \
        : "+f"((d)[0]), "+f"((d)[1]), "+f"((d)[2]), "+f"((d)[3]) \
        : "r"((a)[0]), "r"((a)[1]), "r"((a)[2]), "r"((a)[3]), "r"(b0), "r"(b1))

// ============================================================================
// Generalized bf16-split tensor GEMM (3 products hh+lh+hl):
//   R = alpha * A @ B^T (+ C if BETA) (+ I if ADDI)
//   FPOUT: fp32 out.  HLOUT: bf16 hi/lo out.  F16OUT: fp16 single out (Chl).
// ============================================================================
#define TILE_B   8192
#define STAGE_B  (4 * TILE_B)
#define GEMM_SMEM (3 * STAGE_B)
#define GEMM_THR 128

template <int ADDI, int TRI, int BETA, int BDIAG, int ZB, int FPOUT, int HLOUT, int F16OUT>
__global__ void __launch_bounds__(GEMM_THR, 2)
mma_gemm(const __nv_bfloat16* __restrict__ A, const __nv_bfloat16* __restrict__ B,
         float* __restrict__ C, void* __restrict__ Chl,
         int K, int lda2, int loA, int ldb2, int loB,
         int ldc, int ldchl, float alpha,
         long long zAs, long long zBs, long long zCHs, int M0, int dM)
{
    extern __shared__ __align__(128) char smem[];
    const uint32_t s0 = smem_u32(smem);
    const int tid  = threadIdx.x;
    const int lane = tid & 31;
    const int wid  = tid >> 5;
    const int wm   = wid >> 1;
    const int wn   = wid & 1;

    if (ZB) {
        const int z = blockIdx.z;
        A += zAs * z; B += zBs * z;
        if (HLOUT) Chl = (void*)((__nv_bfloat16*)Chl + zCHs * z);
        if ((int)(blockIdx.y * 128) >= M0 - dM * z) return;
    }

    int row0, col0;
    if (TRI) {
        int bid = blockIdx.x;
        int r = 0;
        while ((r + 1) * (r + 2) / 2 <= bid) ++r;
        row0 = r * 128;
        col0 = (bid - r * (r + 1) / 2) * 128;
    } else {
        row0 = blockIdx.y * 128;
        col0 = blockIdx.x * 128;
    }

    const __nv_bfloat16* Ap = A;
    const __nv_bfloat16* Bp = B;
    int rowA0 = row0;
    if (BDIAG) {
        const int bi = row0 >> 8;
        Ap += (size_t)bi * 256 * lda2;
        Bp += bi * 256;
        rowA0 = row0 & 255;
    }
    const int T = K / 32;

    float acc[4][8][4];
#pragma unroll
    for (int i = 0; i < 4; i++)
#pragma unroll
        for (int j = 0; j < 8; j++)
#pragma unroll
            for (int q = 0; q < 4; q++) acc[i][j][q] = 0.f;

    auto load_stage = [&](int s) {
        const int k0 = s * 32;
        const uint32_t base = s0 + (s % 3) * STAGE_B;
#pragma unroll
        for (int qq = 0; qq < 4; ++qq) {
            const int jj = tid + qq * GEMM_THR;
            const int r  = jj >> 2;
            const int cc = jj & 3;
            const uint32_t soff = r * 64 + ((cc ^ ((r >> 1) & 3)) << 4);
            const __nv_bfloat16* ag = Ap + (size_t)(rowA0 + r) * lda2 + k0 + cc * 8;
            const __nv_bfloat16* bg = Bp + (size_t)(col0 + r) * ldb2 + k0 + cc * 8;
            cpa16(base + 0 * TILE_B + soff, ag);
            cpa16(base + 1 * TILE_B + soff, ag + loA);
            cpa16(base + 2 * TILE_B + soff, bg);
            cpa16(base + 3 * TILE_B + soff, bg + loB);
        }
        CPA_COMMIT();
    };

    load_stage(0); load_stage(1);

    for (int s = 0; s < T; ++s) {
        CPA_WAIT(1);
        __syncthreads();
        if (s + 2 < T) load_stage(s + 2);

        const uint32_t buf = s0 + (s % 3) * STAGE_B;
#pragma unroll
        for (int kk = 0; kk < 2; ++kk) {
            uint32_t ah[4][4], al[4][4], bb[8][2];
#pragma unroll
            for (int mi = 0; mi < 4; ++mi) {
                const int row = wm * 64 + mi * 16 + ((lane >> 3) & 1) * 8 + (lane & 7);
                const int cc  = kk * 2 + (lane >> 4);
                const uint32_t off = row * 64 + ((cc ^ ((row >> 1) & 3)) << 4);
                LDSM4(ah[mi][0], ah[mi][1], ah[mi][2], ah[mi][3], buf + 0 * TILE_B + off);
                LDSM4(al[mi][0], al[mi][1], al[mi][2], al[mi][3], buf + 1 * TILE_B + off);
            }
#pragma unroll
            for (int p = 0; p < 4; ++p) {
                const int row = wn * 64 + p * 16 + (lane >> 4) * 8 + (lane & 7);
                const int cc  = kk * 2 + ((lane >> 3) & 1);
                const uint32_t off = row * 64 + ((cc ^ ((row >> 1) & 3)) << 4);
                LDSM4(bb[p * 2][0], bb[p * 2][1], bb[p * 2 + 1][0], bb[p * 2 + 1][1],
                      buf + 2 * TILE_B + off);
            }
#pragma unroll
            for (int mi = 0; mi < 4; ++mi)
#pragma unroll
                for (int nj = 0; nj < 8; ++nj) {
                    MMA16816(acc[mi][nj], ah[mi], bb[nj][0], bb[nj][1]);  // hh
                    MMA16816(acc[mi][nj], al[mi], bb[nj][0], bb[nj][1]);  // lh
                }
#pragma unroll
            for (int p = 0; p < 4; ++p) {
                const int row = wn * 64 + p * 16 + (lane >> 4) * 8 + (lane & 7);
                const int cc  = kk * 2 + ((lane >> 3) & 1);
                const uint32_t off = row * 64 + ((cc ^ ((row >> 1) & 3)) << 4);
                LDSM4(bb[p * 2][0], bb[p * 2][1], bb[p * 2 + 1][0], bb[p * 2 + 1][1],
                      buf + 3 * TILE_B + off);
            }
#pragma unroll
            for (int mi = 0; mi < 4; ++mi)
#pragma unroll
                for (int nj = 0; nj < 8; ++nj)
                    MMA16816(acc[mi][nj], ah[mi], bb[nj][0], bb[nj][1]);  // hl
        }
    }

    const int g = lane >> 2, t = lane & 3;
    const int half = ldchl >> 1;
#pragma unroll
    for (int mi = 0; mi < 4; ++mi) {
#pragma unroll
        for (int nj = 0; nj < 8; ++nj) {
            const int r_ = row0 + wm * 64 + mi * 16 + g;
            const int c_ = col0 + wn * 64 + nj * 8 + 2 * t;
            float2 v, v2;
            v.x  = alpha * acc[mi][nj][0];
            v.y  = alpha * acc[mi][nj][1];
            v2.x = alpha * acc[mi][nj][2];
            v2.y = alpha * acc[mi][nj][3];
            if (BETA) {
                float2 o  = *reinterpret_cast<const float2*>(&C[(size_t)r_ * ldc + c_]);
                float2 o2 = *reinterpret_cast<const float2*>(&C[(size_t)(r_ + 8) * ldc + c_]);
                v.x += o.x;  v.y += o.y;
                v2.x += o2.x; v2.y += o2.y;
            }
            if (ADDI) {
                if (r_ == c_)     v.x  += 1.f;
                if (r_ == c_ + 1) v.y  += 1.f;
                if (r_ + 8 == c_)     v2.x += 1.f;
                if (r_ + 8 == c_ + 1) v2.y += 1.f;
            }
            if (FPOUT) {
                *reinterpret_cast<float2*>(&C[(size_t)r_ * ldc + c_])       = v;
                *reinterpret_cast<float2*>(&C[(size_t)(r_ + 8) * ldc + c_]) = v2;
            }
            if (HLOUT) {
                __nv_bfloat16* Cb = (__nv_bfloat16*)Chl;
                __nv_bfloat162 h, h2, l, l2;
                h.x  = __float2bfloat16(v.x);   h.y  = __float2bfloat16(v.y);
                h2.x = __float2bfloat16(v2.x);  h2.y = __float2bfloat16(v2.y);
                l.x  = __float2bfloat16(v.x  - __bfloat162float(h.x));
                l.y  = __float2bfloat16(v.y  - __bfloat162float(h.y));
                l2.x = __float2bfloat16(v2.x - __bfloat162float(h2.x));
                l2.y = __float2bfloat16(v2.y - __bfloat162float(h2.y));
                *reinterpret_cast<__nv_bfloat162*>(&Cb[(size_t)r_ * ldchl + c_])              = h;
                *reinterpret_cast<__nv_bfloat162*>(&Cb[(size_t)r_ * ldchl + half + c_])       = l;
                *reinterpret_cast<__nv_bfloat162*>(&Cb[(size_t)(r_ + 8) * ldchl + c_])        = h2;
                *reinterpret_cast<__nv_bfloat162*>(&Cb[(size_t)(r_ + 8) * ldchl + half + c_]) = l2;
            }
            if (F16OUT) {
                __half* Ch = (__half*)Chl;
                *reinterpret_cast<__half2*>(&Ch[(size_t)r_ * ldchl + c_]) =
                    __floats2half2_rn(v.x, v.y);
                *reinterpret_cast<__half2*>(&Ch[(size_t)(r_ + 8) * ldchl + c_]) =
                    __floats2half2_rn(v2.x, v2.y);
            }
        }
    }
}

// ============================================================================
// fp16 single-product GEMM (for out = P @ X):  C = A @ B^T, fp32 accumulate.
//   A: [M, K] fp16 row-major.  B: [N, K] fp16 row-major.
// ============================================================================
#define STAGE_H  (2 * TILE_B)          // Ah, Bh (fp16 128x32 each)
#define GEMMH_SMEM (3 * STAGE_H)

__global__ void __launch_bounds__(GEMM_THR, 2)
mma_gemm_h(const __half* __restrict__ A, const __half* __restrict__ B,
           float* __restrict__ C, int K, int lda, int ldb, int ldc)
{
    extern __shared__ __align__(128) char smem[];
    const uint32_t s0 = smem_u32(smem);
    const int tid  = threadIdx.x;
    const int lane = tid & 31;
    const int wid  = tid >> 5;
    const int wm   = wid >> 1;
    const int wn   = wid & 1;
    const int row0 = blockIdx.y * 128;
    const int col0 = blockIdx.x * 128;
    const int T = K / 32;

    float acc[4][8][4];
#pragma unroll
    for (int i = 0; i < 4; i++)
#pragma unroll
        for (int j = 0; j < 8; j++)
#pragma unroll
            for (int q = 0; q < 4; q++) acc[i][j][q] = 0.f;

    auto load_stage = [&](int s) {
        const int k0 = s * 32;
        const uint32_t base = s0 + (s % 3) * STAGE_H;
#pragma unroll
        for (int qq = 0; qq < 4; ++qq) {
            const int jj = tid + qq * GEMM_THR;
            const int r  = jj >> 2;
            const int cc = jj & 3;
            const uint32_t soff = r * 64 + ((cc ^ ((r >> 1) & 3)) << 4);
            cpa16(base + soff,          A + (size_t)(row0 + r) * lda + k0 + cc * 8);
            cpa16(base + TILE_B + soff, B + (size_t)(col0 + r) * ldb + k0 + cc * 8);
        }
        CPA_COMMIT();
    };

    load_stage(0); load_stage(1);

    for (int s = 0; s < T; ++s) {
        CPA_WAIT(1);
        __syncthreads();
        if (s + 2 < T) load_stage(s + 2);

        const uint32_t buf = s0 + (s % 3) * STAGE_H;
#pragma unroll
        for (int kk = 0; kk < 2; ++kk) {
            uint32_t ah[4][4], bb[8][2];
#pragma unroll
            for (int mi = 0; mi < 4; ++mi) {
                const int row = wm * 64 + mi * 16 + ((lane >> 3) & 1) * 8 + (lane & 7);
                const int cc  = kk * 2 + (lane >> 4);
                const uint32_t off = row * 64 + ((cc ^ ((row >> 1) & 3)) << 4);
                LDSM4(ah[mi][0], ah[mi][1], ah[mi][2], ah[mi][3], buf + off);
            }
#pragma unroll
            for (int p = 0; p < 4; ++p) {
                const int row = wn * 64 + p * 16 + (lane >> 4) * 8 + (lane & 7);
                const int cc  = kk * 2 + ((lane >> 3) & 1);
                const uint32_t off = row * 64 + ((cc ^ ((row >> 1) & 3)) << 4);
                LDSM4(bb[p * 2][0], bb[p * 2][1], bb[p * 2 + 1][0], bb[p * 2 + 1][1],
                      buf + TILE_B + off);
            }
#pragma unroll
            for (int mi = 0; mi < 4; ++mi)
#pragma unroll
                for (int nj = 0; nj < 8; ++nj)
                    MMA16816H(acc[mi][nj], ah[mi], bb[nj][0], bb[nj][1]);
        }
    }

    const int g = lane >> 2, t = lane & 3;
#pragma unroll
    for (int mi = 0; mi < 4; ++mi) {
#pragma unroll
        for (int nj = 0; nj < 8; ++nj) {
            const int r_ = row0 + wm * 64 + mi * 16 + g;
            const int c_ = col0 + wn * 64 + nj * 8 + 2 * t;
            *reinterpret_cast<float2*>(&C[(size_t)r_ * ldc + c_]) =
                make_float2(acc[mi][nj][0], acc[mi][nj][1]);
            *reinterpret_cast<float2*>(&C[(size_t)(r_ + 8) * ldc + c_]) =
                make_float2(acc[mi][nj][2], acc[mi][nj][3]);
        }
    }
}

// ============================================================================
// Row-normalize U -> Vn (fp32), Vn_hl (hi|lo), RHS = 2*Vn
// ============================================================================
__global__ void normalize_kernel(const float* __restrict__ U) {
    int row = blockIdx.x;
    const float* u = U + (size_t)row * D_DIM;
    __shared__ float red[256];
    float s = 0.f;
    for (int c = threadIdx.x; c < D_DIM; c += 256) { float v = u[c]; s += v * v; }
    red[threadIdx.x] = s;
    __syncthreads();
    for (int off = 128; off > 0; off >>= 1) {
        if (threadIdx.x < off) red[threadIdx.x] += red[threadIdx.x + off];
        __syncthreads();
    }
    float inv = rsqrtf(red[0]);
    for (int c = threadIdx.x; c < D_DIM; c += 256) {
        float v = u[c] * inv;
        g_Vn [(size_t)row * D_DIM + c] = v;
        g_RHS[(size_t)row * D_DIM + c] = 2.f * v;
        __nv_bfloat16 h = __float2bfloat16(v);
        g_Vn_hl[(size_t)row * 2 * D_DIM + c]         = h;
        g_Vn_hl[(size_t)row * 2 * D_DIM + D_DIM + c] =
            __float2bfloat16(v - __bfloat162float(h));
    }
}

// ============================================================================
// conversions
// ============================================================================
__global__ void conv_hl(const float* __restrict__ in, __nv_bfloat16* __restrict__ out, int C) {
    int r = blockIdx.y;
    int c = blockIdx.x * 256 + threadIdx.x;
    float x = in[(size_t)r * C + c];
    __nv_bfloat16 h = __float2bfloat16(x);
    out[(size_t)r * 2 * C + c]     = h;
    out[(size_t)r * 2 * C + C + c] = __float2bfloat16(x - __bfloat162float(h));
}
__global__ void conv_hl_T_gen(const float* __restrict__ in, int R, int C,
                              __nv_bfloat16* __restrict__ out, int outld,
                              int outcol0, int looff,
                              long long zIn, long long zOut) {
    in  += zIn  * blockIdx.z;
    out += zOut * blockIdx.z;
    __shared__ float t[32][33];
    int r0 = blockIdx.y * 32, c0 = blockIdx.x * 32;
    int tx = threadIdx.x, ty = threadIdx.y;
    for (int i = 0; i < 32; i += 8)
        t[ty + i][tx] = in[(size_t)(r0 + ty + i) * C + c0 + tx];
    __syncthreads();
    for (int i = 0; i < 32; i += 8) {
        float x = t[tx][ty + i];
        __nv_bfloat16 h = __float2bfloat16(x);
        out[(size_t)(c0 + ty + i) * outld + outcol0 + r0 + tx] = h;
        out[(size_t)(c0 + ty + i) * outld + looff + outcol0 + r0 + tx] =
            __float2bfloat16(x - __bfloat162float(h));
    }
}
// Transposed fp16 single conversion: in [R, C] fp32 -> out [C, R] fp16
__global__ void conv_h_T(const float* __restrict__ in, int R, int C,
                         __half* __restrict__ out, int outld) {
    __shared__ float t[32][33];
    int r0 = blockIdx.y * 32, c0 = blockIdx.x * 32;
    int tx = threadIdx.x, ty = threadIdx.y;
    for (int i = 0; i < 32; i += 8)
        t[ty + i][tx] = in[(size_t)(r0 + ty + i) * C + c0 + tx];
    __syncthreads();
    for (int i = 0; i < 32; i += 8)
        out[(size_t)(c0 + ty + i) * outld + r0 + tx] = __float2half(t[tx][ty + i]);
}

// ============================================================================
// Diag-block inversion, column-sliced: grid (NBLK, 8)
// ============================================================================
#define INV_SMEM ((128 * 129 + 128 * 17) * (int)sizeof(float))
__global__ void invert_diag_kernel() {
    extern __shared__ float sm[];
    float (*Gs)[129] = (float (*)[129])sm;
    float (*Zs)[17]  = (float (*)[17])(sm + 128 * 129);
    const int b0 = blockIdx.x * NB;
    const int c0 = blockIdx.y * 16;
    const int tid = threadIdx.x;

    for (int idx = tid; idx < 128 * 128; idx += 256) {
        int r = idx >> 7, c = idx & 127;
        Gs[r][c] = g_G[(size_t)(b0 + r) * D_DIM + b0 + c];
    }
    for (int idx = tid; idx < 128 * 16; idx += 256) {
        int r = idx >> 4, c = idx & 15;
        Zs[r][c] = (r == c0 + c) ? 1.f : 0.f;
    }
    __syncthreads();
    for (int j = 0; j < NB - 1; ++j) {
        const int rows = NB - 1 - j;
        for (int idx = tid; idx < rows * 16; idx += 256) {
            int r = j + 1 + (idx >> 4);
            int c = idx & 15;
            Zs[r][c] -= 2.f * Gs[r][j] * Zs[j][c];
        }
        __syncthreads();
    }
    float* outp = g_Tinv + (size_t)blockIdx.x * NB * NB;
    for (int idx = tid; idx < 128 * 16; idx += 256) {
        int r = idx >> 4, c = idx & 15;
        outp[(size_t)r * NB + c0 + c] = Zs[r][c];
    }
}

// ============================================================================
// Pair-combine: 7 Tinv2 blocks (256x256) fp32, coalesced.
// ============================================================================
#define CMB_SMEM (3 * 128 * 129 * (int)sizeof(float))
__global__ void __launch_bounds__(256, 1) combine_tinv() {
    extern __shared__ float sm[];
    float (*Abuf)[129] = (float (*)[129])sm;
    float (*Bbuf)[129] = (float (*)[129])(sm + 128 * 129);
    float (*Tm)[129]   = (float (*)[129])(sm + 2 * 128 * 129);
    const int p = blockIdx.x;
    const int tid = threadIdx.x;
    const int trow = (tid / 16) * 8;
    const int tcol = (tid % 16) * 8;
    const float* InvA = g_Tinv + (size_t)(2 * p)     * NB * NB;
    const float* InvB = g_Tinv + (size_t)(2 * p + 1) * NB * NB;
    const size_t g21 = (size_t)(p * 256 + 128) * D_DIM + p * 256;

    for (int idx = tid; idx < 128 * 128; idx += 256) {
        int r = idx >> 7, c = idx & 127;
        Abuf[r][c] = 2.f * g_G[g21 + (size_t)r * D_DIM + c];
        Bbuf[r][c] = InvA[idx];
    }
    __syncthreads();
    {
        float acc[8][8];
#pragma unroll
        for (int i = 0; i < 8; i++)
#pragma unroll
            for (int j = 0; j < 8; j++) acc[i][j] = 0.f;
        for (int k = 0; k < 128; ++k) {
            float a[8], b[8];
#pragma unroll
            for (int i = 0; i < 8; i++) a[i] = Abuf[trow + i][k];
#pragma unroll
            for (int j = 0; j < 8; j++) b[j] = Bbuf[k][tcol + j];
#pragma unroll
            for (int i = 0; i < 8; i++)
#pragma unroll
                for (int j = 0; j < 8; j++) acc[i][j] += a[i] * b[j];
        }
        __syncthreads();
#pragma unroll
        for (int i = 0; i < 8; i++)
#pragma unroll
            for (int j = 0; j < 8; j++) Tm[trow + i][tcol + j] = acc[i][j];
    }
    __syncthreads();
    for (int idx = tid; idx < 128 * 128; idx += 256) {
        int r = idx >> 7, c = idx & 127;
        Abuf[r][c] = InvB[idx];
    }
    __syncthreads();
    float* outp = g_Tinv2 + (size_t)p * NB2 * NB2;
    {
        float acc[8][8];
#pragma unroll
        for (int i = 0; i < 8; i++)
#pragma unroll
            for (int j = 0; j < 8; j++) acc[i][j] = 0.f;
        for (int k = 0; k < 128; ++k) {
            float a[8], b[8];
#pragma unroll
            for (int i = 0; i < 8; i++) a[i] = Abuf[trow + i][k];
#pragma unroll
            for (int j = 0; j < 8; j++) b[j] = Tm[k][tcol + j];
#pragma unroll
            for (int i = 0; i < 8; i++)
#pragma unroll
                for (int j = 0; j < 8; j++) acc[i][j] += a[i] * b[j];
        }
#pragma unroll
        for (int i = 0; i < 8; i++) {
#pragma unroll
            for (int j = 0; j < 8; j++) {
                int r = trow + i, c = tcol + j;
                outp[(size_t)r * NB2 + c]               = Bbuf[r][c];
                outp[(size_t)r * NB2 + 128 + c]         = 0.f;
                outp[(size_t)(128 + r) * NB2 + c]       = -acc[i][j];
                outp[(size_t)(128 + r) * NB2 + 128 + c] = Abuf[r][c];
            }
        }
    }
}

// ============================================================================
extern "C" void kernel_launch(void* const* d_in, const int* in_sizes, int n_in,
                              void* d_out, int out_size)
{
    const float* X;
    const float* U;
    if (in_sizes[0] == D_DIM * D_DIM && in_sizes[1] != D_DIM * D_DIM) {
        U = (const float*)d_in[0]; X = (const float*)d_in[1];
    } else {
        X = (const float*)d_in[0]; U = (const float*)d_in[1];
    }
    float* out = (float*)d_out;

    float *Vn, *G, *RHS, *Wt, *Tinv2;
    cudaGetSymbolAddress((void**)&Vn,    g_Vn);
    cudaGetSymbolAddress((void**)&G,     g_G);
    cudaGetSymbolAddress((void**)&RHS,   g_RHS);
    cudaGetSymbolAddress((void**)&Wt,    g_Wt);
    cudaGetSymbolAddress((void**)&Tinv2, g_Tinv2);
    __nv_bfloat16 *Vn_hl, *VnT_hl, *G_hl, *WtT_hl, *RHST_hl;
    __nv_bfloat16 *Tinv2_hl, *Tinv2T_hl, *S_hl;
    __half *P_h, *XT_h;
    cudaGetSymbolAddress((void**)&Vn_hl,     g_Vn_hl);
    cudaGetSymbolAddress((void**)&VnT_hl,    g_VnT_hl);
    cudaGetSymbolAddress((void**)&G_hl,      g_G_hl);
    cudaGetSymbolAddress((void**)&WtT_hl,    g_WtT_hl);
    cudaGetSymbolAddress((void**)&RHST_hl,   g_RHST_hl);
    cudaGetSymbolAddress((void**)&Tinv2_hl,  g_Tinv2_hl);
    cudaGetSymbolAddress((void**)&Tinv2T_hl, g_Tinv2T_hl);
    cudaGetSymbolAddress((void**)&S_hl,      g_S_hl);
    cudaGetSymbolAddress((void**)&P_h,       g_P_h);
    cudaGetSymbolAddress((void**)&XT_h,      g_XT_h);

    cudaFuncSetAttribute(invert_diag_kernel,
                         cudaFuncAttributeMaxDynamicSharedMemorySize, INV_SMEM);
    cudaFuncSetAttribute(combine_tinv,
                         cudaFuncAttributeMaxDynamicSharedMemorySize, CMB_SMEM);
    cudaFuncSetAttribute(mma_gemm<0,1,0,0,0,1,1,0>,
                         cudaFuncAttributeMaxDynamicSharedMemorySize, GEMM_SMEM);
    cudaFuncSetAttribute(mma_gemm<0,0,0,0,1,0,1,0>,
                         cudaFuncAttributeMaxDynamicSharedMemorySize, GEMM_SMEM);
    cudaFuncSetAttribute(mma_gemm<0,0,1,0,0,1,0,0>,
                         cudaFuncAttributeMaxDynamicSharedMemorySize, GEMM_SMEM);
    cudaFuncSetAttribute(mma_gemm<0,0,0,1,0,1,0,0>,
                         cudaFuncAttributeMaxDynamicSharedMemorySize, GEMM_SMEM);
    cudaFuncSetAttribute(mma_gemm<1,0,0,0,0,0,0,1>,
                         cudaFuncAttributeMaxDynamicSharedMemorySize, GEMM_SMEM);
    cudaFuncSetAttribute(mma_gemm_h,
                         cudaFuncAttributeMaxDynamicSharedMemorySize, GEMMH_SMEM);

    const dim3 t32x8(32, 8);
    const int D2 = 2 * D_DIM;   // 3584

    // 0) Vn (+hl fused), RHS = 2*Vn
    normalize_kernel<<<D_DIM, 256>>>(U);
    // 1) VnT_hl
    conv_hl_T_gen<<<dim3(D_DIM / 32, D_DIM / 32), t32x8>>>(
        Vn, D_DIM, D_DIM, VnT_hl, D2, 0, D_DIM, 0, 0);
    // 2) G = Vn @ Vn^T (lower tiles; fp32 + hl fused)
    mma_gemm<0,1,0,0,0,1,1,0><<<NBLK * (NBLK + 1) / 2, GEMM_THR, GEMM_SMEM>>>(
        Vn_hl, Vn_hl, G, G_hl, D_DIM, D2, D_DIM, D2, D_DIM, D_DIM, D2, 1.f,
        0, 0, 0, D_DIM, 0);
    // 3) invert 14 diag blocks — column-sliced
    invert_diag_kernel<<<dim3(NBLK, 8), 256, INV_SMEM>>>();
    // 4) combine into 7 Tinv2 blocks + hi/lo splits
    combine_tinv<<<NBLK2, 256, CMB_SMEM>>>();
    conv_hl<<<dim3(1, NBLK2 * NB2), 256>>>(Tinv2, Tinv2_hl, NB2);
    conv_hl_T_gen<<<dim3(NB2 / 32, NB2 / 32, NBLK2), t32x8>>>(
        Tinv2, NB2, NB2, Tinv2T_hl, 2 * NB2, 0, NB2,
        (long long)NB2 * NB2, (long long)NB2 * 2 * NB2);
    // 5) S_i = 2 * G[(i+1)*256:, blk i] @ Tinv2_i^T  (z-batched, hl out)
    mma_gemm<0,0,0,0,1,0,1,0><<<dim3(NB2 / 128, MREM0 / 128, NBLK2 - 1), GEMM_THR, GEMM_SMEM>>>(
        G_hl + (size_t)NB2 * D2, Tinv2T_hl, nullptr, S_hl,
        NB2, D2, D_DIM, 2 * NB2, NB2, 0, 2 * NB2, 2.f,
        (long long)NB2 * D2 + NB2,
        (long long)NB2 * 2 * NB2,
        (long long)MREM0 * 2 * NB2,
        MREM0, NB2);

    // 6..) chain
    for (int i = 0; i < NBLK2; ++i) {
        conv_hl_T_gen<<<dim3(D_DIM / 32, NB2 / 32), t32x8>>>(
            RHS + (size_t)i * NB2 * D_DIM, NB2, D_DIM,
            RHST_hl, D2, i * NB2, D_DIM, 0, 0);
        int mrem = D_DIM - (i + 1) * NB2;
        if (mrem > 0) {
            mma_gemm<0,0,1,0,0,1,0,0><<<dim3(D_DIM / 128, mrem / 128), GEMM_THR, GEMM_SMEM>>>(
                S_hl + (size_t)i * MREM0 * 2 * NB2,
                RHST_hl + (size_t)i * NB2,
                RHS + (size_t)(i + 1) * NB2 * D_DIM, nullptr,
                NB2, 2 * NB2, NB2, D2, D_DIM, D_DIM, 0, -1.f,
                0, 0, 0, mrem, 0);
        }
    }

    // Wt = blockdiag(Tinv2) @ RHS
    mma_gemm<0,0,0,1,0,1,0,0><<<dim3(D_DIM / 128, D_DIM / 128), GEMM_THR, GEMM_SMEM>>>(
        Tinv2_hl, RHST_hl, Wt, nullptr,
        NB2, 2 * NB2, NB2, D2, D_DIM, D_DIM, 0, 1.f, 0, 0, 0, D_DIM, 0);
    conv_hl_T_gen<<<dim3(D_DIM / 32, D_DIM / 32), t32x8>>>(
        Wt, D_DIM, D_DIM, WtT_hl, D2, 0, D_DIM, 0, 0);

    // P = I - Wt^T @ Vn  (fp16 single out)
    mma_gemm<1,0,0,0,0,0,0,1><<<dim3(D_DIM / 128, D_DIM / 128), GEMM_THR, GEMM_SMEM>>>(
        WtT_hl, VnT_hl, nullptr, P_h,
        D_DIM, D2, D_DIM, D2, D_DIM, 0, D_DIM, -1.f, 0, 0, 0, D_DIM, 0);

    // X^T fp16 single conversion
    conv_h_T<<<dim3(B_DIM / 32, D_DIM / 32), t32x8>>>(X, D_DIM, B_DIM, XT_h, D_DIM);

    // out = P @ X  (fp16 single-product tensor GEMM)
    mma_gemm_h<<<dim3(B_DIM / 128, D_DIM / 128), GEMM_THR, GEMMH_SMEM>>>(
        P_h, XT_h, out, D_DIM, D_DIM, D_DIM, B_DIM);

    (void)n_in; (void)out_size;
}

// round 12
// speedup vs baseline: 1.7333x; 1.0548x over previous
#include <cuda_runtime.h>
#include <cuda_bf16.h>
#include <cuda_fp16.h>
#include <cstdint>

#define D_DIM 1792
#define B_DIM 8192
#define NB 128
#define NBLK (D_DIM / NB)     // 14
#define NB2 256
#define NBLK2 (D_DIM / NB2)   // 7
#define MREM0 1536

// ---------------- fp32 scratch ----------------
__device__ __align__(16) float g_Vn   [ (size_t)D_DIM * D_DIM ];
__device__ __align__(16) float g_G    [ (size_t)D_DIM * D_DIM ];
__device__ __align__(16) float g_Tinv [ (size_t)NBLK * NB * NB ];
__device__ __align__(16) float g_Tinv2[ (size_t)NBLK2 * NB2 * NB2 ];

// ---------------- bf16 hi|lo scratch ----------------
__device__ __align__(16) __nv_bfloat16 g_Vn_hl    [ (size_t)D_DIM * 2 * D_DIM ];
__device__ __align__(16) __nv_bfloat16 g_VnT_hl   [ (size_t)D_DIM * 2 * D_DIM ];
__device__ __align__(16) __nv_bfloat16 g_G_hl     [ (size_t)D_DIM * 2 * D_DIM ];
__device__ __align__(16) __nv_bfloat16 g_WtT_hl   [ (size_t)D_DIM * 2 * D_DIM ];
__device__ __align__(16) __nv_bfloat16 g_RHST_hl  [ (size_t)D_DIM * 2 * D_DIM ];
__device__ __align__(16) __nv_bfloat16 g_Tinv2_hl [ (size_t)NBLK2 * NB2 * 2 * NB2 ];
__device__ __align__(16) __nv_bfloat16 g_Tinv2T_hl[ (size_t)NBLK2 * NB2 * 2 * NB2 ];
__device__ __align__(16) __nv_bfloat16 g_S_hl     [ (size_t)(NBLK2 - 1) * MREM0 * 2 * NB2 ];

// ---------------- fp16 operands for PX ----------------
__device__ __align__(16) __half g_P_h [ (size_t)D_DIM * D_DIM ];
__device__ __align__(16) __half g_XT_h[ (size_t)B_DIM * D_DIM ];

// ============================================================================
// helpers
// ============================================================================
__device__ __forceinline__ uint32_t smem_u32(const void* p) {
    uint32_t a;
    asm("{ .reg .u64 t; cvta.to.shared.u64 t, %1; cvt.u32.u64 %0, t; }"
        : "=r"(a) : "l"(p));
    return a;
}
__device__ __forceinline__ void cpa16(uint32_t s, const void* g) {
    asm volatile("cp.async.cg.shared.global [%0], [%1], 16;" :: "r"(s), "l"(g));
}
#define CPA_COMMIT() asm volatile("cp.async.commit_group;" ::: "memory")
#define CPA_WAIT(n)  asm volatile("cp.async.wait_group %0;" :: "n"(n) : "memory")

#define LDSM4(r0, r1, r2, r3, addr) \
    asm volatile("ldmatrix.sync.aligned.m8n8.x4.shared.b16 {%0,%1,%2,%3}, [%4];" \
        : "=r"(r0), "=r"(r1), "=r"(r2), "=r"(r3) : "r"(addr))

#define MMA16816(d, a, b0, b1) \
    asm volatile("mma.sync.aligned.m16n8k16.row.col.f32.bf16.bf16.f32 " \
        "{%0,%1,%2,%3}, {%4,%5,%6,%7}, {%8,%9}, {%0,%1,%2,%3};" \
        : "+f"((d)[0]), "+f"((d)[1]), "+f"((d)[2]), "+f"((d)[3]) \
        : "r"((a)[0]), "r"((a)[1]), "r"((a)[2]), "r"((a)[3]), "r"(b0), "r"(b1))

#define MMA16816H(d, a, b0, b1) \
    asm volatile("mma.sync.aligned.m16n8k16.row.col.f32.f16.f16.f32 " \
        "{%0,%1,%2,%3}, {%4,%5,%6,%7}, {%8,%9}, {%0,%1,%2,%3};" \
        : "+f"((d)[0]), "+f"((d)[1]), "+f"((d)[2]), "+f"((d)[3]) \
        : "r"((a)[0]), "r"((a)[1]), "r"((a)[2]), "r"((a)[3]), "r"(b0), "r"(b1))

// ============================================================================
// Generalized bf16-split tensor GEMM (3 products hh+lh+hl):
//   V = alpha * A @ B^T  [+ rbeta*(hi+lo of Cin) if BETAHL]  [+ I if ADDI]
//   FPOUT: fp32 out to C.  HLOUT: bf16 hi/lo out to Chl.  F16OUT: fp16 to Chl.
// ============================================================================
#define TILE_B   8192
#define STAGE_B  (4 * TILE_B)
#define GEMM_SMEM (3 * STAGE_B)
#define GEMM_THR 128

template <int ADDI, int TRI, int BETAHL, int ZB, int FPOUT, int HLOUT, int F16OUT>
__global__ void __launch_bounds__(GEMM_THR, 2)
mma_gemm(const __nv_bfloat16* __restrict__ A, const __nv_bfloat16* __restrict__ B,
         float* __restrict__ C, void* __restrict__ Chl,
         const __nv_bfloat16* __restrict__ Cin,
         int K, int lda2, int loA, int ldb2, int loB,
         int ldc, int ldchl, float alpha, float rbeta,
         long long zAs, long long zBs, long long zCHs, int M0, int dM)
{
    extern __shared__ __align__(128) char smem[];
    const uint32_t s0 = smem_u32(smem);
    const int tid  = threadIdx.x;
    const int lane = tid & 31;
    const int wid  = tid >> 5;
    const int wm   = wid >> 1;
    const int wn   = wid & 1;

    if (ZB) {
        const int z = blockIdx.z;
        A += zAs * z; B += zBs * z;
        if (HLOUT) Chl = (void*)((__nv_bfloat16*)Chl + zCHs * z);
        if ((int)(blockIdx.y * 128) >= M0 - dM * z) return;
    }

    int row0, col0;
    if (TRI) {
        int bid = blockIdx.x;
        int r = 0;
        while ((r + 1) * (r + 2) / 2 <= bid) ++r;
        row0 = r * 128;
        col0 = (bid - r * (r + 1) / 2) * 128;
    } else {
        row0 = blockIdx.y * 128;
        col0 = blockIdx.x * 128;
    }

    const int T = K / 32;

    float acc[4][8][4];
#pragma unroll
    for (int i = 0; i < 4; i++)
#pragma unroll
        for (int j = 0; j < 8; j++)
#pragma unroll
            for (int q = 0; q < 4; q++) acc[i][j][q] = 0.f;

    auto load_stage = [&](int s) {
        const int k0 = s * 32;
        const uint32_t base = s0 + (s % 3) * STAGE_B;
#pragma unroll
        for (int qq = 0; qq < 4; ++qq) {
            const int jj = tid + qq * GEMM_THR;
            const int r  = jj >> 2;
            const int cc = jj & 3;
            const uint32_t soff = r * 64 + ((cc ^ ((r >> 1) & 3)) << 4);
            const __nv_bfloat16* ag = A + (size_t)(row0 + r) * lda2 + k0 + cc * 8;
            const __nv_bfloat16* bg = B + (size_t)(col0 + r) * ldb2 + k0 + cc * 8;
            cpa16(base + 0 * TILE_B + soff, ag);
            cpa16(base + 1 * TILE_B + soff, ag + loA);
            cpa16(base + 2 * TILE_B + soff, bg);
            cpa16(base + 3 * TILE_B + soff, bg + loB);
        }
        CPA_COMMIT();
    };

    load_stage(0); load_stage(1);

    for (int s = 0; s < T; ++s) {
        CPA_WAIT(1);
        __syncthreads();
        if (s + 2 < T) load_stage(s + 2);

        const uint32_t buf = s0 + (s % 3) * STAGE_B;
#pragma unroll
        for (int kk = 0; kk < 2; ++kk) {
            uint32_t ah[4][4], al[4][4], bb[8][2];
#pragma unroll
            for (int mi = 0; mi < 4; ++mi) {
                const int row = wm * 64 + mi * 16 + ((lane >> 3) & 1) * 8 + (lane & 7);
                const int cc  = kk * 2 + (lane >> 4);
                const uint32_t off = row * 64 + ((cc ^ ((row >> 1) & 3)) << 4);
                LDSM4(ah[mi][0], ah[mi][1], ah[mi][2], ah[mi][3], buf + 0 * TILE_B + off);
                LDSM4(al[mi][0], al[mi][1], al[mi][2], al[mi][3], buf + 1 * TILE_B + off);
            }
#pragma unroll
            for (int p = 0; p < 4; ++p) {
                const int row = wn * 64 + p * 16 + (lane >> 4) * 8 + (lane & 7);
                const int cc  = kk * 2 + ((lane >> 3) & 1);
                const uint32_t off = row * 64 + ((cc ^ ((row >> 1) & 3)) << 4);
                LDSM4(bb[p * 2][0], bb[p * 2][1], bb[p * 2 + 1][0], bb[p * 2 + 1][1],
                      buf + 2 * TILE_B + off);
            }
#pragma unroll
            for (int mi = 0; mi < 4; ++mi)
#pragma unroll
                for (int nj = 0; nj < 8; ++nj) {
                    MMA16816(acc[mi][nj], ah[mi], bb[nj][0], bb[nj][1]);  // hh
                    MMA16816(acc[mi][nj], al[mi], bb[nj][0], bb[nj][1]);  // lh
                }
#pragma unroll
            for (int p = 0; p < 4; ++p) {
                const int row = wn * 64 + p * 16 + (lane >> 4) * 8 + (lane & 7);
                const int cc  = kk * 2 + ((lane >> 3) & 1);
                const uint32_t off = row * 64 + ((cc ^ ((row >> 1) & 3)) << 4);
                LDSM4(bb[p * 2][0], bb[p * 2][1], bb[p * 2 + 1][0], bb[p * 2 + 1][1],
                      buf + 3 * TILE_B + off);
            }
#pragma unroll
            for (int mi = 0; mi < 4; ++mi)
#pragma unroll
                for (int nj = 0; nj < 8; ++nj)
                    MMA16816(acc[mi][nj], ah[mi], bb[nj][0], bb[nj][1]);  // hl
        }
    }

    const int g = lane >> 2, t = lane & 3;
    const int half = ldchl >> 1;
#pragma unroll
    for (int mi = 0; mi < 4; ++mi) {
#pragma unroll
        for (int nj = 0; nj < 8; ++nj) {
            const int r_ = row0 + wm * 64 + mi * 16 + g;
            const int c_ = col0 + wn * 64 + nj * 8 + 2 * t;
            float2 v, v2;
            v.x  = alpha * acc[mi][nj][0];
            v.y  = alpha * acc[mi][nj][1];
            v2.x = alpha * acc[mi][nj][2];
            v2.y = alpha * acc[mi][nj][3];
            if (BETAHL) {
                // read hi/lo pairs from Cin (same ldchl layout), add rbeta*(hi+lo)
                __nv_bfloat162 ih  = *reinterpret_cast<const __nv_bfloat162*>(
                    &Cin[(size_t)r_ * ldchl + c_]);
                __nv_bfloat162 il  = *reinterpret_cast<const __nv_bfloat162*>(
                    &Cin[(size_t)r_ * ldchl + half + c_]);
                __nv_bfloat162 ih2 = *reinterpret_cast<const __nv_bfloat162*>(
                    &Cin[(size_t)(r_ + 8) * ldchl + c_]);
                __nv_bfloat162 il2 = *reinterpret_cast<const __nv_bfloat162*>(
                    &Cin[(size_t)(r_ + 8) * ldchl + half + c_]);
                v.x  += rbeta * (__bfloat162float(ih.x)  + __bfloat162float(il.x));
                v.y  += rbeta * (__bfloat162float(ih.y)  + __bfloat162float(il.y));
                v2.x += rbeta * (__bfloat162float(ih2.x) + __bfloat162float(il2.x));
                v2.y += rbeta * (__bfloat162float(ih2.y) + __bfloat162float(il2.y));
            }
            if (ADDI) {
                if (r_ == c_)     v.x  += 1.f;
                if (r_ == c_ + 1) v.y  += 1.f;
                if (r_ + 8 == c_)     v2.x += 1.f;
                if (r_ + 8 == c_ + 1) v2.y += 1.f;
            }
            if (FPOUT) {
                *reinterpret_cast<float2*>(&C[(size_t)r_ * ldc + c_])       = v;
                *reinterpret_cast<float2*>(&C[(size_t)(r_ + 8) * ldc + c_]) = v2;
            }
            if (HLOUT) {
                __nv_bfloat16* Cb = (__nv_bfloat16*)Chl;
                __nv_bfloat162 h, h2, l, l2;
                h.x  = __float2bfloat16(v.x);   h.y  = __float2bfloat16(v.y);
                h2.x = __float2bfloat16(v2.x);  h2.y = __float2bfloat16(v2.y);
                l.x  = __float2bfloat16(v.x  - __bfloat162float(h.x));
                l.y  = __float2bfloat16(v.y  - __bfloat162float(h.y));
                l2.x = __float2bfloat16(v2.x - __bfloat162float(h2.x));
                l2.y = __float2bfloat16(v2.y - __bfloat162float(h2.y));
                *reinterpret_cast<__nv_bfloat162*>(&Cb[(size_t)r_ * ldchl + c_])              = h;
                *reinterpret_cast<__nv_bfloat162*>(&Cb[(size_t)r_ * ldchl + half + c_])       = l;
                *reinterpret_cast<__nv_bfloat162*>(&Cb[(size_t)(r_ + 8) * ldchl + c_])        = h2;
                *reinterpret_cast<__nv_bfloat162*>(&Cb[(size_t)(r_ + 8) * ldchl + half + c_]) = l2;
            }
            if (F16OUT) {
                __half* Ch = (__half*)Chl;
                *reinterpret_cast<__half2*>(&Ch[(size_t)r_ * ldchl + c_]) =
                    __floats2half2_rn(v.x, v.y);
                *reinterpret_cast<__half2*>(&Ch[(size_t)(r_ + 8) * ldchl + c_]) =
                    __floats2half2_rn(v2.x, v2.y);
            }
        }
    }
}

// ============================================================================
// fp16 single-product GEMM (out = P @ X): K=64 per stage, 128B-row swizzle.
// ============================================================================
#define TILE_H   16384                  // 128 rows x 64 fp16 = 128 B/row
#define STAGE_H  (2 * TILE_H)
#define GEMMH_SMEM (3 * STAGE_H)        // 98304

__global__ void __launch_bounds__(GEMM_THR, 2)
mma_gemm_h(const __half* __restrict__ A, const __half* __restrict__ B,
           float* __restrict__ C, int K, int lda, int ldb, int ldc)
{
    extern __shared__ __align__(128) char smem[];
    const uint32_t s0 = smem_u32(smem);
    const int tid  = threadIdx.x;
    const int lane = tid & 31;
    const int wid  = tid >> 5;
    const int wm   = wid >> 1;
    const int wn   = wid & 1;
    const int row0 = blockIdx.y * 128;
    const int col0 = blockIdx.x * 128;
    const int T = K / 64;

    float acc[4][8][4];
#pragma unroll
    for (int i = 0; i < 4; i++)
#pragma unroll
        for (int j = 0; j < 8; j++)
#pragma unroll
            for (int q = 0; q < 4; q++) acc[i][j][q] = 0.f;

    auto load_stage = [&](int s) {
        const int k0 = s * 64;
        const uint32_t base = s0 + (s % 3) * STAGE_H;
#pragma unroll
        for (int qq = 0; qq < 8; ++qq) {
            const int jj = tid + qq * GEMM_THR;     // 0..1023
            const int r  = jj >> 3;
            const int cc = jj & 7;
            const uint32_t soff = r * 128 + ((cc ^ (r & 7)) << 4);
            cpa16(base + soff,          A + (size_t)(row0 + r) * lda + k0 + cc * 8);
            cpa16(base + TILE_H + soff, B + (size_t)(col0 + r) * ldb + k0 + cc * 8);
        }
        CPA_COMMIT();
    };

    load_stage(0); load_stage(1);

    for (int s = 0; s < T; ++s) {
        CPA_WAIT(1);
        __syncthreads();
        if (s + 2 < T) load_stage(s + 2);

        const uint32_t buf = s0 + (s % 3) * STAGE_H;
#pragma unroll
        for (int kk = 0; kk < 4; ++kk) {
            uint32_t ah[4][4], bb[8][2];
#pragma unroll
            for (int mi = 0; mi < 4; ++mi) {
                const int row = wm * 64 + mi * 16 + ((lane >> 3) & 1) * 8 + (lane & 7);
                const int cc  = kk * 2 + (lane >> 4);
                const uint32_t off = row * 128 + ((cc ^ (row & 7)) << 4);
                LDSM4(ah[mi][0], ah[mi][1], ah[mi][2], ah[mi][3], buf + off);
            }
#pragma unroll
            for (int p = 0; p < 4; ++p) {
                const int row = wn * 64 + p * 16 + (lane >> 4) * 8 + (lane & 7);
                const int cc  = kk * 2 + ((lane >> 3) & 1);
                const uint32_t off = row * 128 + ((cc ^ (row & 7)) << 4);
                LDSM4(bb[p * 2][0], bb[p * 2][1], bb[p * 2 + 1][0], bb[p * 2 + 1][1],
                      buf + TILE_H + off);
            }
#pragma unroll
            for (int mi = 0; mi < 4; ++mi)
#pragma unroll
                for (int nj = 0; nj < 8; ++nj)
                    MMA16816H(acc[mi][nj], ah[mi], bb[nj][0], bb[nj][1]);
        }
    }

    const int g = lane >> 2, t = lane & 3;
#pragma unroll
    for (int mi = 0; mi < 4; ++mi) {
#pragma unroll
        for (int nj = 0; nj < 8; ++nj) {
            const int r_ = row0 + wm * 64 + mi * 16 + g;
            const int c_ = col0 + wn * 64 + nj * 8 + 2 * t;
            *reinterpret_cast<float2*>(&C[(size_t)r_ * ldc + c_]) =
                make_float2(acc[mi][nj][0], acc[mi][nj][1]);
            *reinterpret_cast<float2*>(&C[(size_t)(r_ + 8) * ldc + c_]) =
                make_float2(acc[mi][nj][2], acc[mi][nj][3]);
        }
    }
}

// ============================================================================
// Row-normalize U -> Vn (fp32) + Vn_hl
// ============================================================================
__global__ void normalize_kernel(const float* __restrict__ U) {
    int row = blockIdx.x;
    const float* u = U + (size_t)row * D_DIM;
    __shared__ float red[256];
    float s = 0.f;
    for (int c = threadIdx.x; c < D_DIM; c += 256) { float v = u[c]; s += v * v; }
    red[threadIdx.x] = s;
    __syncthreads();
    for (int off = 128; off > 0; off >>= 1) {
        if (threadIdx.x < off) red[threadIdx.x] += red[threadIdx.x + off];
        __syncthreads();
    }
    float inv = rsqrtf(red[0]);
    for (int c = threadIdx.x; c < D_DIM; c += 256) {
        float v = u[c] * inv;
        g_Vn[(size_t)row * D_DIM + c] = v;
        __nv_bfloat16 h = __float2bfloat16(v);
        g_Vn_hl[(size_t)row * 2 * D_DIM + c]         = h;
        g_Vn_hl[(size_t)row * 2 * D_DIM + D_DIM + c] =
            __float2bfloat16(v - __bfloat162float(h));
    }
}

// ============================================================================
// conversions
// ============================================================================
__global__ void conv_hl(const float* __restrict__ in, __nv_bfloat16* __restrict__ out, int C) {
    int r = blockIdx.y;
    int c = blockIdx.x * 256 + threadIdx.x;
    float x = in[(size_t)r * C + c];
    __nv_bfloat16 h = __float2bfloat16(x);
    out[(size_t)r * 2 * C + c]     = h;
    out[(size_t)r * 2 * C + C + c] = __float2bfloat16(x - __bfloat162float(h));
}
__global__ void conv_hl_T_gen(const float* __restrict__ in, int R, int C,
                              __nv_bfloat16* __restrict__ out, int outld,
                              int outcol0, int looff,
                              long long zIn, long long zOut) {
    in  += zIn  * blockIdx.z;
    out += zOut * blockIdx.z;
    __shared__ float t[32][33];
    int r0 = blockIdx.y * 32, c0 = blockIdx.x * 32;
    int tx = threadIdx.x, ty = threadIdx.y;
    for (int i = 0; i < 32; i += 8)
        t[ty + i][tx] = in[(size_t)(r0 + ty + i) * C + c0 + tx];
    __syncthreads();
    for (int i = 0; i < 32; i += 8) {
        float x = t[tx][ty + i];
        __nv_bfloat16 h = __float2bfloat16(x);
        out[(size_t)(c0 + ty + i) * outld + outcol0 + r0 + tx] = h;
        out[(size_t)(c0 + ty + i) * outld + looff + outcol0 + r0 + tx] =
            __float2bfloat16(x - __bfloat162float(h));
    }
}
__global__ void conv_h_T(const float* __restrict__ in, int R, int C,
                         __half* __restrict__ out, int outld) {
    __shared__ float t[32][33];
    int r0 = blockIdx.y * 32, c0 = blockIdx.x * 32;
    int tx = threadIdx.x, ty = threadIdx.y;
    for (int i = 0; i < 32; i += 8)
        t[ty + i][tx] = in[(size_t)(r0 + ty + i) * C + c0 + tx];
    __syncthreads();
    for (int i = 0; i < 32; i += 8)
        out[(size_t)(c0 + ty + i) * outld + r0 + tx] = __float2half(t[tx][ty + i]);
}
// Seed RHST_hl block 0 = 2 * VnT_hl block 0 (exact, power of 2)
__global__ void seed_rhst0() {
    int r = blockIdx.x;
    int c = threadIdx.x;          // 0..255 -> two entries (hi, lo)
    size_t base = (size_t)r * 2 * D_DIM;
    g_RHST_hl[base + c] =
        __float2bfloat16(2.f * __bfloat162float(g_VnT_hl[base + c]));
    g_RHST_hl[base + D_DIM + c] =
        __float2bfloat16(2.f * __bfloat162float(g_VnT_hl[base + D_DIM + c]));
}

// ============================================================================
// Diag-block inversion, column-sliced: grid (NBLK, 8)
// ============================================================================
#define INV_SMEM ((128 * 129 + 128 * 17) * (int)sizeof(float))
__global__ void invert_diag_kernel() {
    extern __shared__ float sm[];
    float (*Gs)[129] = (float (*)[129])sm;
    float (*Zs)[17]  = (float (*)[17])(sm + 128 * 129);
    const int b0 = blockIdx.x * NB;
    const int c0 = blockIdx.y * 16;
    const int tid = threadIdx.x;

    for (int idx = tid; idx < 128 * 128; idx += 256) {
        int r = idx >> 7, c = idx & 127;
        Gs[r][c] = g_G[(size_t)(b0 + r) * D_DIM + b0 + c];
    }
    for (int idx = tid; idx < 128 * 16; idx += 256) {
        int r = idx >> 4, c = idx & 15;
        Zs[r][c] = (r == c0 + c) ? 1.f : 0.f;
    }
    __syncthreads();
    for (int j = 0; j < NB - 1; ++j) {
        const int rows = NB - 1 - j;
        for (int idx = tid; idx < rows * 16; idx += 256) {
            int r = j + 1 + (idx >> 4);
            int c = idx & 15;
            Zs[r][c] -= 2.f * Gs[r][j] * Zs[j][c];
        }
        __syncthreads();
    }
    float* outp = g_Tinv + (size_t)blockIdx.x * NB * NB;
    for (int idx = tid; idx < 128 * 16; idx += 256) {
        int r = idx >> 4, c = idx & 15;
        outp[(size_t)r * NB + c0 + c] = Zs[r][c];
    }
}

// ============================================================================
// Pair-combine: 7 Tinv2 blocks (256x256) fp32, coalesced.
// ============================================================================
#define CMB_SMEM (3 * 128 * 129 * (int)sizeof(float))
__global__ void __launch_bounds__(256, 1) combine_tinv() {
    extern __shared__ float sm[];
    float (*Abuf)[129] = (float (*)[129])sm;
    float (*Bbuf)[129] = (float (*)[129])(sm + 128 * 129);
    float (*Tm)[129]   = (float (*)[129])(sm + 2 * 128 * 129);
    const int p = blockIdx.x;
    const int tid = threadIdx.x;
    const int trow = (tid / 16) * 8;
    const int tcol = (tid % 16) * 8;
    const float* InvA = g_Tinv + (size_t)(2 * p)     * NB * NB;
    const float* InvB = g_Tinv + (size_t)(2 * p + 1) * NB * NB;
    const size_t g21 = (size_t)(p * 256 + 128) * D_DIM + p * 256;

    for (int idx = tid; idx < 128 * 128; idx += 256) {
        int r = idx >> 7, c = idx & 127;
        Abuf[r][c] = 2.f * g_G[g21 + (size_t)r * D_DIM + c];
        Bbuf[r][c] = InvA[idx];
    }
    __syncthreads();
    {
        float acc[8][8];
#pragma unroll
        for (int i = 0; i < 8; i++)
#pragma unroll
            for (int j = 0; j < 8; j++) acc[i][j] = 0.f;
        for (int k = 0; k < 128; ++k) {
            float a[8], b[8];
#pragma unroll
            for (int i = 0; i < 8; i++) a[i] = Abuf[trow + i][k];
#pragma unroll
            for (int j = 0; j < 8; j++) b[j] = Bbuf[k][tcol + j];
#pragma unroll
            for (int i = 0; i < 8; i++)
#pragma unroll
                for (int j = 0; j < 8; j++) acc[i][j] += a[i] * b[j];
        }
        __syncthreads();
#pragma unroll
        for (int i = 0; i < 8; i++)
#pragma unroll
            for (int j = 0; j < 8; j++) Tm[trow + i][tcol + j] = acc[i][j];
    }
    __syncthreads();
    for (int idx = tid; idx < 128 * 128; idx += 256) {
        int r = idx >> 7, c = idx & 127;
        Abuf[r][c] = InvB[idx];
    }
    __syncthreads();
    float* outp = g_Tinv2 + (size_t)p * NB2 * NB2;
    {
        float acc[8][8];
#pragma unroll
        for (int i = 0; i < 8; i++)
#pragma unroll
            for (int j = 0; j < 8; j++) acc[i][j] = 0.f;
        for (int k = 0; k < 128; ++k) {
            float a[8], b[8];
#pragma unroll
            for (int i = 0; i < 8; i++) a[i] = Abuf[trow + i][k];
#pragma unroll
            for (int j = 0; j < 8; j++) b[j] = Tm[k][tcol + j];
#pragma unroll
            for (int i = 0; i < 8; i++)
#pragma unroll
                for (int j = 0; j < 8; j++) acc[i][j] += a[i] * b[j];
        }
#pragma unroll
        for (int i = 0; i < 8; i++) {
#pragma unroll
            for (int j = 0; j < 8; j++) {
                int r = trow + i, c = tcol + j;
                outp[(size_t)r * NB2 + c]               = Bbuf[r][c];
                outp[(size_t)r * NB2 + 128 + c]         = 0.f;
                outp[(size_t)(128 + r) * NB2 + c]       = -acc[i][j];
                outp[(size_t)(128 + r) * NB2 + 128 + c] = Abuf[r][c];
            }
        }
    }
}

// ============================================================================
extern "C" void kernel_launch(void* const* d_in, const int* in_sizes, int n_in,
                              void* d_out, int out_size)
{
    const float* X;
    const float* U;
    if (in_sizes[0] == D_DIM * D_DIM && in_sizes[1] != D_DIM * D_DIM) {
        U = (const float*)d_in[0]; X = (const float*)d_in[1];
    } else {
        X = (const float*)d_in[0]; U = (const float*)d_in[1];
    }
    float* out = (float*)d_out;

    float *Vn, *G, *Tinv2;
    cudaGetSymbolAddress((void**)&Vn,    g_Vn);
    cudaGetSymbolAddress((void**)&G,     g_G);
    cudaGetSymbolAddress((void**)&Tinv2, g_Tinv2);
    __nv_bfloat16 *Vn_hl, *VnT_hl, *G_hl, *WtT_hl, *RHST_hl;
    __nv_bfloat16 *Tinv2_hl, *Tinv2T_hl, *S_hl;
    __half *P_h, *XT_h;
    cudaGetSymbolAddress((void**)&Vn_hl,     g_Vn_hl);
    cudaGetSymbolAddress((void**)&VnT_hl,    g_VnT_hl);
    cudaGetSymbolAddress((void**)&G_hl,      g_G_hl);
    cudaGetSymbolAddress((void**)&WtT_hl,    g_WtT_hl);
    cudaGetSymbolAddress((void**)&RHST_hl,   g_RHST_hl);
    cudaGetSymbolAddress((void**)&Tinv2_hl,  g_Tinv2_hl);
    cudaGetSymbolAddress((void**)&Tinv2T_hl, g_Tinv2T_hl);
    cudaGetSymbolAddress((void**)&S_hl,      g_S_hl);
    cudaGetSymbolAddress((void**)&P_h,       g_P_h);
    cudaGetSymbolAddress((void**)&XT_h,      g_XT_h);

    cudaFuncSetAttribute(invert_diag_kernel,
                         cudaFuncAttributeMaxDynamicSharedMemorySize, INV_SMEM);
    cudaFuncSetAttribute(combine_tinv,
                         cudaFuncAttributeMaxDynamicSharedMemorySize, CMB_SMEM);
    cudaFuncSetAttribute(mma_gemm<0,1,0,0,1,1,0>,
                         cudaFuncAttributeMaxDynamicSharedMemorySize, GEMM_SMEM);
    cudaFuncSetAttribute(mma_gemm<0,0,0,1,0,1,0>,
                         cudaFuncAttributeMaxDynamicSharedMemorySize, GEMM_SMEM);
    cudaFuncSetAttribute(mma_gemm<0,0,1,0,0,1,0>,
                         cudaFuncAttributeMaxDynamicSharedMemorySize, GEMM_SMEM);
    cudaFuncSetAttribute(mma_gemm<1,0,0,0,0,0,1>,
                         cudaFuncAttributeMaxDynamicSharedMemorySize, GEMM_SMEM);
    cudaFuncSetAttribute(mma_gemm_h,
                         cudaFuncAttributeMaxDynamicSharedMemorySize, GEMMH_SMEM);

    const dim3 t32x8(32, 8);
    const int D2 = 2 * D_DIM;   // 3584

    // 0) Vn (+hl fused)
    normalize_kernel<<<D_DIM, 256>>>(U);
    // 1) VnT_hl
    conv_hl_T_gen<<<dim3(D_DIM / 32, D_DIM / 32), t32x8>>>(
        Vn, D_DIM, D_DIM, VnT_hl, D2, 0, D_DIM, 0, 0);
    // 2) G = Vn @ Vn^T (lower tiles; fp32 + hl fused)
    mma_gemm<0,1,0,0,1,1,0><<<NBLK * (NBLK + 1) / 2, GEMM_THR, GEMM_SMEM>>>(
        Vn_hl, Vn_hl, G, G_hl, nullptr,
        D_DIM, D2, D_DIM, D2, D_DIM, D_DIM, D2, 1.f, 0.f, 0, 0, 0, D_DIM, 0);
    // 3) invert 14 diag blocks (column-sliced)
    invert_diag_kernel<<<dim3(NBLK, 8), 256, INV_SMEM>>>();
    // 4) combine into 7 Tinv2 blocks + hi/lo splits
    combine_tinv<<<NBLK2, 256, CMB_SMEM>>>();
    conv_hl<<<dim3(1, NBLK2 * NB2), 256>>>(Tinv2, Tinv2_hl, NB2);
    conv_hl_T_gen<<<dim3(NB2 / 32, NB2 / 32, NBLK2), t32x8>>>(
        Tinv2, NB2, NB2, Tinv2T_hl, 2 * NB2, 0, NB2,
        (long long)NB2 * NB2, (long long)NB2 * 2 * NB2);
    // 5) S_i = 2 * G[(i+1)*256:, blk i] @ Tinv2_i^T  (z-batched, hl out)
    mma_gemm<0,0,0,1,0,1,0><<<dim3(NB2 / 128, MREM0 / 128, NBLK2 - 1), GEMM_THR, GEMM_SMEM>>>(
        G_hl + (size_t)NB2 * D2, Tinv2T_hl, nullptr, S_hl, nullptr,
        NB2, D2, D_DIM, 2 * NB2, NB2, 0, 2 * NB2, 2.f, 0.f,
        (long long)NB2 * D2 + NB2,
        (long long)NB2 * 2 * NB2,
        (long long)MREM0 * 2 * NB2,
        MREM0, NB2);
    // 5b) seed RHST_hl block 0 = 2 * VnT_hl block 0
    seed_rhst0<<<D_DIM, 256>>>();

    // 6) transposed chain: RHST[:, >bl_i] = rbeta*(Cin) - RHST[:, bl_i] @ S_i^T
    for (int i = 0; i < NBLK2 - 1; ++i) {
        int mrem = D_DIM - (i + 1) * NB2;
        const __nv_bfloat16* Cin = (i == 0) ? (VnT_hl + NB2) : (RHST_hl + (i + 1) * NB2);
        float rbeta = (i == 0) ? 2.f : 1.f;
        mma_gemm<0,0,1,0,0,1,0><<<dim3(mrem / 128, D_DIM / 128), GEMM_THR, GEMM_SMEM>>>(
            RHST_hl + (size_t)i * NB2,
            S_hl + (size_t)i * MREM0 * 2 * NB2,
            nullptr, RHST_hl + (i + 1) * NB2, Cin,
            NB2, D2, D_DIM, 2 * NB2, NB2, 0, D2, -1.f, rbeta,
            0, 0, 0, D_DIM, 0);
    }

    // 7) WtT(:, bi) = RHST(:, bi) @ Tinv2_bi^T  (z-batched over 7 blocks)
    mma_gemm<0,0,0,1,0,1,0><<<dim3(NB2 / 128, D_DIM / 128, NBLK2), GEMM_THR, GEMM_SMEM>>>(
        RHST_hl, Tinv2_hl, nullptr, WtT_hl, nullptr,
        NB2, D2, D_DIM, 2 * NB2, NB2, 0, D2, 1.f, 0.f,
        (long long)NB2,
        (long long)NB2 * 2 * NB2,
        (long long)NB2,
        D_DIM, 0);

    // 8) P = I - WtT @ Vn^T-rows  (fp16 single out)
    mma_gemm<1,0,0,0,0,0,1><<<dim3(D_DIM / 128, D_DIM / 128), GEMM_THR, GEMM_SMEM>>>(
        WtT_hl, VnT_hl, nullptr, P_h, nullptr,
        D_DIM, D2, D_DIM, D2, D_DIM, 0, D_DIM, -1.f, 0.f, 0, 0, 0, D_DIM, 0);

    // 9) X^T fp16
    conv_h_T<<<dim3(B_DIM / 32, D_DIM / 32), t32x8>>>(X, D_DIM, B_DIM, XT_h, D_DIM);

    // 10) out = P @ X  (fp16 single product, K=64 stages)
    mma_gemm_h<<<dim3(B_DIM / 128, D_DIM / 128), GEMM_THR, GEMMH_SMEM>>>(
        P_h, XT_h, out, D_DIM, D_DIM, D_DIM, B_DIM);

    (void)n_in; (void)out_size;
}

// round 13
// speedup vs baseline: 1.7472x; 1.0080x over previous
#include <cuda_runtime.h>
#include <cuda_bf16.h>
#include <cuda_fp16.h>
#include <cstdint>

#define D_DIM 1792
#define B_DIM 8192
#define NB 128
#define NBLK (D_DIM / NB)     // 14
#define NB2 256
#define NBLK2 (D_DIM / NB2)   // 7
#define MREM0 1536

// ---------------- fp32 scratch ----------------
__device__ __align__(16) float g_Vn   [ (size_t)D_DIM * D_DIM ];
__device__ __align__(16) float g_G    [ (size_t)D_DIM * D_DIM ];
__device__ __align__(16) float g_Tinv [ (size_t)NBLK * NB * NB ];
__device__ __align__(16) float g_Tinv2[ (size_t)NBLK2 * NB2 * NB2 ];

// ---------------- bf16 hi|lo scratch ----------------
__device__ __align__(16) __nv_bfloat16 g_Vn_hl    [ (size_t)D_DIM * 2 * D_DIM ];
__device__ __align__(16) __nv_bfloat16 g_VnT_hl   [ (size_t)D_DIM * 2 * D_DIM ];
__device__ __align__(16) __nv_bfloat16 g_G_hl     [ (size_t)D_DIM * 2 * D_DIM ];
__device__ __align__(16) __nv_bfloat16 g_WtT_hl   [ (size_t)D_DIM * 2 * D_DIM ];
__device__ __align__(16) __nv_bfloat16 g_RHST_hl  [ (size_t)D_DIM * 2 * D_DIM ];
__device__ __align__(16) __nv_bfloat16 g_Tinv2_hl [ (size_t)NBLK2 * NB2 * 2 * NB2 ];
__device__ __align__(16) __nv_bfloat16 g_Tinv2T_hl[ (size_t)NBLK2 * NB2 * 2 * NB2 ];
__device__ __align__(16) __nv_bfloat16 g_S_hl     [ (size_t)(NBLK2 - 1) * MREM0 * 2 * NB2 ];

// ---------------- fp16 operands for PX ----------------
__device__ __align__(16) __half g_P_h [ (size_t)D_DIM * D_DIM ];
__device__ __align__(16) __half g_XT_h[ (size_t)B_DIM * D_DIM ];

// ============================================================================
// helpers
// ============================================================================
__device__ __forceinline__ uint32_t smem_u32(const void* p) {
    uint32_t a;
    asm("{ .reg .u64 t; cvta.to.shared.u64 t, %1; cvt.u32.u64 %0, t; }"
        : "=r"(a) : "l"(p));
    return a;
}
__device__ __forceinline__ void cpa16(uint32_t s, const void* g) {
    asm volatile("cp.async.cg.shared.global [%0], [%1], 16;" :: "r"(s), "l"(g));
}
#define CPA_COMMIT() asm volatile("cp.async.commit_group;" ::: "memory")
#define CPA_WAIT(n)  asm volatile("cp.async.wait_group %0;" :: "n"(n) : "memory")

#define LDSM4(r0, r1, r2, r3, addr) \
    asm volatile("ldmatrix.sync.aligned.m8n8.x4.shared.b16 {%0,%1,%2,%3}, [%4];" \
        : "=r"(r0), "=r"(r1), "=r"(r2), "=r"(r3) : "r"(addr))

#define MMA16816(d, a, b0, b1) \
    asm volatile("mma.sync.aligned.m16n8k16.row.col.f32.bf16.bf16.f32 " \
        "{%0,%1,%2,%3}, {%4,%5,%6,%7}, {%8,%9}, {%0,%1,%2,%3};" \
        : "+f"((d)[0]), "+f"((d)[1]), "+f"((d)[2]), "+f"((d)[3]) \
        : "r"((a)[0]), "r"((a)[1]), "r"((a)[2]), "r"((a)[3]), "r"(b0), "r"(b1))

#define MMA16816H(d, a, b0, b1) \
    asm volatile("mma.sync.aligned.m16n8k16.row.col.f32.f16.f16.f32 " \
        "{%0,%1,%2,%3}, {%4,%5,%6,%7}, {%8,%9}, {%0,%1,%2,%3};" \
        : "+f"((d)[0]), "+f"((d)[1]), "+f"((d)[2]), "+f"((d)[3]) \
        : "r"((a)[0]), "r"((a)[1]), "r"((a)[2]), "r"((a)[3]), "r"(b0), "r"(b1))

// ============================================================================
// Generalized bf16-split tensor GEMM (3 products hh+lh+hl):
//   V = alpha * A @ B^T  [+ rbeta*(hi+lo of Cin) if BETAHL]  [+ I if ADDI]
//   FPOUT: fp32 out to C.  HLOUT: bf16 hi/lo out to Chl.  F16OUT: fp16 to Chl.
// ============================================================================
#define TILE_B   8192
#define STAGE_B  (4 * TILE_B)
#define GEMM_SMEM (3 * STAGE_B)
#define GEMM_THR 128

template <int ADDI, int TRI, int BETAHL, int ZB, int FPOUT, int HLOUT, int F16OUT>
__global__ void __launch_bounds__(GEMM_THR, 2)
mma_gemm(const __nv_bfloat16* __restrict__ A, const __nv_bfloat16* __restrict__ B,
         float* __restrict__ C, void* __restrict__ Chl,
         const __nv_bfloat16* __restrict__ Cin,
         int K, int lda2, int loA, int ldb2, int loB,
         int ldc, int ldchl, float alpha, float rbeta,
         long long zAs, long long zBs, long long zCHs, int M0, int dM)
{
    extern __shared__ __align__(128) char smem[];
    const uint32_t s0 = smem_u32(smem);
    const int tid  = threadIdx.x;
    const int lane = tid & 31;
    const int wid  = tid >> 5;
    const int wm   = wid >> 1;
    const int wn   = wid & 1;

    if (ZB) {
        const int z = blockIdx.z;
        A += zAs * z; B += zBs * z;
        if (HLOUT) Chl = (void*)((__nv_bfloat16*)Chl + zCHs * z);
        if ((int)(blockIdx.y * 128) >= M0 - dM * z) return;
    }

    int row0, col0;
    if (TRI) {
        int bid = blockIdx.x;
        int r = 0;
        while ((r + 1) * (r + 2) / 2 <= bid) ++r;
        row0 = r * 128;
        col0 = (bid - r * (r + 1) / 2) * 128;
    } else {
        row0 = blockIdx.y * 128;
        col0 = blockIdx.x * 128;
    }

    const int T = K / 32;

    float acc[4][8][4];
#pragma unroll
    for (int i = 0; i < 4; i++)
#pragma unroll
        for (int j = 0; j < 8; j++)
#pragma unroll
            for (int q = 0; q < 4; q++) acc[i][j][q] = 0.f;

    auto load_stage = [&](int s) {
        const int k0 = s * 32;
        const uint32_t base = s0 + (s % 3) * STAGE_B;
#pragma unroll
        for (int qq = 0; qq < 4; ++qq) {
            const int jj = tid + qq * GEMM_THR;
            const int r  = jj >> 2;
            const int cc = jj & 3;
            const uint32_t soff = r * 64 + ((cc ^ ((r >> 1) & 3)) << 4);
            const __nv_bfloat16* ag = A + (size_t)(row0 + r) * lda2 + k0 + cc * 8;
            const __nv_bfloat16* bg = B + (size_t)(col0 + r) * ldb2 + k0 + cc * 8;
            cpa16(base + 0 * TILE_B + soff, ag);
            cpa16(base + 1 * TILE_B + soff, ag + loA);
            cpa16(base + 2 * TILE_B + soff, bg);
            cpa16(base + 3 * TILE_B + soff, bg + loB);
        }
        CPA_COMMIT();
    };

    load_stage(0); load_stage(1);

    for (int s = 0; s < T; ++s) {
        CPA_WAIT(1);
        __syncthreads();
        if (s + 2 < T) load_stage(s + 2);

        const uint32_t buf = s0 + (s % 3) * STAGE_B;
#pragma unroll
        for (int kk = 0; kk < 2; ++kk) {
            uint32_t ah[4][4], al[4][4], bb[8][2];
#pragma unroll
            for (int mi = 0; mi < 4; ++mi) {
                const int row = wm * 64 + mi * 16 + ((lane >> 3) & 1) * 8 + (lane & 7);
                const int cc  = kk * 2 + (lane >> 4);
                const uint32_t off = row * 64 + ((cc ^ ((row >> 1) & 3)) << 4);
                LDSM4(ah[mi][0], ah[mi][1], ah[mi][2], ah[mi][3], buf + 0 * TILE_B + off);
                LDSM4(al[mi][0], al[mi][1], al[mi][2], al[mi][3], buf + 1 * TILE_B + off);
            }
#pragma unroll
            for (int p = 0; p < 4; ++p) {
                const int row = wn * 64 + p * 16 + (lane >> 4) * 8 + (lane & 7);
                const int cc  = kk * 2 + ((lane >> 3) & 1);
                const uint32_t off = row * 64 + ((cc ^ ((row >> 1) & 3)) << 4);
                LDSM4(bb[p * 2][0], bb[p * 2][1], bb[p * 2 + 1][0], bb[p * 2 + 1][1],
                      buf + 2 * TILE_B + off);
            }
#pragma unroll
            for (int mi = 0; mi < 4; ++mi)
#pragma unroll
                for (int nj = 0; nj < 8; ++nj) {
                    MMA16816(acc[mi][nj], ah[mi], bb[nj][0], bb[nj][1]);  // hh
                    MMA16816(acc[mi][nj], al[mi], bb[nj][0], bb[nj][1]);  // lh
                }
#pragma unroll
            for (int p = 0; p < 4; ++p) {
                const int row = wn * 64 + p * 16 + (lane >> 4) * 8 + (lane & 7);
                const int cc  = kk * 2 + ((lane >> 3) & 1);
                const uint32_t off = row * 64 + ((cc ^ ((row >> 1) & 3)) << 4);
                LDSM4(bb[p * 2][0], bb[p * 2][1], bb[p * 2 + 1][0], bb[p * 2 + 1][1],
                      buf + 3 * TILE_B + off);
            }
#pragma unroll
            for (int mi = 0; mi < 4; ++mi)
#pragma unroll
                for (int nj = 0; nj < 8; ++nj)
                    MMA16816(acc[mi][nj], ah[mi], bb[nj][0], bb[nj][1]);  // hl
        }
    }

    const int g = lane >> 2, t = lane & 3;
    const int half = ldchl >> 1;
#pragma unroll
    for (int mi = 0; mi < 4; ++mi) {
#pragma unroll
        for (int nj = 0; nj < 8; ++nj) {
            const int r_ = row0 + wm * 64 + mi * 16 + g;
            const int c_ = col0 + wn * 64 + nj * 8 + 2 * t;
            float2 v, v2;
            v.x  = alpha * acc[mi][nj][0];
            v.y  = alpha * acc[mi][nj][1];
            v2.x = alpha * acc[mi][nj][2];
            v2.y = alpha * acc[mi][nj][3];
            if (BETAHL) {
                __nv_bfloat162 ih  = *reinterpret_cast<const __nv_bfloat162*>(
                    &Cin[(size_t)r_ * ldchl + c_]);
                __nv_bfloat162 il  = *reinterpret_cast<const __nv_bfloat162*>(
                    &Cin[(size_t)r_ * ldchl + half + c_]);
                __nv_bfloat162 ih2 = *reinterpret_cast<const __nv_bfloat162*>(
                    &Cin[(size_t)(r_ + 8) * ldchl + c_]);
                __nv_bfloat162 il2 = *reinterpret_cast<const __nv_bfloat162*>(
                    &Cin[(size_t)(r_ + 8) * ldchl + half + c_]);
                v.x  += rbeta * (__bfloat162float(ih.x)  + __bfloat162float(il.x));
                v.y  += rbeta * (__bfloat162float(ih.y)  + __bfloat162float(il.y));
                v2.x += rbeta * (__bfloat162float(ih2.x) + __bfloat162float(il2.x));
                v2.y += rbeta * (__bfloat162float(ih2.y) + __bfloat162float(il2.y));
            }
            if (ADDI) {
                if (r_ == c_)     v.x  += 1.f;
                if (r_ == c_ + 1) v.y  += 1.f;
                if (r_ + 8 == c_)     v2.x += 1.f;
                if (r_ + 8 == c_ + 1) v2.y += 1.f;
            }
            if (FPOUT) {
                *reinterpret_cast<float2*>(&C[(size_t)r_ * ldc + c_])       = v;
                *reinterpret_cast<float2*>(&C[(size_t)(r_ + 8) * ldc + c_]) = v2;
            }
            if (HLOUT) {
                __nv_bfloat16* Cb = (__nv_bfloat16*)Chl;
                __nv_bfloat162 h, h2, l, l2;
                h.x  = __float2bfloat16(v.x);   h.y  = __float2bfloat16(v.y);
                h2.x = __float2bfloat16(v2.x);  h2.y = __float2bfloat16(v2.y);
                l.x  = __float2bfloat16(v.x  - __bfloat162float(h.x));
                l.y  = __float2bfloat16(v.y  - __bfloat162float(h.y));
                l2.x = __float2bfloat16(v2.x - __bfloat162float(h2.x));
                l2.y = __float2bfloat16(v2.y - __bfloat162float(h2.y));
                *reinterpret_cast<__nv_bfloat162*>(&Cb[(size_t)r_ * ldchl + c_])              = h;
                *reinterpret_cast<__nv_bfloat162*>(&Cb[(size_t)r_ * ldchl + half + c_])       = l;
                *reinterpret_cast<__nv_bfloat162*>(&Cb[(size_t)(r_ + 8) * ldchl + c_])        = h2;
                *reinterpret_cast<__nv_bfloat162*>(&Cb[(size_t)(r_ + 8) * ldchl + half + c_]) = l2;
            }
            if (F16OUT) {
                __half* Ch = (__half*)Chl;
                *reinterpret_cast<__half2*>(&Ch[(size_t)r_ * ldchl + c_]) =
                    __floats2half2_rn(v.x, v.y);
                *reinterpret_cast<__half2*>(&Ch[(size_t)(r_ + 8) * ldchl + c_]) =
                    __floats2half2_rn(v2.x, v2.y);
            }
        }
    }
}

// ============================================================================
// fp16 single-product GEMM (out = P @ X): K=64 per stage, 128B-row swizzle.
// ============================================================================
#define TILE_H   16384
#define STAGE_H  (2 * TILE_H)
#define GEMMH_SMEM (3 * STAGE_H)

__global__ void __launch_bounds__(GEMM_THR, 2)
mma_gemm_h(const __half* __restrict__ A, const __half* __restrict__ B,
           float* __restrict__ C, int K, int lda, int ldb, int ldc)
{
    extern __shared__ __align__(128) char smem[];
    const uint32_t s0 = smem_u32(smem);
    const int tid  = threadIdx.x;
    const int lane = tid & 31;
    const int wid  = tid >> 5;
    const int wm   = wid >> 1;
    const int wn   = wid & 1;
    const int row0 = blockIdx.y * 128;
    const int col0 = blockIdx.x * 128;
    const int T = K / 64;

    float acc[4][8][4];
#pragma unroll
    for (int i = 0; i < 4; i++)
#pragma unroll
        for (int j = 0; j < 8; j++)
#pragma unroll
            for (int q = 0; q < 4; q++) acc[i][j][q] = 0.f;

    auto load_stage = [&](int s) {
        const int k0 = s * 64;
        const uint32_t base = s0 + (s % 3) * STAGE_H;
#pragma unroll
        for (int qq = 0; qq < 8; ++qq) {
            const int jj = tid + qq * GEMM_THR;
            const int r  = jj >> 3;
            const int cc = jj & 7;
            const uint32_t soff = r * 128 + ((cc ^ (r & 7)) << 4);
            cpa16(base + soff,          A + (size_t)(row0 + r) * lda + k0 + cc * 8);
            cpa16(base + TILE_H + soff, B + (size_t)(col0 + r) * ldb + k0 + cc * 8);
        }
        CPA_COMMIT();
    };

    load_stage(0); load_stage(1);

    for (int s = 0; s < T; ++s) {
        CPA_WAIT(1);
        __syncthreads();
        if (s + 2 < T) load_stage(s + 2);

        const uint32_t buf = s0 + (s % 3) * STAGE_H;
#pragma unroll
        for (int kk = 0; kk < 4; ++kk) {
            uint32_t ah[4][4], bb[8][2];
#pragma unroll
            for (int mi = 0; mi < 4; ++mi) {
                const int row = wm * 64 + mi * 16 + ((lane >> 3) & 1) * 8 + (lane & 7);
                const int cc  = kk * 2 + (lane >> 4);
                const uint32_t off = row * 128 + ((cc ^ (row & 7)) << 4);
                LDSM4(ah[mi][0], ah[mi][1], ah[mi][2], ah[mi][3], buf + off);
            }
#pragma unroll
            for (int p = 0; p < 4; ++p) {
                const int row = wn * 64 + p * 16 + (lane >> 4) * 8 + (lane & 7);
                const int cc  = kk * 2 + ((lane >> 3) & 1);
                const uint32_t off = row * 128 + ((cc ^ (row & 7)) << 4);
                LDSM4(bb[p * 2][0], bb[p * 2][1], bb[p * 2 + 1][0], bb[p * 2 + 1][1],
                      buf + TILE_H + off);
            }
#pragma unroll
            for (int mi = 0; mi < 4; ++mi)
#pragma unroll
                for (int nj = 0; nj < 8; ++nj)
                    MMA16816H(acc[mi][nj], ah[mi], bb[nj][0], bb[nj][1]);
        }
    }

    const int g = lane >> 2, t = lane & 3;
#pragma unroll
    for (int mi = 0; mi < 4; ++mi) {
#pragma unroll
        for (int nj = 0; nj < 8; ++nj) {
            const int r_ = row0 + wm * 64 + mi * 16 + g;
            const int c_ = col0 + wn * 64 + nj * 8 + 2 * t;
            *reinterpret_cast<float2*>(&C[(size_t)r_ * ldc + c_]) =
                make_float2(acc[mi][nj][0], acc[mi][nj][1]);
            *reinterpret_cast<float2*>(&C[(size_t)(r_ + 8) * ldc + c_]) =
                make_float2(acc[mi][nj][2], acc[mi][nj][3]);
        }
    }
}

// ============================================================================
// Row-normalize U -> Vn (fp32) + Vn_hl
// ============================================================================
__global__ void normalize_kernel(const float* __restrict__ U) {
    int row = blockIdx.x;
    const float* u = U + (size_t)row * D_DIM;
    __shared__ float red[256];
    float s = 0.f;
    for (int c = threadIdx.x; c < D_DIM; c += 256) { float v = u[c]; s += v * v; }
    red[threadIdx.x] = s;
    __syncthreads();
    for (int off = 128; off > 0; off >>= 1) {
        if (threadIdx.x < off) red[threadIdx.x] += red[threadIdx.x + off];
        __syncthreads();
    }
    float inv = rsqrtf(red[0]);
    for (int c = threadIdx.x; c < D_DIM; c += 256) {
        float v = u[c] * inv;
        g_Vn[(size_t)row * D_DIM + c] = v;
        __nv_bfloat16 h = __float2bfloat16(v);
        g_Vn_hl[(size_t)row * 2 * D_DIM + c]         = h;
        g_Vn_hl[(size_t)row * 2 * D_DIM + D_DIM + c] =
            __float2bfloat16(v - __bfloat162float(h));
    }
}

// ============================================================================
// conversions
// ============================================================================
__global__ void conv_hl_T_gen(const float* __restrict__ in, int R, int C,
                              __nv_bfloat16* __restrict__ out, int outld,
                              int outcol0, int looff,
                              long long zIn, long long zOut) {
    in  += zIn  * blockIdx.z;
    out += zOut * blockIdx.z;
    __shared__ float t[32][33];
    int r0 = blockIdx.y * 32, c0 = blockIdx.x * 32;
    int tx = threadIdx.x, ty = threadIdx.y;
    for (int i = 0; i < 32; i += 8)
        t[ty + i][tx] = in[(size_t)(r0 + ty + i) * C + c0 + tx];
    __syncthreads();
    for (int i = 0; i < 32; i += 8) {
        float x = t[tx][ty + i];
        __nv_bfloat16 h = __float2bfloat16(x);
        out[(size_t)(c0 + ty + i) * outld + outcol0 + r0 + tx] = h;
        out[(size_t)(c0 + ty + i) * outld + looff + outcol0 + r0 + tx] =
            __float2bfloat16(x - __bfloat162float(h));
    }
}
__global__ void conv_h_T(const float* __restrict__ in, int R, int C,
                         __half* __restrict__ out, int outld) {
    __shared__ float t[32][33];
    int r0 = blockIdx.y * 32, c0 = blockIdx.x * 32;
    int tx = threadIdx.x, ty = threadIdx.y;
    for (int i = 0; i < 32; i += 8)
        t[ty + i][tx] = in[(size_t)(r0 + ty + i) * C + c0 + tx];
    __syncthreads();
    for (int i = 0; i < 32; i += 8)
        out[(size_t)(c0 + ty + i) * outld + r0 + tx] = __float2half(t[tx][ty + i]);
}
// Seed RHST_hl block 0 = 2 * VnT_hl block 0 (exact, power of 2)
__global__ void seed_rhst0() {
    int r = blockIdx.x;
    int c = threadIdx.x;
    size_t base = (size_t)r * 2 * D_DIM;
    g_RHST_hl[base + c] =
        __float2bfloat16(2.f * __bfloat162float(g_VnT_hl[base + c]));
    g_RHST_hl[base + D_DIM + c] =
        __float2bfloat16(2.f * __bfloat162float(g_VnT_hl[base + D_DIM + c]));
}

// ============================================================================
// Diag-block inversion, column-sliced (NBLK, 8) + 4-column-fused rounds.
//   Per round (j += 4): phase1 computes the 4 finalized pivot rows
//   W = L4^{-1} Zblock via expanded coefficients; phase2 updates trailing
//   rows from W.  32 rounds, 2 barriers each.
// ============================================================================
#define INV_SMEM ((128 * 129 + 128 * 17 + 4 * 17) * (int)sizeof(float))
__global__ void invert_diag_kernel() {
    extern __shared__ float sm[];
    float (*Gs)[129] = (float (*)[129])sm;
    float (*Zs)[17]  = (float (*)[17])(sm + 128 * 129);
    float (*Pv)[17]  = (float (*)[17])(sm + 128 * 129 + 128 * 17);
    const int b0 = blockIdx.x * NB;
    const int c0 = blockIdx.y * 16;
    const int tid = threadIdx.x;

    for (int idx = tid; idx < 128 * 128; idx += 256) {
        int r = idx >> 7, c = idx & 127;
        Gs[r][c] = g_G[(size_t)(b0 + r) * D_DIM + b0 + c];
    }
    for (int idx = tid; idx < 128 * 16; idx += 256) {
        int r = idx >> 4, c = idx & 15;
        Zs[r][c] = (r == c0 + c) ? 1.f : 0.f;
    }
    __syncthreads();

    for (int j = 0; j < NB; j += 4) {
        // phase1: finalized pivot rows W_p (p = 0..3), 64 work items
        if (tid < 64) {
            const int p = tid >> 4;
            const int c = tid & 15;
            float g0 = (p > 0) ? 2.f * Gs[j + p][j]     : 0.f;
            float g1 = (p > 1) ? 2.f * Gs[j + p][j + 1] : 0.f;
            float g2 = (p > 2) ? 2.f * Gs[j + p][j + 2] : 0.f;
            float h10 = 2.f * Gs[j + 1][j];
            float h20 = 2.f * Gs[j + 2][j];
            float h21 = 2.f * Gs[j + 2][j + 1];
            float a2 = g2;
            float a1 = g1 - a2 * h21;
            float a0 = g0 - a1 * h10 - a2 * h20;
            Pv[p][c] = Zs[j + p][c]
                     - (a0 * Zs[j][c] + a1 * Zs[j + 1][c] + a2 * Zs[j + 2][c]);
        }
        __syncthreads();
        // phase2: rows j+1 .. 127
        const int rows = NB - 1 - j;
        for (int idx = tid; idx < rows * 16; idx += 256) {
            const int r = j + 1 + (idx >> 4);
            const int c = idx & 15;
            if (r <= j + 3) {
                Zs[r][c] = Pv[r - j][c];
            } else {
                float g0 = 2.f * Gs[r][j];
                float g1 = 2.f * Gs[r][j + 1];
                float g2 = 2.f * Gs[r][j + 2];
                float g3 = 2.f * Gs[r][j + 3];
                Zs[r][c] -= g0 * Pv[0][c] + g1 * Pv[1][c]
                          + g2 * Pv[2][c] + g3 * Pv[3][c];
            }
        }
        __syncthreads();
    }

    float* outp = g_Tinv + (size_t)blockIdx.x * NB * NB;
    for (int idx = tid; idx < 128 * 16; idx += 256) {
        int r = idx >> 4, c = idx & 15;
        outp[(size_t)r * NB + c0 + c] = Zs[r][c];
    }
}

// ============================================================================
// Pair-combine: 7 Tinv2 blocks (256x256) fp32 + fused row-major hi/lo split.
// ============================================================================
#define CMB_SMEM (3 * 128 * 129 * (int)sizeof(float))
__device__ __forceinline__ void cmb_wr_hl(__nv_bfloat16* Thl, int r, int c, float x) {
    __nv_bfloat16 h = __float2bfloat16(x);
    Thl[(size_t)r * 512 + c]       = h;
    Thl[(size_t)r * 512 + 256 + c] = __float2bfloat16(x - __bfloat162float(h));
}
__global__ void __launch_bounds__(256, 1) combine_tinv() {
    extern __shared__ float sm[];
    float (*Abuf)[129] = (float (*)[129])sm;
    float (*Bbuf)[129] = (float (*)[129])(sm + 128 * 129);
    float (*Tm)[129]   = (float (*)[129])(sm + 2 * 128 * 129);
    const int p = blockIdx.x;
    const int tid = threadIdx.x;
    const int trow = (tid / 16) * 8;
    const int tcol = (tid % 16) * 8;
    const float* InvA = g_Tinv + (size_t)(2 * p)     * NB * NB;
    const float* InvB = g_Tinv + (size_t)(2 * p + 1) * NB * NB;
    const size_t g21 = (size_t)(p * 256 + 128) * D_DIM + p * 256;
    __nv_bfloat16* Thl = g_Tinv2_hl + (size_t)p * NB2 * 2 * NB2;

    for (int idx = tid; idx < 128 * 128; idx += 256) {
        int r = idx >> 7, c = idx & 127;
        Abuf[r][c] = 2.f * g_G[g21 + (size_t)r * D_DIM + c];
        Bbuf[r][c] = InvA[idx];
    }
    __syncthreads();
    {
        float acc[8][8];
#pragma unroll
        for (int i = 0; i < 8; i++)
#pragma unroll
            for (int j = 0; j < 8; j++) acc[i][j] = 0.f;
        for (int k = 0; k < 128; ++k) {
            float a[8], b[8];
#pragma unroll
            for (int i = 0; i < 8; i++) a[i] = Abuf[trow + i][k];
#pragma unroll
            for (int j = 0; j < 8; j++) b[j] = Bbuf[k][tcol + j];
#pragma unroll
            for (int i = 0; i < 8; i++)
#pragma unroll
                for (int j = 0; j < 8; j++) acc[i][j] += a[i] * b[j];
        }
        __syncthreads();
#pragma unroll
        for (int i = 0; i < 8; i++)
#pragma unroll
            for (int j = 0; j < 8; j++) Tm[trow + i][tcol + j] = acc[i][j];
    }
    __syncthreads();
    for (int idx = tid; idx < 128 * 128; idx += 256) {
        int r = idx >> 7, c = idx & 127;
        Abuf[r][c] = InvB[idx];
    }
    __syncthreads();
    float* outp = g_Tinv2 + (size_t)p * NB2 * NB2;
    {
        float acc[8][8];
#pragma unroll
        for (int i = 0; i < 8; i++)
#pragma unroll
            for (int j = 0; j < 8; j++) acc[i][j] = 0.f;
        for (int k = 0; k < 128; ++k) {
            float a[8], b[8];
#pragma unroll
            for (int i = 0; i < 8; i++) a[i] = Abuf[trow + i][k];
#pragma unroll
            for (int j = 0; j < 8; j++) b[j] = Tm[k][tcol + j];
#pragma unroll
            for (int i = 0; i < 8; i++)
#pragma unroll
                for (int j = 0; j < 8; j++) acc[i][j] += a[i] * b[j];
        }
#pragma unroll
        for (int i = 0; i < 8; i++) {
#pragma unroll
            for (int j = 0; j < 8; j++) {
                int r = trow + i, c = tcol + j;
                float q21 = -acc[i][j];
                outp[(size_t)(128 + r) * NB2 + c] = q21;
                cmb_wr_hl(Thl, 128 + r, c, q21);
            }
        }
    }
    // Q11 = InvA (Bbuf), Q22 = InvB (Abuf), Q12 = 0  (fp32 + hl fused)
    for (int idx = tid; idx < 128 * 128; idx += 256) {
        int r = idx >> 7, c = idx & 127;
        float q11 = Bbuf[r][c];
        float q22 = Abuf[r][c];
        outp[(size_t)r * NB2 + c]               = q11;
        outp[(size_t)r * NB2 + 128 + c]         = 0.f;
        outp[(size_t)(128 + r) * NB2 + 128 + c] = q22;
        cmb_wr_hl(Thl, r, c, q11);
        cmb_wr_hl(Thl, r, 128 + c, 0.f);
        cmb_wr_hl(Thl, 128 + r, 128 + c, q22);
    }
}

// ============================================================================
extern "C" void kernel_launch(void* const* d_in, const int* in_sizes, int n_in,
                              void* d_out, int out_size)
{
    const float* X;
    const float* U;
    if (in_sizes[0] == D_DIM * D_DIM && in_sizes[1] != D_DIM * D_DIM) {
        U = (const float*)d_in[0]; X = (const float*)d_in[1];
    } else {
        X = (const float*)d_in[0]; U = (const float*)d_in[1];
    }
    float* out = (float*)d_out;

    float *Vn, *G, *Tinv2;
    cudaGetSymbolAddress((void**)&Vn,    g_Vn);
    cudaGetSymbolAddress((void**)&G,     g_G);
    cudaGetSymbolAddress((void**)&Tinv2, g_Tinv2);
    __nv_bfloat16 *Vn_hl, *VnT_hl, *G_hl, *WtT_hl, *RHST_hl;
    __nv_bfloat16 *Tinv2_hl, *Tinv2T_hl, *S_hl;
    __half *P_h, *XT_h;
    cudaGetSymbolAddress((void**)&Vn_hl,     g_Vn_hl);
    cudaGetSymbolAddress((void**)&VnT_hl,    g_VnT_hl);
    cudaGetSymbolAddress((void**)&G_hl,      g_G_hl);
    cudaGetSymbolAddress((void**)&WtT_hl,    g_WtT_hl);
    cudaGetSymbolAddress((void**)&RHST_hl,   g_RHST_hl);
    cudaGetSymbolAddress((void**)&Tinv2_hl,  g_Tinv2_hl);
    cudaGetSymbolAddress((void**)&Tinv2T_hl, g_Tinv2T_hl);
    cudaGetSymbolAddress((void**)&S_hl,      g_S_hl);
    cudaGetSymbolAddress((void**)&P_h,       g_P_h);
    cudaGetSymbolAddress((void**)&XT_h,      g_XT_h);

    cudaFuncSetAttribute(invert_diag_kernel,
                         cudaFuncAttributeMaxDynamicSharedMemorySize, INV_SMEM);
    cudaFuncSetAttribute(combine_tinv,
                         cudaFuncAttributeMaxDynamicSharedMemorySize, CMB_SMEM);
    cudaFuncSetAttribute(mma_gemm<0,1,0,0,1,1,0>,
                         cudaFuncAttributeMaxDynamicSharedMemorySize, GEMM_SMEM);
    cudaFuncSetAttribute(mma_gemm<0,0,0,1,0,1,0>,
                         cudaFuncAttributeMaxDynamicSharedMemorySize, GEMM_SMEM);
    cudaFuncSetAttribute(mma_gemm<0,0,1,0,0,1,0>,
                         cudaFuncAttributeMaxDynamicSharedMemorySize, GEMM_SMEM);
    cudaFuncSetAttribute(mma_gemm<1,0,0,0,0,0,1>,
                         cudaFuncAttributeMaxDynamicSharedMemorySize, GEMM_SMEM);
    cudaFuncSetAttribute(mma_gemm_h,
                         cudaFuncAttributeMaxDynamicSharedMemorySize, GEMMH_SMEM);

    const dim3 t32x8(32, 8);
    const int D2 = 2 * D_DIM;   // 3584

    // 0) Vn (+hl fused)
    normalize_kernel<<<D_DIM, 256>>>(U);
    // 1) VnT_hl
    conv_hl_T_gen<<<dim3(D_DIM / 32, D_DIM / 32), t32x8>>>(
        Vn, D_DIM, D_DIM, VnT_hl, D2, 0, D_DIM, 0, 0);
    // 2) G = Vn @ Vn^T (lower tiles; fp32 + hl fused)
    mma_gemm<0,1,0,0,1,1,0><<<NBLK * (NBLK + 1) / 2, GEMM_THR, GEMM_SMEM>>>(
        Vn_hl, Vn_hl, G, G_hl, nullptr,
        D_DIM, D2, D_DIM, D2, D_DIM, D_DIM, D2, 1.f, 0.f, 0, 0, 0, D_DIM, 0);
    // 3) invert 14 diag blocks (column-sliced, 4-col fused rounds)
    invert_diag_kernel<<<dim3(NBLK, 8), 256, INV_SMEM>>>();
    // 4) combine into 7 Tinv2 blocks (fp32 + Tinv2_hl fused)
    combine_tinv<<<NBLK2, 256, CMB_SMEM>>>();
    // 4b) Tinv2T_hl (transposed hi/lo split from fp32)
    conv_hl_T_gen<<<dim3(NB2 / 32, NB2 / 32, NBLK2), t32x8>>>(
        Tinv2, NB2, NB2, Tinv2T_hl, 2 * NB2, 0, NB2,
        (long long)NB2 * NB2, (long long)NB2 * 2 * NB2);
    // 5) S_i = 2 * G[(i+1)*256:, blk i] @ Tinv2_i^T  (z-batched, hl out)
    mma_gemm<0,0,0,1,0,1,0><<<dim3(NB2 / 128, MREM0 / 128, NBLK2 - 1), GEMM_THR, GEMM_SMEM>>>(
        G_hl + (size_t)NB2 * D2, Tinv2T_hl, nullptr, S_hl, nullptr,
        NB2, D2, D_DIM, 2 * NB2, NB2, 0, 2 * NB2, 2.f, 0.f,
        (long long)NB2 * D2 + NB2,
        (long long)NB2 * 2 * NB2,
        (long long)MREM0 * 2 * NB2,
        MREM0, NB2);
    // 5b) seed RHST_hl block 0
    seed_rhst0<<<D_DIM, 256>>>();

    // 6) transposed chain
    for (int i = 0; i < NBLK2 - 1; ++i) {
        int mrem = D_DIM - (i + 1) * NB2;
        const __nv_bfloat16* Cin = (i == 0) ? (VnT_hl + NB2) : (RHST_hl + (i + 1) * NB2);
        float rbeta = (i == 0) ? 2.f : 1.f;
        mma_gemm<0,0,1,0,0,1,0><<<dim3(mrem / 128, D_DIM / 128), GEMM_THR, GEMM_SMEM>>>(
            RHST_hl + (size_t)i * NB2,
            S_hl + (size_t)i * MREM0 * 2 * NB2,
            nullptr, RHST_hl + (i + 1) * NB2, Cin,
            NB2, D2, D_DIM, 2 * NB2, NB2, 0, D2, -1.f, rbeta,
            0, 0, 0, D_DIM, 0);
    }

    // 7) WtT(:, bi) = RHST(:, bi) @ Tinv2_bi^T  (z-batched)
    mma_gemm<0,0,0,1,0,1,0><<<dim3(NB2 / 128, D_DIM / 128, NBLK2), GEMM_THR, GEMM_SMEM>>>(
        RHST_hl, Tinv2_hl, nullptr, WtT_hl, nullptr,
        NB2, D2, D_DIM, 2 * NB2, NB2, 0, D2, 1.f, 0.f,
        (long long)NB2,
        (long long)NB2 * 2 * NB2,
        (long long)NB2,
        D_DIM, 0);

    // 8) P = I - WtT @ VnT-rows  (fp16 single out)
    mma_gemm<1,0,0,0,0,0,1><<<dim3(D_DIM / 128, D_DIM / 128), GEMM_THR, GEMM_SMEM>>>(
        WtT_hl, VnT_hl, nullptr, P_h, nullptr,
        D_DIM, D2, D_DIM, D2, D_DIM, 0, D_DIM, -1.f, 0.f, 0, 0, 0, D_DIM, 0);

    // 9) X^T fp16
    conv_h_T<<<dim3(B_DIM / 32, D_DIM / 32), t32x8>>>(X, D_DIM, B_DIM, XT_h, D_DIM);

    // 10) out = P @ X
    mma_gemm_h<<<dim3(B_DIM / 128, D_DIM / 128), GEMM_THR, GEMMH_SMEM>>>(
        P_h, XT_h, out, D_DIM, D_DIM, D_DIM, B_DIM);

    (void)n_in; (void)out_size;
}

// round 14
// speedup vs baseline: 1.8327x; 1.0489x over previous
#include <cuda_runtime.h>
#include <cuda_bf16.h>
#include <cuda_fp16.h>
#include <cstdint>

#define D_DIM 1792
#define B_DIM 8192
#define NB 128
#define NBLK (D_DIM / NB)     // 14
#define NB2 256
#define NBLK2 (D_DIM / NB2)   // 7
#define MREM0 1536

// ---------------- fp32 scratch ----------------
__device__ __align__(16) float g_Vn   [ (size_t)D_DIM * D_DIM ];
__device__ __align__(16) float g_G    [ (size_t)D_DIM * D_DIM ];
__device__ __align__(16) float g_Tinv [ (size_t)NBLK * NB * NB ];
__device__ __align__(16) float g_Tinv2[ (size_t)NBLK2 * NB2 * NB2 ];

// ---------------- bf16 hi|lo scratch ----------------
__device__ __align__(16) __nv_bfloat16 g_Vn_hl    [ (size_t)D_DIM * 2 * D_DIM ];
__device__ __align__(16) __nv_bfloat16 g_VnT_hl   [ (size_t)D_DIM * 2 * D_DIM ];
__device__ __align__(16) __nv_bfloat16 g_G_hl     [ (size_t)D_DIM * 2 * D_DIM ];
__device__ __align__(16) __nv_bfloat16 g_RHST_hl  [ (size_t)D_DIM * 2 * D_DIM ];
__device__ __align__(16) __nv_bfloat16 g_Tinv2_hl [ (size_t)NBLK2 * NB2 * 2 * NB2 ];
__device__ __align__(16) __nv_bfloat16 g_Tinv2T_hl[ (size_t)NBLK2 * NB2 * 2 * NB2 ];
__device__ __align__(16) __nv_bfloat16 g_S_hl     [ (size_t)(NBLK2 - 1) * MREM0 * 2 * NB2 ];

// ---------------- fp16 operands ----------------
__device__ __align__(16) __half g_P_h    [ (size_t)D_DIM * D_DIM ];
__device__ __align__(16) __half g_XT_h   [ (size_t)B_DIM * D_DIM ];
__device__ __align__(16) __half g_WtT_h2 [ (size_t)D_DIM * 2 * D_DIM ];  // hi|lo fp16
__device__ __align__(16) __half g_VnT_h  [ (size_t)D_DIM * D_DIM ];

// ============================================================================
// helpers
// ============================================================================
__device__ __forceinline__ uint32_t smem_u32(const void* p) {
    uint32_t a;
    asm("{ .reg .u64 t; cvta.to.shared.u64 t, %1; cvt.u32.u64 %0, t; }"
        : "=r"(a) : "l"(p));
    return a;
}
__device__ __forceinline__ void cpa16(uint32_t s, const void* g) {
    asm volatile("cp.async.cg.shared.global [%0], [%1], 16;" :: "r"(s), "l"(g));
}
#define CPA_COMMIT() asm volatile("cp.async.commit_group;" ::: "memory")
#define CPA_WAIT(n)  asm volatile("cp.async.wait_group %0;" :: "n"(n) : "memory")

#define LDSM4(r0, r1, r2, r3, addr) \
    asm volatile("ldmatrix.sync.aligned.m8n8.x4.shared.b16 {%0,%1,%2,%3}, [%4];" \
        : "=r"(r0), "=r"(r1), "=r"(r2), "=r"(r3) : "r"(addr))

#define MMA16816(d, a, b0, b1) \
    asm volatile("mma.sync.aligned.m16n8k16.row.col.f32.bf16.bf16.f32 " \
        "{%0,%1,%2,%3}, {%4,%5,%6,%7}, {%8,%9}, {%0,%1,%2,%3};" \
        : "+f"((d)[0]), "+f"((d)[1]), "+f"((d)[2]), "+f"((d)[3]) \
        : "r"((a)[0]), "r"((a)[1]), "r"((a)[2]), "r"((a)[3]), "r"(b0), "r"(b1))

#define MMA16816H(d, a, b0, b1) \
    asm volatile("mma.sync.aligned.m16n8k16.row.col.f32.f16.f16.f32 " \
        "{%0,%1,%2,%3}, {%4,%5,%6,%7}, {%8,%9}, {%0,%1,%2,%3};" \
        : "+f"((d)[0]), "+f"((d)[1]), "+f"((d)[2]), "+f"((d)[3]) \
        : "r"((a)[0]), "r"((a)[1]), "r"((a)[2]), "r"((a)[3]), "r"(b0), "r"(b1))

// ============================================================================
// Generalized bf16-split tensor GEMM (3 products hh+lh+hl):
//   V = alpha * A @ B^T  [+ rbeta*(hi+lo of Cin) if BETAHL]  [+ I if ADDI]
//   FPOUT: fp32 out.  HLOUT: bf16 hi/lo out.  F16M: 1 = fp16 single out,
//   2 = fp16 hi/lo out (half offset = ldchl/2).
// ============================================================================
#define TILE_B   8192
#define STAGE_B  (4 * TILE_B)
#define GEMM_SMEM (3 * STAGE_B)
#define GEMM_THR 128

template <int ADDI, int TRI, int BETAHL, int ZB, int FPOUT, int HLOUT, int F16M>
__global__ void __launch_bounds__(GEMM_THR, 2)
mma_gemm(const __nv_bfloat16* __restrict__ A, const __nv_bfloat16* __restrict__ B,
         float* __restrict__ C, void* __restrict__ Chl,
         const __nv_bfloat16* __restrict__ Cin,
         int K, int lda2, int loA, int ldb2, int loB,
         int ldc, int ldchl, float alpha, float rbeta,
         long long zAs, long long zBs, long long zCHs, int M0, int dM)
{
    extern __shared__ __align__(128) char smem[];
    const uint32_t s0 = smem_u32(smem);
    const int tid  = threadIdx.x;
    const int lane = tid & 31;
    const int wid  = tid >> 5;
    const int wm   = wid >> 1;
    const int wn   = wid & 1;

    if (ZB) {
        const int z = blockIdx.z;
        A += zAs * z; B += zBs * z;
        if (HLOUT || F16M) Chl = (void*)((char*)Chl + zCHs * 2 * (long long)z);
        if ((int)(blockIdx.y * 128) >= M0 - dM * z) return;
    }

    int row0, col0;
    if (TRI) {
        int bid = blockIdx.x;
        int r = 0;
        while ((r + 1) * (r + 2) / 2 <= bid) ++r;
        row0 = r * 128;
        col0 = (bid - r * (r + 1) / 2) * 128;
    } else {
        row0 = blockIdx.y * 128;
        col0 = blockIdx.x * 128;
    }

    const int T = K / 32;

    float acc[4][8][4];
#pragma unroll
    for (int i = 0; i < 4; i++)
#pragma unroll
        for (int j = 0; j < 8; j++)
#pragma unroll
            for (int q = 0; q < 4; q++) acc[i][j][q] = 0.f;

    auto load_stage = [&](int s) {
        const int k0 = s * 32;
        const uint32_t base = s0 + (s % 3) * STAGE_B;
#pragma unroll
        for (int qq = 0; qq < 4; ++qq) {
            const int jj = tid + qq * GEMM_THR;
            const int r  = jj >> 2;
            const int cc = jj & 3;
            const uint32_t soff = r * 64 + ((cc ^ ((r >> 1) & 3)) << 4);
            const __nv_bfloat16* ag = A + (size_t)(row0 + r) * lda2 + k0 + cc * 8;
            const __nv_bfloat16* bg = B + (size_t)(col0 + r) * ldb2 + k0 + cc * 8;
            cpa16(base + 0 * TILE_B + soff, ag);
            cpa16(base + 1 * TILE_B + soff, ag + loA);
            cpa16(base + 2 * TILE_B + soff, bg);
            cpa16(base + 3 * TILE_B + soff, bg + loB);
        }
        CPA_COMMIT();
    };

    load_stage(0); load_stage(1);

    for (int s = 0; s < T; ++s) {
        CPA_WAIT(1);
        __syncthreads();
        if (s + 2 < T) load_stage(s + 2);

        const uint32_t buf = s0 + (s % 3) * STAGE_B;
#pragma unroll
        for (int kk = 0; kk < 2; ++kk) {
            uint32_t ah[4][4], al[4][4], bb[8][2];
#pragma unroll
            for (int mi = 0; mi < 4; ++mi) {
                const int row = wm * 64 + mi * 16 + ((lane >> 3) & 1) * 8 + (lane & 7);
                const int cc  = kk * 2 + (lane >> 4);
                const uint32_t off = row * 64 + ((cc ^ ((row >> 1) & 3)) << 4);
                LDSM4(ah[mi][0], ah[mi][1], ah[mi][2], ah[mi][3], buf + 0 * TILE_B + off);
                LDSM4(al[mi][0], al[mi][1], al[mi][2], al[mi][3], buf + 1 * TILE_B + off);
            }
#pragma unroll
            for (int p = 0; p < 4; ++p) {
                const int row = wn * 64 + p * 16 + (lane >> 4) * 8 + (lane & 7);
                const int cc  = kk * 2 + ((lane >> 3) & 1);
                const uint32_t off = row * 64 + ((cc ^ ((row >> 1) & 3)) << 4);
                LDSM4(bb[p * 2][0], bb[p * 2][1], bb[p * 2 + 1][0], bb[p * 2 + 1][1],
                      buf + 2 * TILE_B + off);
            }
#pragma unroll
            for (int mi = 0; mi < 4; ++mi)
#pragma unroll
                for (int nj = 0; nj < 8; ++nj) {
                    MMA16816(acc[mi][nj], ah[mi], bb[nj][0], bb[nj][1]);  // hh
                    MMA16816(acc[mi][nj], al[mi], bb[nj][0], bb[nj][1]);  // lh
                }
#pragma unroll
            for (int p = 0; p < 4; ++p) {
                const int row = wn * 64 + p * 16 + (lane >> 4) * 8 + (lane & 7);
                const int cc  = kk * 2 + ((lane >> 3) & 1);
                const uint32_t off = row * 64 + ((cc ^ ((row >> 1) & 3)) << 4);
                LDSM4(bb[p * 2][0], bb[p * 2][1], bb[p * 2 + 1][0], bb[p * 2 + 1][1],
                      buf + 3 * TILE_B + off);
            }
#pragma unroll
            for (int mi = 0; mi < 4; ++mi)
#pragma unroll
                for (int nj = 0; nj < 8; ++nj)
                    MMA16816(acc[mi][nj], ah[mi], bb[nj][0], bb[nj][1]);  // hl
        }
    }

    const int g = lane >> 2, t = lane & 3;
    const int half = ldchl >> 1;
#pragma unroll
    for (int mi = 0; mi < 4; ++mi) {
#pragma unroll
        for (int nj = 0; nj < 8; ++nj) {
            const int r_ = row0 + wm * 64 + mi * 16 + g;
            const int c_ = col0 + wn * 64 + nj * 8 + 2 * t;
            float2 v, v2;
            v.x  = alpha * acc[mi][nj][0];
            v.y  = alpha * acc[mi][nj][1];
            v2.x = alpha * acc[mi][nj][2];
            v2.y = alpha * acc[mi][nj][3];
            if (BETAHL) {
                __nv_bfloat162 ih  = *reinterpret_cast<const __nv_bfloat162*>(
                    &Cin[(size_t)r_ * ldchl + c_]);
                __nv_bfloat162 il  = *reinterpret_cast<const __nv_bfloat162*>(
                    &Cin[(size_t)r_ * ldchl + half + c_]);
                __nv_bfloat162 ih2 = *reinterpret_cast<const __nv_bfloat162*>(
                    &Cin[(size_t)(r_ + 8) * ldchl + c_]);
                __nv_bfloat162 il2 = *reinterpret_cast<const __nv_bfloat162*>(
                    &Cin[(size_t)(r_ + 8) * ldchl + half + c_]);
                v.x  += rbeta * (__bfloat162float(ih.x)  + __bfloat162float(il.x));
                v.y  += rbeta * (__bfloat162float(ih.y)  + __bfloat162float(il.y));
                v2.x += rbeta * (__bfloat162float(ih2.x) + __bfloat162float(il2.x));
                v2.y += rbeta * (__bfloat162float(ih2.y) + __bfloat162float(il2.y));
            }
            if (ADDI) {
                if (r_ == c_)     v.x  += 1.f;
                if (r_ == c_ + 1) v.y  += 1.f;
                if (r_ + 8 == c_)     v2.x += 1.f;
                if (r_ + 8 == c_ + 1) v2.y += 1.f;
            }
            if (FPOUT) {
                *reinterpret_cast<float2*>(&C[(size_t)r_ * ldc + c_])       = v;
                *reinterpret_cast<float2*>(&C[(size_t)(r_ + 8) * ldc + c_]) = v2;
            }
            if (HLOUT) {
                __nv_bfloat16* Cb = (__nv_bfloat16*)Chl;
                __nv_bfloat162 h, h2, l, l2;
                h.x  = __float2bfloat16(v.x);   h.y  = __float2bfloat16(v.y);
                h2.x = __float2bfloat16(v2.x);  h2.y = __float2bfloat16(v2.y);
                l.x  = __float2bfloat16(v.x  - __bfloat162float(h.x));
                l.y  = __float2bfloat16(v.y  - __bfloat162float(h.y));
                l2.x = __float2bfloat16(v2.x - __bfloat162float(h2.x));
                l2.y = __float2bfloat16(v2.y - __bfloat162float(h2.y));
                *reinterpret_cast<__nv_bfloat162*>(&Cb[(size_t)r_ * ldchl + c_])              = h;
                *reinterpret_cast<__nv_bfloat162*>(&Cb[(size_t)r_ * ldchl + half + c_])       = l;
                *reinterpret_cast<__nv_bfloat162*>(&Cb[(size_t)(r_ + 8) * ldchl + c_])        = h2;
                *reinterpret_cast<__nv_bfloat162*>(&Cb[(size_t)(r_ + 8) * ldchl + half + c_]) = l2;
            }
            if (F16M == 1) {
                __half* Ch = (__half*)Chl;
                *reinterpret_cast<__half2*>(&Ch[(size_t)r_ * ldchl + c_]) =
                    __floats2half2_rn(v.x, v.y);
                *reinterpret_cast<__half2*>(&Ch[(size_t)(r_ + 8) * ldchl + c_]) =
                    __floats2half2_rn(v2.x, v2.y);
            }
            if (F16M == 2) {
                __half* Ch = (__half*)Chl;
                __half2 h  = __floats2half2_rn(v.x,  v.y);
                __half2 h2 = __floats2half2_rn(v2.x, v2.y);
                __half2 l  = __floats2half2_rn(v.x  - __half2float(h.x),
                                               v.y  - __half2float(h.y));
                __half2 l2 = __floats2half2_rn(v2.x - __half2float(h2.x),
                                               v2.y - __half2float(h2.y));
                *reinterpret_cast<__half2*>(&Ch[(size_t)r_ * ldchl + c_])              = h;
                *reinterpret_cast<__half2*>(&Ch[(size_t)r_ * ldchl + half + c_])       = l;
                *reinterpret_cast<__half2*>(&Ch[(size_t)(r_ + 8) * ldchl + c_])        = h2;
                *reinterpret_cast<__half2*>(&Ch[(size_t)(r_ + 8) * ldchl + half + c_]) = l2;
            }
        }
    }
}

// ============================================================================
// fp16 single-product GEMM (out = P @ X): K=64 per stage, 128B-row swizzle.
// ============================================================================
#define TILE_H   16384
#define STAGE_H  (2 * TILE_H)
#define GEMMH_SMEM (3 * STAGE_H)

__global__ void __launch_bounds__(GEMM_THR, 2)
mma_gemm_h(const __half* __restrict__ A, const __half* __restrict__ B,
           float* __restrict__ C, int K, int lda, int ldb, int ldc)
{
    extern __shared__ __align__(128) char smem[];
    const uint32_t s0 = smem_u32(smem);
    const int tid  = threadIdx.x;
    const int lane = tid & 31;
    const int wid  = tid >> 5;
    const int wm   = wid >> 1;
    const int wn   = wid & 1;
    const int row0 = blockIdx.y * 128;
    const int col0 = blockIdx.x * 128;
    const int T = K / 64;

    float acc[4][8][4];
#pragma unroll
    for (int i = 0; i < 4; i++)
#pragma unroll
        for (int j = 0; j < 8; j++)
#pragma unroll
            for (int q = 0; q < 4; q++) acc[i][j][q] = 0.f;

    auto load_stage = [&](int s) {
        const int k0 = s * 64;
        const uint32_t base = s0 + (s % 3) * STAGE_H;
#pragma unroll
        for (int qq = 0; qq < 8; ++qq) {
            const int jj = tid + qq * GEMM_THR;
            const int r  = jj >> 3;
            const int cc = jj & 7;
            const uint32_t soff = r * 128 + ((cc ^ (r & 7)) << 4);
            cpa16(base + soff,          A + (size_t)(row0 + r) * lda + k0 + cc * 8);
            cpa16(base + TILE_H + soff, B + (size_t)(col0 + r) * ldb + k0 + cc * 8);
        }
        CPA_COMMIT();
    };

    load_stage(0); load_stage(1);

    for (int s = 0; s < T; ++s) {
        CPA_WAIT(1);
        __syncthreads();
        if (s + 2 < T) load_stage(s + 2);

        const uint32_t buf = s0 + (s % 3) * STAGE_H;
#pragma unroll
        for (int kk = 0; kk < 4; ++kk) {
            uint32_t ah[4][4], bb[8][2];
#pragma unroll
            for (int mi = 0; mi < 4; ++mi) {
                const int row = wm * 64 + mi * 16 + ((lane >> 3) & 1) * 8 + (lane & 7);
                const int cc  = kk * 2 + (lane >> 4);
                const uint32_t off = row * 128 + ((cc ^ (row & 7)) << 4);
                LDSM4(ah[mi][0], ah[mi][1], ah[mi][2], ah[mi][3], buf + off);
            }
#pragma unroll
            for (int p = 0; p < 4; ++p) {
                const int row = wn * 64 + p * 16 + (lane >> 4) * 8 + (lane & 7);
                const int cc  = kk * 2 + ((lane >> 3) & 1);
                const uint32_t off = row * 128 + ((cc ^ (row & 7)) << 4);
                LDSM4(bb[p * 2][0], bb[p * 2][1], bb[p * 2 + 1][0], bb[p * 2 + 1][1],
                      buf + TILE_H + off);
            }
#pragma unroll
            for (int mi = 0; mi < 4; ++mi)
#pragma unroll
                for (int nj = 0; nj < 8; ++nj)
                    MMA16816H(acc[mi][nj], ah[mi], bb[nj][0], bb[nj][1]);
        }
    }

    const int g = lane >> 2, t = lane & 3;
#pragma unroll
    for (int mi = 0; mi < 4; ++mi) {
#pragma unroll
        for (int nj = 0; nj < 8; ++nj) {
            const int r_ = row0 + wm * 64 + mi * 16 + g;
            const int c_ = col0 + wn * 64 + nj * 8 + 2 * t;
            *reinterpret_cast<float2*>(&C[(size_t)r_ * ldc + c_]) =
                make_float2(acc[mi][nj][0], acc[mi][nj][1]);
            *reinterpret_cast<float2*>(&C[(size_t)(r_ + 8) * ldc + c_]) =
                make_float2(acc[mi][nj][2], acc[mi][nj][3]);
        }
    }
}

// ============================================================================
// fp16 2-product GEMM for P = I - A @ B^T:
//   A: [M, 2K] fp16 (hi | lo).  B: [N, K] fp16 single.  Out: fp16 P.
//   K=32/stage, 3 tiles/stage (Ah, Al, B), 3 stages.
// ============================================================================
#define TILE_P 8192
#define STAGE_P (3 * TILE_P)
#define GEMMP_SMEM (3 * STAGE_P)

__global__ void __launch_bounds__(GEMM_THR, 2)
p_gemm_h2(const __half* __restrict__ A, const __half* __restrict__ B,
          __half* __restrict__ P, int K, int lda2, int loA, int ldb, int ldp)
{
    extern __shared__ __align__(128) char smem[];
    const uint32_t s0 = smem_u32(smem);
    const int tid  = threadIdx.x;
    const int lane = tid & 31;
    const int wid  = tid >> 5;
    const int wm   = wid >> 1;
    const int wn   = wid & 1;
    const int row0 = blockIdx.y * 128;
    const int col0 = blockIdx.x * 128;
    const int T = K / 32;

    float acc[4][8][4];
#pragma unroll
    for (int i = 0; i < 4; i++)
#pragma unroll
        for (int j = 0; j < 8; j++)
#pragma unroll
            for (int q = 0; q < 4; q++) acc[i][j][q] = 0.f;

    auto load_stage = [&](int s) {
        const int k0 = s * 32;
        const uint32_t base = s0 + (s % 3) * STAGE_P;
#pragma unroll
        for (int qq = 0; qq < 4; ++qq) {
            const int jj = tid + qq * GEMM_THR;
            const int r  = jj >> 2;
            const int cc = jj & 3;
            const uint32_t soff = r * 64 + ((cc ^ ((r >> 1) & 3)) << 4);
            const __half* ag = A + (size_t)(row0 + r) * lda2 + k0 + cc * 8;
            cpa16(base + 0 * TILE_P + soff, ag);
            cpa16(base + 1 * TILE_P + soff, ag + loA);
            cpa16(base + 2 * TILE_P + soff,
                  B + (size_t)(col0 + r) * ldb + k0 + cc * 8);
        }
        CPA_COMMIT();
    };

    load_stage(0); load_stage(1);

    for (int s = 0; s < T; ++s) {
        CPA_WAIT(1);
        __syncthreads();
        if (s + 2 < T) load_stage(s + 2);

        const uint32_t buf = s0 + (s % 3) * STAGE_P;
#pragma unroll
        for (int kk = 0; kk < 2; ++kk) {
            uint32_t ah[4][4], al[4][4], bb[8][2];
#pragma unroll
            for (int mi = 0; mi < 4; ++mi) {
                const int row = wm * 64 + mi * 16 + ((lane >> 3) & 1) * 8 + (lane & 7);
                const int cc  = kk * 2 + (lane >> 4);
                const uint32_t off = row * 64 + ((cc ^ ((row >> 1) & 3)) << 4);
                LDSM4(ah[mi][0], ah[mi][1], ah[mi][2], ah[mi][3], buf + 0 * TILE_P + off);
                LDSM4(al[mi][0], al[mi][1], al[mi][2], al[mi][3], buf + 1 * TILE_P + off);
            }
#pragma unroll
            for (int p = 0; p < 4; ++p) {
                const int row = wn * 64 + p * 16 + (lane >> 4) * 8 + (lane & 7);
                const int cc  = kk * 2 + ((lane >> 3) & 1);
                const uint32_t off = row * 64 + ((cc ^ ((row >> 1) & 3)) << 4);
                LDSM4(bb[p * 2][0], bb[p * 2][1], bb[p * 2 + 1][0], bb[p * 2 + 1][1],
                      buf + 2 * TILE_P + off);
            }
#pragma unroll
            for (int mi = 0; mi < 4; ++mi)
#pragma unroll
                for (int nj = 0; nj < 8; ++nj) {
                    MMA16816H(acc[mi][nj], ah[mi], bb[nj][0], bb[nj][1]);
                    MMA16816H(acc[mi][nj], al[mi], bb[nj][0], bb[nj][1]);
                }
        }
    }

    const int g = lane >> 2, t = lane & 3;
#pragma unroll
    for (int mi = 0; mi < 4; ++mi) {
#pragma unroll
        for (int nj = 0; nj < 8; ++nj) {
            const int r_ = row0 + wm * 64 + mi * 16 + g;
            const int c_ = col0 + wn * 64 + nj * 8 + 2 * t;
            float2 v, v2;
            v.x  = -acc[mi][nj][0];
            v.y  = -acc[mi][nj][1];
            v2.x = -acc[mi][nj][2];
            v2.y = -acc[mi][nj][3];
            if (r_ == c_)     v.x  += 1.f;
            if (r_ == c_ + 1) v.y  += 1.f;
            if (r_ + 8 == c_)     v2.x += 1.f;
            if (r_ + 8 == c_ + 1) v2.y += 1.f;
            *reinterpret_cast<__half2*>(&P[(size_t)r_ * ldp + c_]) =
                __floats2half2_rn(v.x, v.y);
            *reinterpret_cast<__half2*>(&P[(size_t)(r_ + 8) * ldp + c_]) =
                __floats2half2_rn(v2.x, v2.y);
        }
    }
}

// ============================================================================
// Row-normalize U -> Vn (fp32) + Vn_hl
// ============================================================================
__global__ void normalize_kernel(const float* __restrict__ U) {
    int row = blockIdx.x;
    const float* u = U + (size_t)row * D_DIM;
    __shared__ float red[256];
    float s = 0.f;
    for (int c = threadIdx.x; c < D_DIM; c += 256) { float v = u[c]; s += v * v; }
    red[threadIdx.x] = s;
    __syncthreads();
    for (int off = 128; off > 0; off >>= 1) {
        if (threadIdx.x < off) red[threadIdx.x] += red[threadIdx.x + off];
        __syncthreads();
    }
    float inv = rsqrtf(red[0]);
    for (int c = threadIdx.x; c < D_DIM; c += 256) {
        float v = u[c] * inv;
        g_Vn[(size_t)row * D_DIM + c] = v;
        __nv_bfloat16 h = __float2bfloat16(v);
        g_Vn_hl[(size_t)row * 2 * D_DIM + c]         = h;
        g_Vn_hl[(size_t)row * 2 * D_DIM + D_DIM + c] =
            __float2bfloat16(v - __bfloat162float(h));
    }
}

// ============================================================================
// conversions
// ============================================================================
__global__ void conv_hl_T_gen(const float* __restrict__ in, int R, int C,
                              __nv_bfloat16* __restrict__ out, int outld,
                              int outcol0, int looff,
                              long long zIn, long long zOut) {
    in  += zIn  * blockIdx.z;
    out += zOut * blockIdx.z;
    __shared__ float t[32][33];
    int r0 = blockIdx.y * 32, c0 = blockIdx.x * 32;
    int tx = threadIdx.x, ty = threadIdx.y;
    for (int i = 0; i < 32; i += 8)
        t[ty + i][tx] = in[(size_t)(r0 + ty + i) * C + c0 + tx];
    __syncthreads();
    for (int i = 0; i < 32; i += 8) {
        float x = t[tx][ty + i];
        __nv_bfloat16 h = __float2bfloat16(x);
        out[(size_t)(c0 + ty + i) * outld + outcol0 + r0 + tx] = h;
        out[(size_t)(c0 + ty + i) * outld + looff + outcol0 + r0 + tx] =
            __float2bfloat16(x - __bfloat162float(h));
    }
}
// Vn transpose: emits bf16 hi/lo (VnT_hl) AND fp16 single (VnT_h)
__global__ void conv_T_vn(const float* __restrict__ in) {
    __shared__ float t[32][33];
    int r0 = blockIdx.y * 32, c0 = blockIdx.x * 32;
    int tx = threadIdx.x, ty = threadIdx.y;
    for (int i = 0; i < 32; i += 8)
        t[ty + i][tx] = in[(size_t)(r0 + ty + i) * D_DIM + c0 + tx];
    __syncthreads();
    for (int i = 0; i < 32; i += 8) {
        float x = t[tx][ty + i];
        __nv_bfloat16 h = __float2bfloat16(x);
        size_t ro = (size_t)(c0 + ty + i);
        g_VnT_hl[ro * 2 * D_DIM + r0 + tx]         = h;
        g_VnT_hl[ro * 2 * D_DIM + D_DIM + r0 + tx] =
            __float2bfloat16(x - __bfloat162float(h));
        g_VnT_h [ro * D_DIM + r0 + tx] = __float2half(x);
    }
}
__global__ void conv_h_T(const float* __restrict__ in, int R, int C,
                         __half* __restrict__ out, int outld) {
    __shared__ float t[32][33];
    int r0 = blockIdx.y * 32, c0 = blockIdx.x * 32;
    int tx = threadIdx.x, ty = threadIdx.y;
    for (int i = 0; i < 32; i += 8)
        t[ty + i][tx] = in[(size_t)(r0 + ty + i) * C + c0 + tx];
    __syncthreads();
    for (int i = 0; i < 32; i += 8)
        out[(size_t)(c0 + ty + i) * outld + r0 + tx] = __float2half(t[tx][ty + i]);
}
// Seed RHST_hl block 0 = 2 * VnT_hl block 0 (exact, power of 2)
__global__ void seed_rhst0() {
    int r = blockIdx.x;
    int c = threadIdx.x;
    size_t base = (size_t)r * 2 * D_DIM;
    g_RHST_hl[base + c] =
        __float2bfloat16(2.f * __bfloat162float(g_VnT_hl[base + c]));
    g_RHST_hl[base + D_DIM + c] =
        __float2bfloat16(2.f * __bfloat162float(g_VnT_hl[base + D_DIM + c]));
}

// ============================================================================
// Diag-block inversion, column-sliced (NBLK, 8) + 8-column band rounds.
//   phase1 (warp 0): micro-eliminate within the 8-row pivot band.
//   phase2 (all):    8-term trailing update.  16 rounds, 2 block barriers each.
// ============================================================================
#define INV_SMEM ((128 * 129 + 128 * 17) * (int)sizeof(float))
__global__ void invert_diag_kernel() {
    extern __shared__ float sm[];
    float (*Gs)[129] = (float (*)[129])sm;
    float (*Zs)[17]  = (float (*)[17])(sm + 128 * 129);
    const int b0 = blockIdx.x * NB;
    const int c0 = blockIdx.y * 16;
    const int tid = threadIdx.x;

    for (int idx = tid; idx < 128 * 128; idx += 256) {
        int r = idx >> 7, c = idx & 127;
        Gs[r][c] = g_G[(size_t)(b0 + r) * D_DIM + b0 + c];
    }
    for (int idx = tid; idx < 128 * 16; idx += 256) {
        int r = idx >> 4, c = idx & 15;
        Zs[r][c] = (r == c0 + c) ? 1.f : 0.f;
    }
    __syncthreads();

    for (int j = 0; j < NB; j += 8) {
        // phase1: warp 0 finalizes band rows j..j+7 (cols 0..15)
        if (tid < 32) {
            const int c  = tid & 15;
            const int rg = tid >> 4;           // 0: rows 0..3, 1: rows 4..7
#pragma unroll
            for (int q = 0; q < 7; ++q) {
                float zq = Zs[j + q][c];
#pragma unroll
                for (int rr = 0; rr < 4; ++rr) {
                    int r = rg * 4 + rr;
                    if (r > q)
                        Zs[j + r][c] -= 2.f * Gs[j + r][j + q] * zq;
                }
                __syncwarp();
            }
        }
        __syncthreads();
        // phase2: trailing rows j+8..127
        const int rows = NB - 8 - j;
        for (int idx = tid; idx < rows * 16; idx += 256) {
            const int r = j + 8 + (idx >> 4);
            const int c = idx & 15;
            float acc = Zs[r][c];
#pragma unroll
            for (int q = 0; q < 8; ++q)
                acc -= 2.f * Gs[r][j + q] * Zs[j + q][c];
            Zs[r][c] = acc;
        }
        __syncthreads();
    }

    float* outp = g_Tinv + (size_t)blockIdx.x * NB * NB;
    for (int idx = tid; idx < 128 * 16; idx += 256) {
        int r = idx >> 4, c = idx & 15;
        outp[(size_t)r * NB + c0 + c] = Zs[r][c];
    }
}

// ============================================================================
// Pair-combine: 7 Tinv2 blocks (256x256) fp32 + fused row-major hi/lo split.
// ============================================================================
#define CMB_SMEM (3 * 128 * 129 * (int)sizeof(float))
__device__ __forceinline__ void cmb_wr_hl(__nv_bfloat16* Thl, int r, int c, float x) {
    __nv_bfloat16 h = __float2bfloat16(x);
    Thl[(size_t)r * 512 + c]       = h;
    Thl[(size_t)r * 512 + 256 + c] = __float2bfloat16(x - __bfloat162float(h));
}
__global__ void __launch_bounds__(256, 1) combine_tinv() {
    extern __shared__ float sm[];
    float (*Abuf)[129] = (float (*)[129])sm;
    float (*Bbuf)[129] = (float (*)[129])(sm + 128 * 129);
    float (*Tm)[129]   = (float (*)[129])(sm + 2 * 128 * 129);
    const int p = blockIdx.x;
    const int tid = threadIdx.x;
    const int trow = (tid / 16) * 8;
    const int tcol = (tid % 16) * 8;
    const float* InvA = g_Tinv + (size_t)(2 * p)     * NB * NB;
    const float* InvB = g_Tinv + (size_t)(2 * p + 1) * NB * NB;
    const size_t g21 = (size_t)(p * 256 + 128) * D_DIM + p * 256;
    __nv_bfloat16* Thl = g_Tinv2_hl + (size_t)p * NB2 * 2 * NB2;

    for (int idx = tid; idx < 128 * 128; idx += 256) {
        int r = idx >> 7, c = idx & 127;
        Abuf[r][c] = 2.f * g_G[g21 + (size_t)r * D_DIM + c];
        Bbuf[r][c] = InvA[idx];
    }
    __syncthreads();
    {
        float acc[8][8];
#pragma unroll
        for (int i = 0; i < 8; i++)
#pragma unroll
            for (int j = 0; j < 8; j++) acc[i][j] = 0.f;
        for (int k = 0; k < 128; ++k) {
            float a[8], b[8];
#pragma unroll
            for (int i = 0; i < 8; i++) a[i] = Abuf[trow + i][k];
#pragma unroll
            for (int j = 0; j < 8; j++) b[j] = Bbuf[k][tcol + j];
#pragma unroll
            for (int i = 0; i < 8; i++)
#pragma unroll
                for (int j = 0; j < 8; j++) acc[i][j] += a[i] * b[j];
        }
        __syncthreads();
#pragma unroll
        for (int i = 0; i < 8; i++)
#pragma unroll
            for (int j = 0; j < 8; j++) Tm[trow + i][tcol + j] = acc[i][j];
    }
    __syncthreads();
    for (int idx = tid; idx < 128 * 128; idx += 256) {
        int r = idx >> 7, c = idx & 127;
        Abuf[r][c] = InvB[idx];
    }
    __syncthreads();
    float* outp = g_Tinv2 + (size_t)p * NB2 * NB2;
    {
        float acc[8][8];
#pragma unroll
        for (int i = 0; i < 8; i++)
#pragma unroll
            for (int j = 0; j < 8; j++) acc[i][j] = 0.f;
        for (int k = 0; k < 128; ++k) {
            float a[8], b[8];
#pragma unroll
            for (int i = 0; i < 8; i++) a[i] = Abuf[trow + i][k];
#pragma unroll
            for (int j = 0; j < 8; j++) b[j] = Tm[k][tcol + j];
#pragma unroll
            for (int i = 0; i < 8; i++)
#pragma unroll
                for (int j = 0; j < 8; j++) acc[i][j] += a[i] * b[j];
        }
#pragma unroll
        for (int i = 0; i < 8; i++) {
#pragma unroll
            for (int j = 0; j < 8; j++) {
                int r = trow + i, c = tcol + j;
                float q21 = -acc[i][j];
                outp[(size_t)(128 + r) * NB2 + c] = q21;
                cmb_wr_hl(Thl, 128 + r, c, q21);
            }
        }
    }
    for (int idx = tid; idx < 128 * 128; idx += 256) {
        int r = idx >> 7, c = idx & 127;
        float q11 = Bbuf[r][c];
        float q22 = Abuf[r][c];
        outp[(size_t)r * NB2 + c]               = q11;
        outp[(size_t)r * NB2 + 128 + c]         = 0.f;
        outp[(size_t)(128 + r) * NB2 + 128 + c] = q22;
        cmb_wr_hl(Thl, r, c, q11);
        cmb_wr_hl(Thl, r, 128 + c, 0.f);
        cmb_wr_hl(Thl, 128 + r, 128 + c, q22);
    }
}

// ============================================================================
extern "C" void kernel_launch(void* const* d_in, const int* in_sizes, int n_in,
                              void* d_out, int out_size)
{
    const float* X;
    const float* U;
    if (in_sizes[0] == D_DIM * D_DIM && in_sizes[1] != D_DIM * D_DIM) {
        U = (const float*)d_in[0]; X = (const float*)d_in[1];
    } else {
        X = (const float*)d_in[0]; U = (const float*)d_in[1];
    }
    float* out = (float*)d_out;

    float *Vn, *G, *Tinv2;
    cudaGetSymbolAddress((void**)&Vn,    g_Vn);
    cudaGetSymbolAddress((void**)&G,     g_G);
    cudaGetSymbolAddress((void**)&Tinv2, g_Tinv2);
    __nv_bfloat16 *Vn_hl, *VnT_hl, *G_hl, *RHST_hl;
    __nv_bfloat16 *Tinv2_hl, *Tinv2T_hl, *S_hl;
    __half *P_h, *XT_h, *WtT_h2, *VnT_h;
    cudaGetSymbolAddress((void**)&Vn_hl,     g_Vn_hl);
    cudaGetSymbolAddress((void**)&VnT_hl,    g_VnT_hl);
    cudaGetSymbolAddress((void**)&G_hl,      g_G_hl);
    cudaGetSymbolAddress((void**)&RHST_hl,   g_RHST_hl);
    cudaGetSymbolAddress((void**)&Tinv2_hl,  g_Tinv2_hl);
    cudaGetSymbolAddress((void**)&Tinv2T_hl, g_Tinv2T_hl);
    cudaGetSymbolAddress((void**)&S_hl,      g_S_hl);
    cudaGetSymbolAddress((void**)&P_h,       g_P_h);
    cudaGetSymbolAddress((void**)&XT_h,      g_XT_h);
    cudaGetSymbolAddress((void**)&WtT_h2,    g_WtT_h2);
    cudaGetSymbolAddress((void**)&VnT_h,     g_VnT_h);

    cudaFuncSetAttribute(invert_diag_kernel,
                         cudaFuncAttributeMaxDynamicSharedMemorySize, INV_SMEM);
    cudaFuncSetAttribute(combine_tinv,
                         cudaFuncAttributeMaxDynamicSharedMemorySize, CMB_SMEM);
    cudaFuncSetAttribute(mma_gemm<0,1,0,0,1,1,0>,
                         cudaFuncAttributeMaxDynamicSharedMemorySize, GEMM_SMEM);
    cudaFuncSetAttribute(mma_gemm<0,0,0,1,0,1,0>,
                         cudaFuncAttributeMaxDynamicSharedMemorySize, GEMM_SMEM);
    cudaFuncSetAttribute(mma_gemm<0,0,1,0,0,1,0>,
                         cudaFuncAttributeMaxDynamicSharedMemorySize, GEMM_SMEM);
    cudaFuncSetAttribute(mma_gemm<0,0,0,1,0,0,2>,
                         cudaFuncAttributeMaxDynamicSharedMemorySize, GEMM_SMEM);
    cudaFuncSetAttribute(p_gemm_h2,
                         cudaFuncAttributeMaxDynamicSharedMemorySize, GEMMP_SMEM);
    cudaFuncSetAttribute(mma_gemm_h,
                         cudaFuncAttributeMaxDynamicSharedMemorySize, GEMMH_SMEM);

    const dim3 t32x8(32, 8);
    const int D2 = 2 * D_DIM;   // 3584

    // 0) Vn (+hl fused)
    normalize_kernel<<<D_DIM, 256>>>(U);
    // 1) VnT: bf16 hi/lo + fp16 single (fused)
    conv_T_vn<<<dim3(D_DIM / 32, D_DIM / 32), t32x8>>>(Vn);
    // 2) G = Vn @ Vn^T (lower tiles; fp32 + hl fused)
    mma_gemm<0,1,0,0,1,1,0><<<NBLK * (NBLK + 1) / 2, GEMM_THR, GEMM_SMEM>>>(
        Vn_hl, Vn_hl, G, G_hl, nullptr,
        D_DIM, D2, D_DIM, D2, D_DIM, D_DIM, D2, 1.f, 0.f, 0, 0, 0, D_DIM, 0);
    // 3) invert 14 diag blocks (column-sliced, 8-col band rounds)
    invert_diag_kernel<<<dim3(NBLK, 8), 256, INV_SMEM>>>();
    // 4) combine into 7 Tinv2 blocks (fp32 + Tinv2_hl fused)
    combine_tinv<<<NBLK2, 256, CMB_SMEM>>>();
    // 4b) Tinv2T_hl (transposed hi/lo split from fp32)
    conv_hl_T_gen<<<dim3(NB2 / 32, NB2 / 32, NBLK2), t32x8>>>(
        Tinv2, NB2, NB2, Tinv2T_hl, 2 * NB2, 0, NB2,
        (long long)NB2 * NB2, (long long)NB2 * 2 * NB2);
    // 5) S_i = 2 * G[(i+1)*256:, blk i] @ Tinv2_i^T  (z-batched, hl out)
    mma_gemm<0,0,0,1,0,1,0><<<dim3(NB2 / 128, MREM0 / 128, NBLK2 - 1), GEMM_THR, GEMM_SMEM>>>(
        G_hl + (size_t)NB2 * D2, Tinv2T_hl, nullptr, S_hl, nullptr,
        NB2, D2, D_DIM, 2 * NB2, NB2, 0, 2 * NB2, 2.f, 0.f,
        (long long)NB2 * D2 + NB2,
        (long long)NB2 * 2 * NB2,
        (long long)MREM0 * 2 * NB2,
        MREM0, NB2);
    // 5b) seed RHST_hl block 0
    seed_rhst0<<<D_DIM, 256>>>();

    // 6) transposed chain
    for (int i = 0; i < NBLK2 - 1; ++i) {
        int mrem = D_DIM - (i + 1) * NB2;
        const __nv_bfloat16* Cin = (i == 0) ? (VnT_hl + NB2) : (RHST_hl + (i + 1) * NB2);
        float rbeta = (i == 0) ? 2.f : 1.f;
        mma_gemm<0,0,1,0,0,1,0><<<dim3(mrem / 128, D_DIM / 128), GEMM_THR, GEMM_SMEM>>>(
            RHST_hl + (size_t)i * NB2,
            S_hl + (size_t)i * MREM0 * 2 * NB2,
            nullptr, RHST_hl + (i + 1) * NB2, Cin,
            NB2, D2, D_DIM, 2 * NB2, NB2, 0, D2, -1.f, rbeta,
            0, 0, 0, D_DIM, 0);
    }

    // 7) WtT(:, bi) = RHST(:, bi) @ Tinv2_bi^T — fp16 hi/lo out (z-batched)
    mma_gemm<0,0,0,1,0,0,2><<<dim3(NB2 / 128, D_DIM / 128, NBLK2), GEMM_THR, GEMM_SMEM>>>(
        RHST_hl, Tinv2_hl, nullptr, WtT_h2, nullptr,
        NB2, D2, D_DIM, 2 * NB2, NB2, 0, D2, 1.f, 0.f,
        (long long)NB2,
        (long long)NB2 * 2 * NB2,
        (long long)NB2,
        D_DIM, 0);

    // 8) P = I - WtT @ VnT-rows  (fp16 2-product, fp16 out)
    p_gemm_h2<<<dim3(D_DIM / 128, D_DIM / 128), GEMM_THR, GEMMP_SMEM>>>(
        WtT_h2, VnT_h, P_h, D_DIM, D2, D_DIM, D_DIM, D_DIM);

    // 9) X^T fp16
    conv_h_T<<<dim3(B_DIM / 32, D_DIM / 32), t32x8>>>(X, D_DIM, B_DIM, XT_h, D_DIM);

    // 10) out = P @ X
    mma_gemm_h<<<dim3(B_DIM / 128, D_DIM / 128), GEMM_THR, GEMMH_SMEM>>>(
        P_h, XT_h, out, D_DIM, D_DIM, D_DIM, B_DIM);

    (void)n_in; (void)out_size;
}